// round 7
// baseline (speedup 1.0000x reference)
#include <cuda_runtime.h>
#include <cuda_bf16.h>
#include <math.h>
#include <stdint.h>

#define NH   16
#define NKV  4
#define HD   128
#define HIDD 2048
#define FFI  8192
#define QKVW ((NH + 2*NKV) * HD)   /* 3072 */
#define QMAX 16256.0f

// ================= scratch (B=4, S=1024) =================
static __device__ float g_qkv[4096L * QKVW];
static __device__ float g_scores[(long)4 * NH * 1024 * 1024];
static __device__ float g_attnout[4096L * HIDD];
static __device__ float g_h1[4096L * HIDD];
static __device__ float g_gu[4096L * 2 * FFI];

// bf16 attention operands
static __device__ __nv_bfloat16 g_qh[(long)4*NH*1024*HD], g_ql[(long)4*NH*1024*HD];
static __device__ __nv_bfloat16 g_kh[(long)4*NKV*1024*HD], g_kl[(long)4*NKV*1024*HD];
static __device__ __nv_bfloat16 g_vth[(long)4*NKV*HD*1024], g_vtl[(long)4*NKV*HD*1024];
static __device__ __nv_bfloat16 g_ph[(long)4*NH*1024*1024], g_pl[(long)4*NH*1024*1024];

// int8 limbs (activations)
static __device__ int8_t g_hq1[4096L * HIDD], g_hq0[4096L * HIDD];
static __device__ int8_t g_aoq1[4096L * HIDD], g_aoq0[4096L * HIDD];
static __device__ int8_t g_actq1[4096L * FFI], g_actq0[4096L * FFI];
// int8 limbs (weights, [N,K])
static __device__ int8_t g_wq1[(long)QKVW * HIDD], g_wq0[(long)QKVW * HIDD];
static __device__ int8_t g_wo1[(long)HIDD * HIDD], g_wo0[(long)HIDD * HIDD];
static __device__ int8_t g_gu1[(long)2*FFI * HIDD], g_gu0[(long)2*FFI * HIDD];
static __device__ int8_t g_dn1[(long)HIDD * FFI],  g_dn0[(long)HIDD * FFI];
// scales
static __device__ float g_sH[4096], g_sAO[4096], g_sACT[4096];
static __device__ float g_sWq[QKVW], g_sWo[HIDD], g_sGU[2*FFI], g_sDn[HIDD];

// ================= PTX helpers =================
__device__ __forceinline__ uint32_t smem_u32(const void* p) {
    uint32_t a;
    asm("{ .reg .u64 t; cvta.to.shared.u64 t, %1; cvt.u32.u64 %0, t; }" : "=r"(a) : "l"(p));
    return a;
}
__device__ __forceinline__ void cp16(uint32_t dst, const void* src) {
    asm volatile("cp.async.cg.shared.global [%0], [%1], 16;" :: "r"(dst), "l"(src));
}
__device__ __forceinline__ void cp_commit() { asm volatile("cp.async.commit_group;"); }
__device__ __forceinline__ void cp_wait1() { asm volatile("cp.async.wait_group 1;"); }
__device__ __forceinline__ void cp_wait0() { asm volatile("cp.async.wait_group 0;"); }

__device__ __forceinline__ void ldm_x4(uint32_t* r, uint32_t addr) {
    asm volatile("ldmatrix.sync.aligned.m8n8.x4.shared.b16 {%0,%1,%2,%3}, [%4];"
        : "=r"(r[0]), "=r"(r[1]), "=r"(r[2]), "=r"(r[3]) : "r"(addr));
}
__device__ __forceinline__ void mma16816(float* d, const uint32_t* a, const uint32_t* b) {
    asm volatile("mma.sync.aligned.m16n8k16.row.col.f32.bf16.bf16.f32 "
        "{%0,%1,%2,%3}, {%4,%5,%6,%7}, {%8,%9}, {%0,%1,%2,%3};"
        : "+f"(d[0]), "+f"(d[1]), "+f"(d[2]), "+f"(d[3])
        : "r"(a[0]), "r"(a[1]), "r"(a[2]), "r"(a[3]), "r"(b[0]), "r"(b[1]));
}
__device__ __forceinline__ void imma16832(int* d, const uint32_t* a, const uint32_t* b) {
    asm volatile("mma.sync.aligned.m16n8k32.row.col.s32.s8.s8.s32 "
        "{%0,%1,%2,%3}, {%4,%5,%6,%7}, {%8,%9}, {%0,%1,%2,%3};"
        : "+r"(d[0]), "+r"(d[1]), "+r"(d[2]), "+r"(d[3])
        : "r"(a[0]), "r"(a[1]), "r"(a[2]), "r"(a[3]), "r"(b[0]), "r"(b[1]));
}

__device__ __forceinline__ void split_store(float v, __nv_bfloat16* hi, __nv_bfloat16* lo, long idx) {
    __nv_bfloat16 h = __float2bfloat16(v);
    hi[idx] = h;
    lo[idx] = __float2bfloat16(v - __bfloat162float(h));
}
__device__ __forceinline__ void quant_store(float v, float inv, int8_t* q1, int8_t* q0, long idx) {
    float qf = rintf(v * inv);
    float a1 = rintf(qf * (1.0f/128.0f));
    q1[idx] = (int8_t)a1;
    q0[idx] = (int8_t)(qf - 128.0f * a1);
}

// ================= block reductions =================
__device__ __forceinline__ float block_sum(float v) {
    #pragma unroll
    for (int o = 16; o > 0; o >>= 1) v += __shfl_xor_sync(0xffffffffu, v, o);
    __shared__ float sh[8]; __shared__ float total;
    int w = threadIdx.x >> 5, l = threadIdx.x & 31;
    if (l == 0) sh[w] = v;
    __syncthreads();
    if (threadIdx.x == 0) { float s = 0.f; for (int i = 0; i < 8; i++) s += sh[i]; total = s; }
    __syncthreads();
    return total;
}
__device__ __forceinline__ float block_max(float v) {
    #pragma unroll
    for (int o = 16; o > 0; o >>= 1) v = fmaxf(v, __shfl_xor_sync(0xffffffffu, v, o));
    __shared__ float shm[8]; __shared__ float totalm;
    int w = threadIdx.x >> 5, l = threadIdx.x & 31;
    if (l == 0) shm[w] = v;
    __syncthreads();
    if (threadIdx.x == 0) { float s = 0.f; for (int i = 0; i < 8; i++) s = fmaxf(s, shm[i]); totalm = s; }
    __syncthreads();
    return totalm;
}

// ================= int8 limb GEMM =================
// C[M,N] = (16384*S11 + 128*(S10+S01)) * sA[m] * sB[n]  (+R)
// A limbs [M,K], B limbs [N,K]. CTA tile 128x128, BK=64, 8 warps 2x4.
#define ISAS 80
#define ITILE (128 * ISAS)       /* 10240 */
#define ISTG  (4 * ITILE)        /* 40960 */
#define IG_SMEM (2 * ISTG)       /* 81920 */

template<bool RES>
__global__ void __launch_bounds__(256, 1)
igemm(const int8_t* __restrict__ A1, const int8_t* __restrict__ A0,
      const int8_t* __restrict__ B1, const int8_t* __restrict__ B0,
      const float* __restrict__ sA, const float* __restrict__ sB,
      const float* __restrict__ R, float* __restrict__ C, int K, int N)
{
    extern __shared__ char sm[];
    const uint32_t sbase = smem_u32(sm);
    const int tid = threadIdx.x;

    int lin = blockIdx.y * gridDim.x + blockIdx.x;
    int grpSize = gridDim.x * 8;
    int grp = lin / grpSize, rem = lin % grpSize;
    const int m0 = (rem >> 3) * 128;
    const int n0 = (grp * 8 + (rem & 7)) * 128;

    const int wid = tid >> 5, lane = tid & 31;
    const int wm = (wid >> 2) * 64;
    const int wn = (wid & 3) * 32;

    const int8_t* srcs[4] = {
        A1 + (long)m0 * K, A0 + (long)m0 * K,
        B1 + (long)n0 * K, B0 + (long)n0 * K };

    int accM[4][4][4], accC[4][4][4];
    #pragma unroll
    for (int i = 0; i < 4; i++)
        #pragma unroll
        for (int j = 0; j < 4; j++)
            #pragma unroll
            for (int q = 0; q < 4; q++) { accM[i][j][q] = 0; accC[i][j][q] = 0; }

    auto load_stage = [&](int s, int blk) {
        const long kb = (long)blk << 6;
        #pragma unroll
        for (int t = 0; t < 4; t++) {
            const int8_t* S = srcs[t] + kb;
            const uint32_t dbase = sbase + s * ISTG + t * ITILE;
            #pragma unroll
            for (int i = 0; i < 2; i++) {
                int idx = tid + 256 * i;
                int r = idx >> 2, c = idx & 3;
                cp16(dbase + r * ISAS + c * 16, S + (long)r * K + c * 16);
            }
        }
        cp_commit();
    };

    const int NB = K >> 6;
    load_stage(0, 0);

    // ldmatrix address components
    const int arow = wm + (lane & 15);
    const int brow = wn + ((lane >> 4) & 1) * 8 + (lane & 7);

    for (int blk = 0; blk < NB; blk++) {
        const int s = blk & 1;
        if (blk + 1 < NB) { load_stage(s ^ 1, blk + 1); cp_wait1(); }
        else              { cp_wait0(); }
        __syncthreads();

        const uint32_t sA1 = sbase + s * ISTG;
        const uint32_t sA0 = sA1 + ITILE;
        const uint32_t sB1 = sA1 + 2 * ITILE;
        const uint32_t sB0 = sA1 + 3 * ITILE;

        #pragma unroll
        for (int kt = 0; kt < 2; kt++) {
            uint32_t a1[4][4], a0[4][4], b1[4][2], b0[4][2];
            const int akb = kt * 32 + ((lane >> 4) & 1) * 16;
            const int bkb = kt * 32 + ((lane >> 3) & 1) * 16;
            #pragma unroll
            for (int ma = 0; ma < 4; ma++) {
                uint32_t ao = (arow + ma * 16) * ISAS + akb;
                ldm_x4(a1[ma], sA1 + ao);
                ldm_x4(a0[ma], sA0 + ao);
            }
            #pragma unroll
            for (int p = 0; p < 2; p++) {
                uint32_t bo = (brow + p * 16) * ISAS + bkb;
                uint32_t q[4];
                ldm_x4(q, sB1 + bo);
                b1[2*p+0][0] = q[0]; b1[2*p+0][1] = q[1];
                b1[2*p+1][0] = q[2]; b1[2*p+1][1] = q[3];
                ldm_x4(q, sB0 + bo);
                b0[2*p+0][0] = q[0]; b0[2*p+0][1] = q[1];
                b0[2*p+1][0] = q[2]; b0[2*p+1][1] = q[3];
            }
            #pragma unroll
            for (int ma = 0; ma < 4; ma++)
                #pragma unroll
                for (int na = 0; na < 4; na++) {
                    imma16832(accM[ma][na], a1[ma], b1[na]);
                    imma16832(accC[ma][na], a1[ma], b0[na]);
                    imma16832(accC[ma][na], a0[ma], b1[na]);
                }
        }
        __syncthreads();
    }

    const int erow = lane >> 2, ecol = (lane & 3) * 2;
    #pragma unroll
    for (int ma = 0; ma < 4; ma++) {
        long r0 = m0 + wm + ma * 16 + erow;
        float sa0 = sA[r0], sa1 = sA[r0 + 8];
        #pragma unroll
        for (int na = 0; na < 4; na++) {
            long cc = n0 + wn + na * 8 + ecol;
            float sb0 = sB[cc], sb1 = sB[cc + 1];
            float v00 = ((float)accM[ma][na][0] * 16384.f + (float)accC[ma][na][0] * 128.f) * sa0 * sb0;
            float v01 = ((float)accM[ma][na][1] * 16384.f + (float)accC[ma][na][1] * 128.f) * sa0 * sb1;
            float v10 = ((float)accM[ma][na][2] * 16384.f + (float)accC[ma][na][2] * 128.f) * sa1 * sb0;
            float v11 = ((float)accM[ma][na][3] * 16384.f + (float)accC[ma][na][3] * 128.f) * sa1 * sb1;
            if (RES) {
                const float2 q0 = *(const float2*)&R[r0 * N + cc];
                const float2 q1 = *(const float2*)&R[(r0 + 8) * N + cc];
                v00 += q0.x; v01 += q0.y; v10 += q1.x; v11 += q1.y;
            }
            float2 w0 = {v00, v01}, w1 = {v10, v11};
            *(float2*)&C[r0 * N + cc] = w0;
            *(float2*)&C[(r0 + 8) * N + cc] = w1;
        }
    }
}

// ================= bf16x3 HMMA GEMM for attention =================
// MODE 1: QK^T (fp32 out, causal tile skip). MODE 2: PV (fp32 out, K truncated).
#define SAS 72
#define TILEB (128 * SAS * 2)
#define STAGE (4 * TILEB)
#define HG_SMEM (2 * STAGE)

template<int MODE>
__global__ void __launch_bounds__(256, 1)
hgemm(const __nv_bfloat16* __restrict__ Ahi, const __nv_bfloat16* __restrict__ Alo,
      const __nv_bfloat16* __restrict__ Bhi, const __nv_bfloat16* __restrict__ Blo,
      float* __restrict__ Cf,
      int K, int ldc, long sA, long sB, long sCb, long sCh, float alpha)
{
    extern __shared__ char sm[];
    const uint32_t sbase = smem_u32(sm);
    const int tid = threadIdx.x;
    const int m0 = blockIdx.x * 128, n0 = blockIdx.y * 128;
    if (MODE == 1 && n0 > m0) return;

    const int z = blockIdx.z;
    const long offA = (long)z * sA;
    const long offB = (long)(z >> 2) * sB;
    const long offC = (long)(z >> 4) * sCb + (long)(z & 15) * sCh;

    int NB = K >> 6;
    if (MODE == 2) { int nbe = (m0 >> 6) + 2; if (nbe < NB) NB = nbe; }

    const int wid = tid >> 5, lane = tid & 31;
    const int wm = (wid >> 2) * 64;
    const int wn = (wid & 3) * 32;

    const __nv_bfloat16* srcs[4] = {
        Ahi + offA + (long)m0 * K, Alo + offA + (long)m0 * K,
        Bhi + offB + (long)n0 * K, Blo + offB + (long)n0 * K };

    const int alr = lane & 15, alc = (lane >> 4) * 8;
    const int blr = lane & 7;
    const int bhalf = (lane >> 3) & 1;
    const int bquad = (lane >> 4) * 8;

    float acc[4][4][4];
    #pragma unroll
    for (int i = 0; i < 4; i++)
        #pragma unroll
        for (int j = 0; j < 4; j++)
            #pragma unroll
            for (int q = 0; q < 4; q++) acc[i][j][q] = 0.f;

    auto load_stage = [&](int s, int blk) {
        const long kb = (long)blk << 6;
        #pragma unroll
        for (int t = 0; t < 4; t++) {
            const __nv_bfloat16* S = srcs[t] + kb;
            const uint32_t dbase = sbase + s * STAGE + t * TILEB;
            #pragma unroll
            for (int i = 0; i < 4; i++) {
                int idx = tid + 256 * i;
                int r = idx >> 3, c = idx & 7;
                cp16(dbase + (r * SAS + c * 8) * 2, S + (long)r * K + c * 8);
            }
        }
        cp_commit();
    };

    load_stage(0, 0);

    for (int blk = 0; blk < NB; blk++) {
        const int s = blk & 1;
        if (blk + 1 < NB) { load_stage(s ^ 1, blk + 1); cp_wait1(); }
        else              { cp_wait0(); }
        __syncthreads();

        const uint32_t sAh = sbase + s * STAGE;
        const uint32_t sAl = sAh + TILEB;
        const uint32_t sBh = sAh + 2 * TILEB;
        const uint32_t sBl = sAh + 3 * TILEB;

        #pragma unroll
        for (int kt = 0; kt < 4; kt++) {
            uint32_t ah[4][4], al[4][4], bh[4][2], bl[4][2];
            #pragma unroll
            for (int ma = 0; ma < 4; ma++) {
                uint32_t ao = ((wm + ma * 16 + alr) * SAS + kt * 16 + alc) * 2;
                ldm_x4(ah[ma], sAh + ao);
                ldm_x4(al[ma], sAl + ao);
            }
            #pragma unroll
            for (int np = 0; np < 2; np++) {
                uint32_t bo = ((wn + np * 16 + bquad + blr) * SAS + kt * 16 + bhalf * 8) * 2;
                uint32_t t4[4];
                ldm_x4(t4, sBh + bo);
                bh[np*2+0][0] = t4[0]; bh[np*2+0][1] = t4[1];
                bh[np*2+1][0] = t4[2]; bh[np*2+1][1] = t4[3];
                ldm_x4(t4, sBl + bo);
                bl[np*2+0][0] = t4[0]; bl[np*2+0][1] = t4[1];
                bl[np*2+1][0] = t4[2]; bl[np*2+1][1] = t4[3];
            }
            #pragma unroll
            for (int ma = 0; ma < 4; ma++)
                #pragma unroll
                for (int na = 0; na < 4; na++) {
                    mma16816(acc[ma][na], ah[ma], bh[na]);
                    mma16816(acc[ma][na], ah[ma], bl[na]);
                    mma16816(acc[ma][na], al[ma], bh[na]);
                }
        }
        __syncthreads();
    }

    const int erow = lane >> 2, ecol = (lane & 3) * 2;
    #pragma unroll
    for (int ma = 0; ma < 4; ma++) {
        #pragma unroll
        for (int na = 0; na < 4; na++) {
            long r0 = m0 + wm + ma * 16 + erow;
            long cc = n0 + wn + na * 8 + ecol;
            float2 w0 = { acc[ma][na][0] * alpha, acc[ma][na][1] * alpha };
            float2 w1 = { acc[ma][na][2] * alpha, acc[ma][na][3] * alpha };
            *(float2*)&Cf[offC + r0 * ldc + cc] = w0;
            *(float2*)&Cf[offC + (r0 + 8) * ldc + cc] = w1;
        }
    }
}

// ================= elementwise / quant =================
__global__ void rmsnorm_q_kernel(const float* __restrict__ x, const float* __restrict__ w,
                                 int8_t* __restrict__ q1, int8_t* __restrict__ q0,
                                 float* __restrict__ sOut) {
    long row = blockIdx.x;
    const float* xr = x + row * HIDD;
    float s = 0.f, am = 0.f;
    for (int i = threadIdx.x; i < HIDD; i += 256) {
        float v = xr[i]; s += v * v;
        am = fmaxf(am, fabsf(v * w[i]));
    }
    s = block_sum(s);
    am = block_max(am);
    float invr = rsqrtf(s / (float)HIDD + 1e-6f);
    float sc = fmaxf(am * invr, 1e-30f) / QMAX;
    if (threadIdx.x == 0) sOut[row] = sc;
    float inv = 1.f / sc;
    for (int i = threadIdx.x; i < HIDD; i += 256)
        quant_store(xr[i] * invr * w[i], inv, q1, q0, row * HIDD + i);
}

__global__ void quant_rows_kernel(const float* __restrict__ in, int ncols,
                                  int8_t* __restrict__ q1, int8_t* __restrict__ q0,
                                  float* __restrict__ sOut) {
    long row = blockIdx.x;
    const float* p = in + row * ncols;
    float am = 0.f;
    for (int i = threadIdx.x; i < ncols; i += 256) am = fmaxf(am, fabsf(p[i]));
    am = block_max(am);
    float sc = fmaxf(am, 1e-30f) / QMAX;
    if (threadIdx.x == 0) sOut[row] = sc;
    float inv = 1.f / sc;
    for (int i = threadIdx.x; i < ncols; i += 256)
        quant_store(p[i], inv, q1, q0, row * ncols + i);
}

__global__ void silu_q_kernel(const float* __restrict__ gu,
                              int8_t* __restrict__ q1, int8_t* __restrict__ q0,
                              float* __restrict__ sOut) {
    __shared__ float buf[FFI];
    long row = blockIdx.x;
    const float* g = gu + row * (2L * FFI);
    float am = 0.f;
    for (int i = threadIdx.x; i < FFI; i += 256) {
        float gg = g[i], u = g[i + FFI];
        float v = (gg / (1.f + expf(-gg))) * u;
        buf[i] = v;
        am = fmaxf(am, fabsf(v));
    }
    __syncthreads();
    am = block_max(am);
    float sc = fmaxf(am, 1e-30f) / QMAX;
    if (threadIdx.x == 0) sOut[row] = sc;
    float inv = 1.f / sc;
    for (int i = threadIdx.x; i < FFI; i += 256)
        quant_store(buf[i], inv, q1, q0, row * (long)FFI + i);
}

// per-column amax of W [K,N] -> scale sB[n] = amax/QMAX
__global__ void colmax_kernel(const float* __restrict__ W, int K, int N,
                              float* __restrict__ sB) {
    int n = blockIdx.x * 256 + threadIdx.x;
    if (n >= N) return;
    float m = 0.f;
    for (int k = 0; k < K; k++) m = fmaxf(m, fabsf(W[(long)k * N + n]));
    sB[n] = fmaxf(m, 1e-30f) / QMAX;
}

// transpose + quantize: W [K,N] -> limbs [N,K]
__global__ void quantT_kernel(const float* __restrict__ W, const float* __restrict__ sB,
                              int8_t* __restrict__ q1, int8_t* __restrict__ q0,
                              int K, int N) {
    __shared__ float t[32][33];
    int n0 = blockIdx.x * 32, k0 = blockIdx.y * 32;
    for (int i = threadIdx.y; i < 32; i += 8)
        t[i][threadIdx.x] = W[(long)(k0 + i) * N + n0 + threadIdx.x];
    __syncthreads();
    for (int i = threadIdx.y; i < 32; i += 8) {
        float v = t[threadIdx.x][i];
        float inv = 1.f / sB[n0 + i];
        quant_store(v, inv, q1, q0, (long)(n0 + i) * K + k0 + threadIdx.x);
    }
}

// rope + split q,k: qkv fp32 -> bf16 hi/lo per-head layouts
__global__ void conv_qk_kernel(const float* __restrict__ qkv, const int* __restrict__ pos,
                               __nv_bfloat16* __restrict__ qh, __nv_bfloat16* __restrict__ ql,
                               __nv_bfloat16* __restrict__ kh, __nv_bfloat16* __restrict__ kl,
                               int S) {
    long idx = (long)blockIdx.x * 256 + threadIdx.x;
    int d = (int)(idx & 63);
    long t = idx >> 6;
    int head = (int)(t % (NH + NKV)); t /= (NH + NKV);
    int s = (int)(t % S);
    int b = (int)(t / S);
    const float* base = qkv + ((long)(b * S + s)) * QKVW + head * HD;
    float t1 = base[d], t2 = base[d + 64];
    float invf = powf(10000.f, -(float)d / 64.f);
    float ang = (float)pos[s] * invf;
    float sn, cs;
    sincosf(ang, &sn, &cs);
    float r1 = t1 * cs - t2 * sn;
    float r2 = t2 * cs + t1 * sn;
    if (head < NH) {
        long o = ((long)(b * NH + head) * S + s) * HD;
        split_store(r1, qh, ql, o + d);
        split_store(r2, qh, ql, o + d + 64);
    } else {
        long o = ((long)(b * NKV + head - NH) * S + s) * HD;
        split_store(r1, kh, kl, o + d);
        split_store(r2, kh, kl, o + d + 64);
    }
}

__global__ void conv_vt_kernel(const float* __restrict__ qkv,
                               __nv_bfloat16* __restrict__ vth, __nv_bfloat16* __restrict__ vtl,
                               int S) {
    __shared__ float t[32][33];
    int s0 = blockIdx.x * 32, d0 = blockIdx.y * 32;
    int z = blockIdx.z;
    int b = z >> 2, h = z & 3;
    for (int i = threadIdx.y; i < 32; i += 8)
        t[i][threadIdx.x] = qkv[((long)(b * S + s0 + i)) * QKVW + (NH + NKV + h) * HD + d0 + threadIdx.x];
    __syncthreads();
    for (int i = threadIdx.y; i < 32; i += 8) {
        float v = t[threadIdx.x][i];
        long o = ((long)z * HD + d0 + i) * S + s0 + threadIdx.x;
        split_store(v, vth, vtl, o);
    }
}

__global__ void softmax_split_kernel(const float* __restrict__ sc,
                                     __nv_bfloat16* __restrict__ ph, __nv_bfloat16* __restrict__ pl,
                                     int S) {
    long row = blockIdx.x;
    int r = (int)(row & (S - 1));
    int len = r + 1;
    const float* p = sc + row * (long)S;
    float mx = -3.4e38f;
    for (int i = threadIdx.x; i < len; i += 256) mx = fmaxf(mx, p[i]);
    #pragma unroll
    for (int o = 16; o > 0; o >>= 1) mx = fmaxf(mx, __shfl_xor_sync(0xffffffffu, mx, o));
    __shared__ float shm[8]; __shared__ float totalm;
    { int w = threadIdx.x >> 5, l = threadIdx.x & 31;
      if (l == 0) shm[w] = mx;
      __syncthreads();
      if (threadIdx.x == 0) { float s2 = -3.4e38f; for (int i = 0; i < 8; i++) s2 = fmaxf(s2, shm[i]); totalm = s2; }
      __syncthreads();
      mx = totalm; }
    float sum = 0.f;
    for (int i = threadIdx.x; i < len; i += 256) sum += __expf(p[i] - mx);
    sum = block_sum(sum);
    float rinv = 1.f / sum;
    long o = row * (long)S;
    for (int i = threadIdx.x; i < len; i += 256)
        split_store(__expf(p[i] - mx) * rinv, ph, pl, o + i);
    __nv_bfloat16 z = __float2bfloat16(0.f);
    for (int i = len + threadIdx.x; i < S; i += 256) { ph[o + i] = z; pl[o + i] = z; }
}

// ================= host launcher =================
extern "C" void kernel_launch(void* const* d_in, const int* in_sizes, int n_in,
                              void* d_out, int out_size) {
    const float* x         = (const float*)d_in[0];
    const float* ln1_w     = (const float*)d_in[1];
    const float* wqkv      = (const float*)d_in[2];
    const float* wo        = (const float*)d_in[3];
    const float* ln2_w     = (const float*)d_in[4];
    const float* w_gate_up = (const float*)d_in[5];
    const float* w_down    = (const float*)d_in[6];
    const int*   pos       = (const int*)d_in[7];
    float* out = (float*)d_out;

    const int S  = in_sizes[7];
    const long BS = (long)in_sizes[0] / HIDD;
    const int Bb = (int)(BS / S);

    float *pQKV, *pSC, *pAO, *pH1, *pGU;
    cudaGetSymbolAddress((void**)&pQKV, g_qkv);
    cudaGetSymbolAddress((void**)&pSC,  g_scores);
    cudaGetSymbolAddress((void**)&pAO,  g_attnout);
    cudaGetSymbolAddress((void**)&pH1,  g_h1);
    cudaGetSymbolAddress((void**)&pGU,  g_gu);
    __nv_bfloat16 *pQh,*pQl,*pKh,*pKl,*pVth,*pVtl,*pPh,*pPl;
    cudaGetSymbolAddress((void**)&pQh, g_qh);   cudaGetSymbolAddress((void**)&pQl, g_ql);
    cudaGetSymbolAddress((void**)&pKh, g_kh);   cudaGetSymbolAddress((void**)&pKl, g_kl);
    cudaGetSymbolAddress((void**)&pVth, g_vth); cudaGetSymbolAddress((void**)&pVtl, g_vtl);
    cudaGetSymbolAddress((void**)&pPh, g_ph);   cudaGetSymbolAddress((void**)&pPl, g_pl);
    int8_t *pHq1,*pHq0,*pAOq1,*pAOq0,*pACTq1,*pACTq0;
    int8_t *pWq1,*pWq0,*pWo1,*pWo0,*pGu1,*pGu0,*pDn1,*pDn0;
    cudaGetSymbolAddress((void**)&pHq1, g_hq1);   cudaGetSymbolAddress((void**)&pHq0, g_hq0);
    cudaGetSymbolAddress((void**)&pAOq1, g_aoq1); cudaGetSymbolAddress((void**)&pAOq0, g_aoq0);
    cudaGetSymbolAddress((void**)&pACTq1, g_actq1); cudaGetSymbolAddress((void**)&pACTq0, g_actq0);
    cudaGetSymbolAddress((void**)&pWq1, g_wq1);   cudaGetSymbolAddress((void**)&pWq0, g_wq0);
    cudaGetSymbolAddress((void**)&pWo1, g_wo1);   cudaGetSymbolAddress((void**)&pWo0, g_wo0);
    cudaGetSymbolAddress((void**)&pGu1, g_gu1);   cudaGetSymbolAddress((void**)&pGu0, g_gu0);
    cudaGetSymbolAddress((void**)&pDn1, g_dn1);   cudaGetSymbolAddress((void**)&pDn0, g_dn0);
    float *psH,*psAO,*psACT,*psWq,*psWo,*psGU,*psDn;
    cudaGetSymbolAddress((void**)&psH, g_sH);     cudaGetSymbolAddress((void**)&psAO, g_sAO);
    cudaGetSymbolAddress((void**)&psACT, g_sACT);
    cudaGetSymbolAddress((void**)&psWq, g_sWq);   cudaGetSymbolAddress((void**)&psWo, g_sWo);
    cudaGetSymbolAddress((void**)&psGU, g_sGU);   cudaGetSymbolAddress((void**)&psDn, g_sDn);

    cudaFuncSetAttribute(igemm<false>, cudaFuncAttributeMaxDynamicSharedMemorySize, IG_SMEM);
    cudaFuncSetAttribute(igemm<true>,  cudaFuncAttributeMaxDynamicSharedMemorySize, IG_SMEM);
    cudaFuncSetAttribute(hgemm<1>, cudaFuncAttributeMaxDynamicSharedMemorySize, HG_SMEM);
    cudaFuncSetAttribute(hgemm<2>, cudaFuncAttributeMaxDynamicSharedMemorySize, HG_SMEM);

    dim3 blkT(32, 8);
    const float inv_sqrt_d = 0.08838834764831843f;

    // weight quantization (scale + transpose-quantize)
    colmax_kernel<<<QKVW/256, 256>>>(wqkv, HIDD, QKVW, psWq);
    colmax_kernel<<<HIDD/256, 256>>>(wo, HIDD, HIDD, psWo);
    colmax_kernel<<<2*FFI/256, 256>>>(w_gate_up, HIDD, 2*FFI, psGU);
    colmax_kernel<<<HIDD/256, 256>>>(w_down, FFI, HIDD, psDn);
    quantT_kernel<<<dim3(QKVW/32,  HIDD/32), blkT>>>(wqkv,      psWq, pWq1, pWq0, HIDD, QKVW);
    quantT_kernel<<<dim3(HIDD/32,  HIDD/32), blkT>>>(wo,        psWo, pWo1, pWo0, HIDD, HIDD);
    quantT_kernel<<<dim3(2*FFI/32, HIDD/32), blkT>>>(w_gate_up, psGU, pGu1, pGu0, HIDD, 2*FFI);
    quantT_kernel<<<dim3(HIDD/32,  FFI/32),  blkT>>>(w_down,    psDn, pDn1, pDn0, FFI,  HIDD);

    // 1. h = rmsnorm(x) -> int8 limbs
    rmsnorm_q_kernel<<<(int)BS, 256>>>(x, ln1_w, pHq1, pHq0, psH);

    // 2. qkv = h @ wqkv
    igemm<false><<<dim3((int)(BS/128), QKVW/128), 256, IG_SMEM>>>(
        pHq1, pHq0, pWq1, pWq0, psH, psWq, nullptr, pQKV, HIDD, QKVW);

    // 3. rope + split q,k ; transpose + split v
    conv_qk_kernel<<<(unsigned)((BS * (NH+NKV) * 64) / 256), 256>>>(pQKV, pos, pQh, pQl, pKh, pKl, S);
    conv_vt_kernel<<<dim3(S/32, HD/32, Bb*NKV), blkT>>>(pQKV, pVth, pVtl, S);

    // 4. scores = QK^T/sqrt(D) (causal tiles only)
    hgemm<1><<<dim3(S/128, S/128, Bb*NH), 256, HG_SMEM>>>(
        pQh, pQl, pKh, pKl, pSC,
        HD, S, (long)S*HD, (long)S*HD, (long)NH*S*S, (long)S*S, inv_sqrt_d);

    // 5. softmax -> P bf16 hi/lo
    softmax_split_kernel<<<(unsigned)(Bb*NH*S), 256>>>(pSC, pPh, pPl, S);

    // 6. attnout = P @ V  (fp32 out [b,s,h*d])
    hgemm<2><<<dim3(S/128, 1, Bb*NH), 256, HG_SMEM>>>(
        pPh, pPl, pVth, pVtl, pAO,
        S, HIDD, (long)S*S, (long)HD*S, (long)S*HIDD, HD, 1.f);

    // 6b. quantize attnout rows
    quant_rows_kernel<<<(int)BS, 256>>>(pAO, HIDD, pAOq1, pAOq0, psAO);

    // 7. h1 = x + attnout @ wo
    igemm<true><<<dim3((int)(BS/128), HIDD/128), 256, IG_SMEM>>>(
        pAOq1, pAOq0, pWo1, pWo0, psAO, psWo, x, pH1, HIDD, HIDD);

    // 8. h2 = rmsnorm(h1) -> int8 limbs
    rmsnorm_q_kernel<<<(int)BS, 256>>>(pH1, ln2_w, pHq1, pHq0, psH);

    // 9. gu = h2 @ w_gate_up
    igemm<false><<<dim3((int)(BS/128), 2*FFI/128), 256, IG_SMEM>>>(
        pHq1, pHq0, pGu1, pGu0, psH, psGU, nullptr, pGU, HIDD, 2*FFI);

    // 10. act = silu(gate)*up -> int8 limbs
    silu_q_kernel<<<(int)BS, 256>>>(pGU, pACTq1, pACTq0, psACT);

    // 11. out = h1 + act @ w_down
    igemm<true><<<dim3((int)(BS/128), HIDD/128), 256, IG_SMEM>>>(
        pACTq1, pACTq0, pDn1, pDn0, psACT, psDn, pH1, out, FFI, HIDD);
}

// round 8
// speedup vs baseline: 3.5731x; 3.5731x over previous
#include <cuda_runtime.h>
#include <cuda_fp16.h>
#include <math.h>
#include <stdint.h>

#define NH   16
#define NKV  4
#define HD   128
#define HIDD 2048
#define FFI  8192
#define QKVW ((NH + 2*NKV) * HD)   /* 3072 */

// ================= scratch (B=4, S=1024) =================
static __device__ float g_qkv[4096L * QKVW];
static __device__ float g_scores[(long)4 * NH * 1024 * 1024];
static __device__ float g_h1[4096L * HIDD];
static __device__ float g_gu[4096L * 2 * FFI];

static __device__ __half g_hh[4096L * HIDD],  g_hl[4096L * HIDD];
static __device__ __half g_aoh[4096L * HIDD], g_aol[4096L * HIDD];
static __device__ __half g_acth[4096L * FFI], g_actl[4096L * FFI];
static __device__ __half g_qh[(long)4*NH*1024*HD], g_ql[(long)4*NH*1024*HD];
static __device__ __half g_kh[(long)4*NKV*1024*HD], g_kl[(long)4*NKV*1024*HD];
static __device__ __half g_vt[(long)4*NKV*HD*1024];
static __device__ __half g_ph[(long)4*NH*1024*1024], g_pl[(long)4*NH*1024*1024];
static __device__ __half g_wqkvT[(long)QKVW * HIDD];
static __device__ __half g_woT[(long)HIDD * HIDD];
static __device__ __half g_guT[(long)2*FFI * HIDD];
static __device__ __half g_dnT[(long)HIDD * FFI];

// ================= PTX helpers =================
__device__ __forceinline__ uint32_t smem_u32(const void* p) {
    uint32_t a;
    asm("{ .reg .u64 t; cvta.to.shared.u64 t, %1; cvt.u32.u64 %0, t; }" : "=r"(a) : "l"(p));
    return a;
}
__device__ __forceinline__ void cp16(uint32_t dst, const void* src) {
    asm volatile("cp.async.cg.shared.global [%0], [%1], 16;" :: "r"(dst), "l"(src));
}
__device__ __forceinline__ void cp_commit() { asm volatile("cp.async.commit_group;"); }
__device__ __forceinline__ void cp_wait1() { asm volatile("cp.async.wait_group 1;"); }
__device__ __forceinline__ void cp_wait0() { asm volatile("cp.async.wait_group 0;"); }

__device__ __forceinline__ void ldm_x4(uint32_t* r, uint32_t addr) {
    asm volatile("ldmatrix.sync.aligned.m8n8.x4.shared.b16 {%0,%1,%2,%3}, [%4];"
        : "=r"(r[0]), "=r"(r[1]), "=r"(r[2]), "=r"(r[3]) : "r"(addr));
}
__device__ __forceinline__ void mma16816h(float* d, const uint32_t* a, const uint32_t* b) {
    asm volatile("mma.sync.aligned.m16n8k16.row.col.f32.f16.f16.f32 "
        "{%0,%1,%2,%3}, {%4,%5,%6,%7}, {%8,%9}, {%0,%1,%2,%3};"
        : "+f"(d[0]), "+f"(d[1]), "+f"(d[2]), "+f"(d[3])
        : "r"(a[0]), "r"(a[1]), "r"(a[2]), "r"(a[3]), "r"(b[0]), "r"(b[1]));
}

__device__ __forceinline__ void split_store_h(float v, __half* hi, __half* lo, long idx) {
    __half h = __float2half_rn(v);
    hi[idx] = h;
    lo[idx] = __float2half_rn(v - __half2float(h));
}

// ================= fp16 two-term TN GEMM =================
// C[M,N] = alpha * (Ahi+Alo)[M,K] x (B[N,K])^T  (+ residual R)
// MODE 0: weights (fp32 out, optional residual, block swizzle)
// MODE 1: QK^T    (fp32 out, causal tile skip, per-head batch via z)
// MODE 2: PV      (fp16 hi/lo out, K truncated by causality, per-head batch)
#define SAS 72
#define TILEB (128 * SAS * 2)     /* 18432 */
#define STAGE (3 * TILEB)         /* Ahi Alo B = 55296 */
#define HG_SMEM (2 * STAGE)       /* 110592 */

template<int MODE, bool RES>
__global__ void __launch_bounds__(256, 1)
hgemm(const __half* __restrict__ Ahi, const __half* __restrict__ Alo,
      const __half* __restrict__ B,
      const float* __restrict__ R, float* __restrict__ Cf,
      __half* __restrict__ Chi, __half* __restrict__ Clo,
      int K, int ldc, long sA, long sB, long sCb, long sCh, float alpha)
{
    extern __shared__ char sm[];
    const uint32_t sbase = smem_u32(sm);
    const int tid = threadIdx.x;

    int m0, n0;
    if (MODE == 0) {
        int lin = blockIdx.y * gridDim.x + blockIdx.x;
        int grpSize = gridDim.x * 8;
        int grp = lin / grpSize, rem = lin % grpSize;
        m0 = (rem >> 3) * 128;
        n0 = (grp * 8 + (rem & 7)) * 128;
    } else {
        m0 = blockIdx.x * 128;
        n0 = blockIdx.y * 128;
    }
    if (MODE == 1 && n0 > m0) return;

    const int z = blockIdx.z;
    const long offA = (long)z * sA;
    const long offB = (long)(z >> 2) * sB;
    const long offC = (long)(z >> 4) * sCb + (long)(z & 15) * sCh;

    int NB = K >> 6;
    if (MODE == 2) { int nbe = (m0 >> 6) + 2; if (nbe < NB) NB = nbe; }

    const int wid = tid >> 5, lane = tid & 31;
    const int wm = (wid >> 2) * 64;
    const int wn = (wid & 3) * 32;

    const __half* srcs[3] = {
        Ahi + offA + (long)m0 * K, Alo + offA + (long)m0 * K,
        B + offB + (long)n0 * K };

    const int alr = lane & 15, alc = (lane >> 4) * 8;
    const int blr = lane & 7;
    const int bhalf = (lane >> 3) & 1;
    const int bquad = (lane >> 4) * 8;

    float acc[4][4][4];
    #pragma unroll
    for (int i = 0; i < 4; i++)
        #pragma unroll
        for (int j = 0; j < 4; j++)
            #pragma unroll
            for (int q = 0; q < 4; q++) acc[i][j][q] = 0.f;

    auto load_stage = [&](int s, int blk) {
        const long kb = (long)blk << 6;
        #pragma unroll
        for (int t = 0; t < 3; t++) {
            const __half* S = srcs[t] + kb;
            const uint32_t dbase = sbase + s * STAGE + t * TILEB;
            #pragma unroll
            for (int i = 0; i < 4; i++) {
                int idx = tid + 256 * i;
                int r = idx >> 3, c = idx & 7;
                cp16(dbase + (r * SAS + c * 8) * 2, S + (long)r * K + c * 8);
            }
        }
        cp_commit();
    };

    load_stage(0, 0);

    for (int blk = 0; blk < NB; blk++) {
        const int s = blk & 1;
        if (blk + 1 < NB) { load_stage(s ^ 1, blk + 1); cp_wait1(); }
        else              { cp_wait0(); }
        __syncthreads();

        const uint32_t sAh = sbase + s * STAGE;
        const uint32_t sAl = sAh + TILEB;
        const uint32_t sB_ = sAh + 2 * TILEB;

        #pragma unroll
        for (int kt = 0; kt < 4; kt++) {
            uint32_t ah[4][4], al[4][4], bb[4][2];
            #pragma unroll
            for (int ma = 0; ma < 4; ma++) {
                uint32_t ao = ((wm + ma * 16 + alr) * SAS + kt * 16 + alc) * 2;
                ldm_x4(ah[ma], sAh + ao);
                ldm_x4(al[ma], sAl + ao);
            }
            #pragma unroll
            for (int np = 0; np < 2; np++) {
                uint32_t bo = ((wn + np * 16 + bquad + blr) * SAS + kt * 16 + bhalf * 8) * 2;
                uint32_t t4[4];
                ldm_x4(t4, sB_ + bo);
                bb[np*2+0][0] = t4[0]; bb[np*2+0][1] = t4[1];
                bb[np*2+1][0] = t4[2]; bb[np*2+1][1] = t4[3];
            }
            #pragma unroll
            for (int ma = 0; ma < 4; ma++)
                #pragma unroll
                for (int na = 0; na < 4; na++) {
                    mma16816h(acc[ma][na], ah[ma], bb[na]);
                    mma16816h(acc[ma][na], al[ma], bb[na]);
                }
        }
        __syncthreads();
    }

    const int erow = lane >> 2, ecol = (lane & 3) * 2;
    #pragma unroll
    for (int ma = 0; ma < 4; ma++) {
        #pragma unroll
        for (int na = 0; na < 4; na++) {
            long r0 = m0 + wm + ma * 16 + erow;
            long cc = n0 + wn + na * 8 + ecol;
            float v00 = acc[ma][na][0] * alpha, v01 = acc[ma][na][1] * alpha;
            float v10 = acc[ma][na][2] * alpha, v11 = acc[ma][na][3] * alpha;
            if (MODE == 2) {
                long o0 = offC + r0 * ldc + cc;
                long o1 = offC + (r0 + 8) * ldc + cc;
                split_store_h(v00, Chi, Clo, o0);
                split_store_h(v01, Chi, Clo, o0 + 1);
                split_store_h(v10, Chi, Clo, o1);
                split_store_h(v11, Chi, Clo, o1 + 1);
            } else {
                if (RES) {
                    const float2 q0 = *(const float2*)&R[offC + r0 * ldc + cc];
                    const float2 q1 = *(const float2*)&R[offC + (r0 + 8) * ldc + cc];
                    v00 += q0.x; v01 += q0.y; v10 += q1.x; v11 += q1.y;
                }
                float2 w0 = {v00, v01}, w1 = {v10, v11};
                *(float2*)&Cf[offC + r0 * ldc + cc] = w0;
                *(float2*)&Cf[offC + (r0 + 8) * ldc + cc] = w1;
            }
        }
    }
}

// ================= block reductions =================
__device__ __forceinline__ float block_sum(float v) {
    #pragma unroll
    for (int o = 16; o > 0; o >>= 1) v += __shfl_xor_sync(0xffffffffu, v, o);
    __shared__ float sh[8]; __shared__ float total;
    int w = threadIdx.x >> 5, l = threadIdx.x & 31;
    if (l == 0) sh[w] = v;
    __syncthreads();
    if (threadIdx.x == 0) { float s = 0.f; for (int i = 0; i < 8; i++) s += sh[i]; total = s; }
    __syncthreads();
    return total;
}
__device__ __forceinline__ float block_max(float v) {
    #pragma unroll
    for (int o = 16; o > 0; o >>= 1) v = fmaxf(v, __shfl_xor_sync(0xffffffffu, v, o));
    __shared__ float shm[8]; __shared__ float totalm;
    int w = threadIdx.x >> 5, l = threadIdx.x & 31;
    if (l == 0) shm[w] = v;
    __syncthreads();
    if (threadIdx.x == 0) { float s = -3.4e38f; for (int i = 0; i < 8; i++) s = fmaxf(s, shm[i]); totalm = s; }
    __syncthreads();
    return totalm;
}

// ================= elementwise =================
__global__ void rmsnorm_h_kernel(const float* __restrict__ x, const float* __restrict__ w,
                                 __half* __restrict__ hi, __half* __restrict__ lo) {
    long row = blockIdx.x;
    const float* xr = x + row * HIDD;
    float s = 0.f;
    for (int i = threadIdx.x; i < HIDD; i += 256) { float v = xr[i]; s += v * v; }
    s = block_sum(s);
    float inv = rsqrtf(s / (float)HIDD + 1e-6f);
    for (int i = threadIdx.x; i < HIDD; i += 256)
        split_store_h(xr[i] * inv * w[i], hi, lo, row * HIDD + i);
}

__global__ void silu_h_kernel(const float* __restrict__ gu,
                              __half* __restrict__ hi, __half* __restrict__ lo, long total) {
    long idx = (long)blockIdx.x * 256 + threadIdx.x;
    if (idx >= total) return;
    long row = idx / FFI;
    int  j   = (int)(idx - row * FFI);
    float g = gu[row * (2L * FFI) + j];
    float u = gu[row * (2L * FFI) + FFI + j];
    split_store_h((g / (1.f + expf(-g))) * u, hi, lo, idx);
}

// transpose-convert: W [K,N] fp32 -> T [N,K] fp16 single
__global__ void convT_h_kernel(const float* __restrict__ W, __half* __restrict__ T,
                               int K, int N) {
    __shared__ float t[32][33];
    int n0 = blockIdx.x * 32, k0 = blockIdx.y * 32;
    for (int i = threadIdx.y; i < 32; i += 8)
        t[i][threadIdx.x] = W[(long)(k0 + i) * N + n0 + threadIdx.x];
    __syncthreads();
    for (int i = threadIdx.y; i < 32; i += 8)
        T[(long)(n0 + i) * K + k0 + threadIdx.x] = __float2half_rn(t[threadIdx.x][i]);
}

// rope + split q,k: qkv fp32 -> fp16 hi/lo per-head layouts
__global__ void conv_qk_kernel(const float* __restrict__ qkv, const int* __restrict__ pos,
                               __half* __restrict__ qh, __half* __restrict__ ql,
                               __half* __restrict__ kh, __half* __restrict__ kl,
                               int S) {
    long idx = (long)blockIdx.x * 256 + threadIdx.x;
    int d = (int)(idx & 63);
    long t = idx >> 6;
    int head = (int)(t % (NH + NKV)); t /= (NH + NKV);
    int s = (int)(t % S);
    int b = (int)(t / S);
    const float* base = qkv + ((long)(b * S + s)) * QKVW + head * HD;
    float t1 = base[d], t2 = base[d + 64];
    float invf = powf(10000.f, -(float)d / 64.f);
    float ang = (float)pos[s] * invf;
    float sn, cs;
    sincosf(ang, &sn, &cs);
    float r1 = t1 * cs - t2 * sn;
    float r2 = t2 * cs + t1 * sn;
    if (head < NH) {
        long o = ((long)(b * NH + head) * S + s) * HD;
        split_store_h(r1, qh, ql, o + d);
        split_store_h(r2, qh, ql, o + d + 64);
    } else {
        long o = ((long)(b * NKV + head - NH) * S + s) * HD;
        split_store_h(r1, kh, kl, o + d);
        split_store_h(r2, kh, kl, o + d + 64);
    }
}

// v transpose: qkv v slice [b,s,hk,128] -> vt [b,hk,d,s] fp16 single
__global__ void conv_vt_kernel(const float* __restrict__ qkv, __half* __restrict__ vt, int S) {
    __shared__ float t[32][33];
    int s0 = blockIdx.x * 32, d0 = blockIdx.y * 32;
    int z = blockIdx.z;
    int b = z >> 2, h = z & 3;
    for (int i = threadIdx.y; i < 32; i += 8)
        t[i][threadIdx.x] = qkv[((long)(b * S + s0 + i)) * QKVW + (NH + NKV + h) * HD + d0 + threadIdx.x];
    __syncthreads();
    for (int i = threadIdx.y; i < 32; i += 8)
        vt[((long)z * HD + d0 + i) * S + s0 + threadIdx.x] = __float2half_rn(t[threadIdx.x][i]);
}

// causal softmax: fp32 scores -> P fp16 hi/lo (zeros above diag)
__global__ void softmax_split_kernel(const float* __restrict__ sc,
                                     __half* __restrict__ ph, __half* __restrict__ pl,
                                     int S) {
    long row = blockIdx.x;
    int r = (int)(row & (S - 1));
    int len = r + 1;
    const float* p = sc + row * (long)S;
    float mx = -3.4e38f;
    for (int i = threadIdx.x; i < len; i += 256) mx = fmaxf(mx, p[i]);
    mx = block_max(mx);
    float sum = 0.f;
    for (int i = threadIdx.x; i < len; i += 256) sum += __expf(p[i] - mx);
    sum = block_sum(sum);
    float rinv = 1.f / sum;
    long o = row * (long)S;
    for (int i = threadIdx.x; i < len; i += 256)
        split_store_h(__expf(p[i] - mx) * rinv, ph, pl, o + i);
    __half z = __float2half_rn(0.f);
    for (int i = len + threadIdx.x; i < S; i += 256) { ph[o + i] = z; pl[o + i] = z; }
}

// ================= host launcher =================
extern "C" void kernel_launch(void* const* d_in, const int* in_sizes, int n_in,
                              void* d_out, int out_size) {
    const float* x         = (const float*)d_in[0];
    const float* ln1_w     = (const float*)d_in[1];
    const float* wqkv      = (const float*)d_in[2];
    const float* wo        = (const float*)d_in[3];
    const float* ln2_w     = (const float*)d_in[4];
    const float* w_gate_up = (const float*)d_in[5];
    const float* w_down    = (const float*)d_in[6];
    const int*   pos       = (const int*)d_in[7];
    float* out = (float*)d_out;

    const int S  = in_sizes[7];                 // 1024
    const long BS = (long)in_sizes[0] / HIDD;   // 4096
    const int Bb = (int)(BS / S);               // 4

    float *pQKV, *pSC, *pH1, *pGU;
    cudaGetSymbolAddress((void**)&pQKV, g_qkv);
    cudaGetSymbolAddress((void**)&pSC,  g_scores);
    cudaGetSymbolAddress((void**)&pH1,  g_h1);
    cudaGetSymbolAddress((void**)&pGU,  g_gu);
    __half *pHh,*pHl,*pAOh,*pAOl,*pACTh,*pACTl;
    __half *pQh,*pQl,*pKh,*pKl,*pVt,*pPh,*pPl;
    __half *pQKVT,*pWOT,*pGUT,*pDNT;
    cudaGetSymbolAddress((void**)&pHh, g_hh);     cudaGetSymbolAddress((void**)&pHl, g_hl);
    cudaGetSymbolAddress((void**)&pAOh, g_aoh);   cudaGetSymbolAddress((void**)&pAOl, g_aol);
    cudaGetSymbolAddress((void**)&pACTh, g_acth); cudaGetSymbolAddress((void**)&pACTl, g_actl);
    cudaGetSymbolAddress((void**)&pQh, g_qh);     cudaGetSymbolAddress((void**)&pQl, g_ql);
    cudaGetSymbolAddress((void**)&pKh, g_kh);     cudaGetSymbolAddress((void**)&pKl, g_kl);
    cudaGetSymbolAddress((void**)&pVt, g_vt);
    cudaGetSymbolAddress((void**)&pPh, g_ph);     cudaGetSymbolAddress((void**)&pPl, g_pl);
    cudaGetSymbolAddress((void**)&pQKVT, g_wqkvT);
    cudaGetSymbolAddress((void**)&pWOT, g_woT);
    cudaGetSymbolAddress((void**)&pGUT, g_guT);
    cudaGetSymbolAddress((void**)&pDNT, g_dnT);

    cudaFuncSetAttribute(hgemm<0,false>, cudaFuncAttributeMaxDynamicSharedMemorySize, HG_SMEM);
    cudaFuncSetAttribute(hgemm<0,true>,  cudaFuncAttributeMaxDynamicSharedMemorySize, HG_SMEM);
    cudaFuncSetAttribute(hgemm<1,false>, cudaFuncAttributeMaxDynamicSharedMemorySize, HG_SMEM);
    cudaFuncSetAttribute(hgemm<2,false>, cudaFuncAttributeMaxDynamicSharedMemorySize, HG_SMEM);

    dim3 blkT(32, 8);
    const float inv_sqrt_d = 0.08838834764831843f;

    // weight transpose+convert (fp16 single, [N,K])
    convT_h_kernel<<<dim3(QKVW/32,  HIDD/32), blkT>>>(wqkv,      pQKVT, HIDD, QKVW);
    convT_h_kernel<<<dim3(HIDD/32,  HIDD/32), blkT>>>(wo,        pWOT,  HIDD, HIDD);
    convT_h_kernel<<<dim3(2*FFI/32, HIDD/32), blkT>>>(w_gate_up, pGUT,  HIDD, 2*FFI);
    convT_h_kernel<<<dim3(HIDD/32,  FFI/32),  blkT>>>(w_down,    pDNT,  FFI,  HIDD);

    // 1. h = rmsnorm(x) -> fp16 hi/lo
    rmsnorm_h_kernel<<<(int)BS, 256>>>(x, ln1_w, pHh, pHl);

    // 2. qkv = h @ wqkv
    hgemm<0,false><<<dim3((int)(BS/128), QKVW/128, 1), 256, HG_SMEM>>>(
        pHh, pHl, pQKVT, nullptr, pQKV, nullptr, nullptr,
        HIDD, QKVW, 0, 0, 0, 0, 1.f);

    // 3. rope + split q,k ; transpose v
    conv_qk_kernel<<<(unsigned)((BS * (NH+NKV) * 64) / 256), 256>>>(pQKV, pos, pQh, pQl, pKh, pKl, S);
    conv_vt_kernel<<<dim3(S/32, HD/32, Bb*NKV), blkT>>>(pQKV, pVt, S);

    // 4. scores = QK^T/sqrt(D) (causal tiles only)
    hgemm<1,false><<<dim3(S/128, S/128, Bb*NH), 256, HG_SMEM>>>(
        pQh, pQl, pKh, nullptr, pSC, nullptr, nullptr,
        HD, S, (long)S*HD, (long)S*HD, (long)NH*S*S, (long)S*S, inv_sqrt_d);

    // 5. softmax -> P fp16 hi/lo
    softmax_split_kernel<<<(unsigned)(Bb*NH*S), 256>>>(pSC, pPh, pPl, S);

    // 6. attnout = P @ V -> fp16 hi/lo [b,s,h*d]
    hgemm<2,false><<<dim3(S/128, 1, Bb*NH), 256, HG_SMEM>>>(
        pPh, pPl, pVt, nullptr, nullptr, pAOh, pAOl,
        S, HIDD, (long)S*S, (long)HD*S, (long)S*HIDD, HD, 1.f);

    // 7. h1 = x + attnout @ wo
    hgemm<0,true><<<dim3((int)(BS/128), HIDD/128, 1), 256, HG_SMEM>>>(
        pAOh, pAOl, pWOT, x, pH1, nullptr, nullptr,
        HIDD, HIDD, 0, 0, 0, 0, 1.f);

    // 8. h2 = rmsnorm(h1)
    rmsnorm_h_kernel<<<(int)BS, 256>>>(pH1, ln2_w, pHh, pHl);

    // 9. gu = h2 @ w_gate_up
    hgemm<0,false><<<dim3((int)(BS/128), 2*FFI/128, 1), 256, HG_SMEM>>>(
        pHh, pHl, pGUT, nullptr, pGU, nullptr, nullptr,
        HIDD, 2*FFI, 0, 0, 0, 0, 1.f);

    // 10. act = silu(gate)*up -> fp16 hi/lo
    long total = BS * FFI;
    silu_h_kernel<<<(unsigned)((total + 255)/256), 256>>>(pGU, pACTh, pACTl, total);

    // 11. out = h1 + act @ w_down
    hgemm<0,true><<<dim3((int)(BS/128), HIDD/128, 1), 256, HG_SMEM>>>(
        pACTh, pACTl, pDNT, pH1, out, nullptr, nullptr,
        FFI, HIDD, 0, 0, 0, 0, 1.f);
}

// round 9
// speedup vs baseline: 6.4815x; 1.8140x over previous
#include <cuda_runtime.h>
#include <cuda_fp16.h>
#include <math.h>
#include <stdint.h>

#define NH   16
#define NKV  4
#define HD   128
#define HIDD 2048
#define FFI  8192
#define QKVW ((NH + 2*NKV) * HD)   /* 3072 */

// ================= scratch (B=4, S=1024) =================
static __device__ float g_qkv[4096L * QKVW];
static __device__ float g_scores[(long)4 * NH * 1024 * 1024];
static __device__ float g_h1[4096L * HIDD];
static __device__ float g_gu[4096L * 2 * FFI];

static __device__ __half g_h[4096L * HIDD];
static __device__ __half g_ao[4096L * HIDD];
static __device__ __half g_act[4096L * FFI];
static __device__ __half g_q[(long)4*NH*1024*HD];
static __device__ __half g_k[(long)4*NKV*1024*HD];
static __device__ __half g_vt[(long)4*NKV*HD*1024];
static __device__ __half g_p[(long)4*NH*1024*1024];
static __device__ __half g_wqkvT[(long)QKVW * HIDD];
static __device__ __half g_woT[(long)HIDD * HIDD];
static __device__ __half g_guT[(long)2*FFI * HIDD];
static __device__ __half g_dnT[(long)HIDD * FFI];

// ================= PTX helpers =================
__device__ __forceinline__ uint32_t smem_u32(const void* p) {
    uint32_t a;
    asm("{ .reg .u64 t; cvta.to.shared.u64 t, %1; cvt.u32.u64 %0, t; }" : "=r"(a) : "l"(p));
    return a;
}
__device__ __forceinline__ void cp16(uint32_t dst, const void* src) {
    asm volatile("cp.async.cg.shared.global [%0], [%1], 16;" :: "r"(dst), "l"(src));
}
__device__ __forceinline__ void cp_commit() { asm volatile("cp.async.commit_group;"); }
__device__ __forceinline__ void cp_wait1() { asm volatile("cp.async.wait_group 1;"); }
__device__ __forceinline__ void cp_wait0() { asm volatile("cp.async.wait_group 0;"); }

__device__ __forceinline__ void ldm_x4(uint32_t* r, uint32_t addr) {
    asm volatile("ldmatrix.sync.aligned.m8n8.x4.shared.b16 {%0,%1,%2,%3}, [%4];"
        : "=r"(r[0]), "=r"(r[1]), "=r"(r[2]), "=r"(r[3]) : "r"(addr));
}
__device__ __forceinline__ void mma16816h(float* d, const uint32_t* a, const uint32_t* b) {
    asm volatile("mma.sync.aligned.m16n8k16.row.col.f32.f16.f16.f32 "
        "{%0,%1,%2,%3}, {%4,%5,%6,%7}, {%8,%9}, {%0,%1,%2,%3};"
        : "+f"(d[0]), "+f"(d[1]), "+f"(d[2]), "+f"(d[3])
        : "r"(a[0]), "r"(a[1]), "r"(a[2]), "r"(a[3]), "r"(b[0]), "r"(b[1]));
}

// ================= fp16 TN GEMM =================
// C[M,N] = alpha * A[M,K] x (B[N,K])^T  (+ residual R)
// MODE 0: weights (fp32 out, optional residual, block swizzle)
// MODE 1: QK^T    (fp32 out, causal tile skip, per-head batch via z)
// MODE 2: PV      (fp16 out, K truncated by causality, per-head batch)
#define SAS 72
#define TILEB (128 * SAS * 2)     /* 18432 */
#define STAGE (2 * TILEB)         /* A B = 36864 */
#define HG_SMEM (2 * STAGE)       /* 73728 */

template<int MODE, bool RES>
__global__ void __launch_bounds__(256, 2)
hgemm(const __half* __restrict__ A, const __half* __restrict__ B,
      const float* __restrict__ R, float* __restrict__ Cf, __half* __restrict__ Ch,
      int K, int ldc, long sA, long sB, long sCb, long sCh, float alpha)
{
    extern __shared__ char sm[];
    const uint32_t sbase = smem_u32(sm);
    const int tid = threadIdx.x;

    int m0, n0;
    if (MODE == 0) {
        int lin = blockIdx.y * gridDim.x + blockIdx.x;
        int grpSize = gridDim.x * 8;
        int grp = lin / grpSize, rem = lin % grpSize;
        m0 = (rem >> 3) * 128;
        n0 = (grp * 8 + (rem & 7)) * 128;
    } else {
        m0 = blockIdx.x * 128;
        n0 = blockIdx.y * 128;
    }
    if (MODE == 1 && n0 > m0) return;

    const int z = blockIdx.z;
    const long offA = (long)z * sA;
    const long offB = (long)(z >> 2) * sB;
    const long offC = (long)(z >> 4) * sCb + (long)(z & 15) * sCh;

    int NB = K >> 6;
    if (MODE == 2) { int nbe = (m0 >> 6) + 2; if (nbe < NB) NB = nbe; }

    const int wid = tid >> 5, lane = tid & 31;
    const int wm = (wid >> 2) * 64;
    const int wn = (wid & 3) * 32;

    const __half* srcs[2] = { A + offA + (long)m0 * K, B + offB + (long)n0 * K };

    const int alr = lane & 15, alc = (lane >> 4) * 8;
    const int blr = lane & 7;
    const int bhalf = (lane >> 3) & 1;
    const int bquad = (lane >> 4) * 8;

    float acc[4][4][4];
    #pragma unroll
    for (int i = 0; i < 4; i++)
        #pragma unroll
        for (int j = 0; j < 4; j++)
            #pragma unroll
            for (int q = 0; q < 4; q++) acc[i][j][q] = 0.f;

    auto load_stage = [&](int s, int blk) {
        const long kb = (long)blk << 6;
        #pragma unroll
        for (int t = 0; t < 2; t++) {
            const __half* S = srcs[t] + kb;
            const uint32_t dbase = sbase + s * STAGE + t * TILEB;
            #pragma unroll
            for (int i = 0; i < 4; i++) {
                int idx = tid + 256 * i;
                int r = idx >> 3, c = idx & 7;
                cp16(dbase + (r * SAS + c * 8) * 2, S + (long)r * K + c * 8);
            }
        }
        cp_commit();
    };

    load_stage(0, 0);

    for (int blk = 0; blk < NB; blk++) {
        const int s = blk & 1;
        if (blk + 1 < NB) { load_stage(s ^ 1, blk + 1); cp_wait1(); }
        else              { cp_wait0(); }
        __syncthreads();

        const uint32_t sA_ = sbase + s * STAGE;
        const uint32_t sB_ = sA_ + TILEB;

        #pragma unroll
        for (int kt = 0; kt < 4; kt++) {
            uint32_t aa[4][4], bb[4][2];
            #pragma unroll
            for (int ma = 0; ma < 4; ma++) {
                uint32_t ao = ((wm + ma * 16 + alr) * SAS + kt * 16 + alc) * 2;
                ldm_x4(aa[ma], sA_ + ao);
            }
            #pragma unroll
            for (int np = 0; np < 2; np++) {
                uint32_t bo = ((wn + np * 16 + bquad + blr) * SAS + kt * 16 + bhalf * 8) * 2;
                uint32_t t4[4];
                ldm_x4(t4, sB_ + bo);
                bb[np*2+0][0] = t4[0]; bb[np*2+0][1] = t4[1];
                bb[np*2+1][0] = t4[2]; bb[np*2+1][1] = t4[3];
            }
            #pragma unroll
            for (int ma = 0; ma < 4; ma++)
                #pragma unroll
                for (int na = 0; na < 4; na++)
                    mma16816h(acc[ma][na], aa[ma], bb[na]);
        }
        __syncthreads();
    }

    const int erow = lane >> 2, ecol = (lane & 3) * 2;
    #pragma unroll
    for (int ma = 0; ma < 4; ma++) {
        #pragma unroll
        for (int na = 0; na < 4; na++) {
            long r0 = m0 + wm + ma * 16 + erow;
            long cc = n0 + wn + na * 8 + ecol;
            float v00 = acc[ma][na][0] * alpha, v01 = acc[ma][na][1] * alpha;
            float v10 = acc[ma][na][2] * alpha, v11 = acc[ma][na][3] * alpha;
            if (MODE == 2) {
                long o0 = offC + r0 * ldc + cc;
                long o1 = offC + (r0 + 8) * ldc + cc;
                __half2 h0 = { __float2half_rn(v00), __float2half_rn(v01) };
                __half2 h1 = { __float2half_rn(v10), __float2half_rn(v11) };
                *(__half2*)&Ch[o0] = h0;
                *(__half2*)&Ch[o1] = h1;
            } else {
                if (RES) {
                    const float2 q0 = *(const float2*)&R[offC + r0 * ldc + cc];
                    const float2 q1 = *(const float2*)&R[offC + (r0 + 8) * ldc + cc];
                    v00 += q0.x; v01 += q0.y; v10 += q1.x; v11 += q1.y;
                }
                float2 w0 = {v00, v01}, w1 = {v10, v11};
                *(float2*)&Cf[offC + r0 * ldc + cc] = w0;
                *(float2*)&Cf[offC + (r0 + 8) * ldc + cc] = w1;
            }
        }
    }
}

// ================= block reductions =================
__device__ __forceinline__ float block_sum(float v) {
    #pragma unroll
    for (int o = 16; o > 0; o >>= 1) v += __shfl_xor_sync(0xffffffffu, v, o);
    __shared__ float sh[8]; __shared__ float total;
    int w = threadIdx.x >> 5, l = threadIdx.x & 31;
    if (l == 0) sh[w] = v;
    __syncthreads();
    if (threadIdx.x == 0) { float s = 0.f; for (int i = 0; i < 8; i++) s += sh[i]; total = s; }
    __syncthreads();
    return total;
}
__device__ __forceinline__ float block_max(float v) {
    #pragma unroll
    for (int o = 16; o > 0; o >>= 1) v = fmaxf(v, __shfl_xor_sync(0xffffffffu, v, o));
    __shared__ float shm[8]; __shared__ float totalm;
    int w = threadIdx.x >> 5, l = threadIdx.x & 31;
    if (l == 0) shm[w] = v;
    __syncthreads();
    if (threadIdx.x == 0) { float s = -3.4e38f; for (int i = 0; i < 8; i++) s = fmaxf(s, shm[i]); totalm = s; }
    __syncthreads();
    return totalm;
}

// ================= elementwise =================
__global__ void rmsnorm_h_kernel(const float* __restrict__ x, const float* __restrict__ w,
                                 __half* __restrict__ out) {
    long row = blockIdx.x;
    const float* xr = x + row * HIDD;
    float s = 0.f;
    for (int i = threadIdx.x; i < HIDD; i += 256) { float v = xr[i]; s += v * v; }
    s = block_sum(s);
    float inv = rsqrtf(s / (float)HIDD + 1e-6f);
    for (int i = threadIdx.x; i < HIDD; i += 256)
        out[row * HIDD + i] = __float2half_rn(xr[i] * inv * w[i]);
}

__global__ void silu_h_kernel(const float* __restrict__ gu, __half* __restrict__ out, long total) {
    long idx = (long)blockIdx.x * 256 + threadIdx.x;
    if (idx >= total) return;
    long row = idx / FFI;
    int  j   = (int)(idx - row * FFI);
    float g = gu[row * (2L * FFI) + j];
    float u = gu[row * (2L * FFI) + FFI + j];
    out[idx] = __float2half_rn((g / (1.f + expf(-g))) * u);
}

// transpose-convert: W [K,N] fp32 -> T [N,K] fp16
__global__ void convT_h_kernel(const float* __restrict__ W, __half* __restrict__ T,
                               int K, int N) {
    __shared__ float t[32][33];
    int n0 = blockIdx.x * 32, k0 = blockIdx.y * 32;
    for (int i = threadIdx.y; i < 32; i += 8)
        t[i][threadIdx.x] = W[(long)(k0 + i) * N + n0 + threadIdx.x];
    __syncthreads();
    for (int i = threadIdx.y; i < 32; i += 8)
        T[(long)(n0 + i) * K + k0 + threadIdx.x] = __float2half_rn(t[threadIdx.x][i]);
}

// rope + split q,k: qkv fp32 -> fp16 per-head layouts
__global__ void conv_qk_kernel(const float* __restrict__ qkv, const int* __restrict__ pos,
                               __half* __restrict__ q, __half* __restrict__ k, int S) {
    long idx = (long)blockIdx.x * 256 + threadIdx.x;
    int d = (int)(idx & 63);
    long t = idx >> 6;
    int head = (int)(t % (NH + NKV)); t /= (NH + NKV);
    int s = (int)(t % S);
    int b = (int)(t / S);
    const float* base = qkv + ((long)(b * S + s)) * QKVW + head * HD;
    float t1 = base[d], t2 = base[d + 64];
    float invf = powf(10000.f, -(float)d / 64.f);
    float ang = (float)pos[s] * invf;
    float sn, cs;
    sincosf(ang, &sn, &cs);
    float r1 = t1 * cs - t2 * sn;
    float r2 = t2 * cs + t1 * sn;
    if (head < NH) {
        long o = ((long)(b * NH + head) * S + s) * HD;
        q[o + d] = __float2half_rn(r1);
        q[o + d + 64] = __float2half_rn(r2);
    } else {
        long o = ((long)(b * NKV + head - NH) * S + s) * HD;
        k[o + d] = __float2half_rn(r1);
        k[o + d + 64] = __float2half_rn(r2);
    }
}

// v transpose: qkv v slice [b,s,hk,128] -> vt [b,hk,d,s] fp16
__global__ void conv_vt_kernel(const float* __restrict__ qkv, __half* __restrict__ vt, int S) {
    __shared__ float t[32][33];
    int s0 = blockIdx.x * 32, d0 = blockIdx.y * 32;
    int z = blockIdx.z;
    int b = z >> 2, h = z & 3;
    for (int i = threadIdx.y; i < 32; i += 8)
        t[i][threadIdx.x] = qkv[((long)(b * S + s0 + i)) * QKVW + (NH + NKV + h) * HD + d0 + threadIdx.x];
    __syncthreads();
    for (int i = threadIdx.y; i < 32; i += 8)
        vt[((long)z * HD + d0 + i) * S + s0 + threadIdx.x] = __float2half_rn(t[threadIdx.x][i]);
}

// causal softmax: fp32 scores -> P fp16 (zeros above diag)
__global__ void softmax_h_kernel(const float* __restrict__ sc, __half* __restrict__ p, int S) {
    long row = blockIdx.x;
    int r = (int)(row & (S - 1));
    int len = r + 1;
    const float* pr = sc + row * (long)S;
    float mx = -3.4e38f;
    for (int i = threadIdx.x; i < len; i += 256) mx = fmaxf(mx, pr[i]);
    mx = block_max(mx);
    float sum = 0.f;
    for (int i = threadIdx.x; i < len; i += 256) sum += __expf(pr[i] - mx);
    sum = block_sum(sum);
    float rinv = 1.f / sum;
    long o = row * (long)S;
    for (int i = threadIdx.x; i < len; i += 256)
        p[o + i] = __float2half_rn(__expf(pr[i] - mx) * rinv);
    __half z = __float2half_rn(0.f);
    for (int i = len + threadIdx.x; i < S; i += 256) p[o + i] = z;
}

// ================= host launcher =================
extern "C" void kernel_launch(void* const* d_in, const int* in_sizes, int n_in,
                              void* d_out, int out_size) {
    const float* x         = (const float*)d_in[0];
    const float* ln1_w     = (const float*)d_in[1];
    const float* wqkv      = (const float*)d_in[2];
    const float* wo        = (const float*)d_in[3];
    const float* ln2_w     = (const float*)d_in[4];
    const float* w_gate_up = (const float*)d_in[5];
    const float* w_down    = (const float*)d_in[6];
    const int*   pos       = (const int*)d_in[7];
    float* out = (float*)d_out;

    const int S  = in_sizes[7];                 // 1024
    const long BS = (long)in_sizes[0] / HIDD;   // 4096
    const int Bb = (int)(BS / S);               // 4

    float *pQKV, *pSC, *pH1, *pGU;
    cudaGetSymbolAddress((void**)&pQKV, g_qkv);
    cudaGetSymbolAddress((void**)&pSC,  g_scores);
    cudaGetSymbolAddress((void**)&pH1,  g_h1);
    cudaGetSymbolAddress((void**)&pGU,  g_gu);
    __half *pH,*pAO,*pACT,*pQ,*pK,*pVt,*pP;
    __half *pQKVT,*pWOT,*pGUT,*pDNT;
    cudaGetSymbolAddress((void**)&pH, g_h);
    cudaGetSymbolAddress((void**)&pAO, g_ao);
    cudaGetSymbolAddress((void**)&pACT, g_act);
    cudaGetSymbolAddress((void**)&pQ, g_q);
    cudaGetSymbolAddress((void**)&pK, g_k);
    cudaGetSymbolAddress((void**)&pVt, g_vt);
    cudaGetSymbolAddress((void**)&pP, g_p);
    cudaGetSymbolAddress((void**)&pQKVT, g_wqkvT);
    cudaGetSymbolAddress((void**)&pWOT, g_woT);
    cudaGetSymbolAddress((void**)&pGUT, g_guT);
    cudaGetSymbolAddress((void**)&pDNT, g_dnT);

    cudaFuncSetAttribute(hgemm<0,false>, cudaFuncAttributeMaxDynamicSharedMemorySize, HG_SMEM);
    cudaFuncSetAttribute(hgemm<0,true>,  cudaFuncAttributeMaxDynamicSharedMemorySize, HG_SMEM);
    cudaFuncSetAttribute(hgemm<1,false>, cudaFuncAttributeMaxDynamicSharedMemorySize, HG_SMEM);
    cudaFuncSetAttribute(hgemm<2,false>, cudaFuncAttributeMaxDynamicSharedMemorySize, HG_SMEM);

    dim3 blkT(32, 8);
    const float inv_sqrt_d = 0.08838834764831843f;

    // weight transpose+convert (fp16, [N,K])
    convT_h_kernel<<<dim3(QKVW/32,  HIDD/32), blkT>>>(wqkv,      pQKVT, HIDD, QKVW);
    convT_h_kernel<<<dim3(HIDD/32,  HIDD/32), blkT>>>(wo,        pWOT,  HIDD, HIDD);
    convT_h_kernel<<<dim3(2*FFI/32, HIDD/32), blkT>>>(w_gate_up, pGUT,  HIDD, 2*FFI);
    convT_h_kernel<<<dim3(HIDD/32,  FFI/32),  blkT>>>(w_down,    pDNT,  FFI,  HIDD);

    // 1. h = rmsnorm(x) -> fp16
    rmsnorm_h_kernel<<<(int)BS, 256>>>(x, ln1_w, pH);

    // 2. qkv = h @ wqkv
    hgemm<0,false><<<dim3((int)(BS/128), QKVW/128, 1), 256, HG_SMEM>>>(
        pH, pQKVT, nullptr, pQKV, nullptr, HIDD, QKVW, 0, 0, 0, 0, 1.f);

    // 3. rope + split q,k ; transpose v
    conv_qk_kernel<<<(unsigned)((BS * (NH+NKV) * 64) / 256), 256>>>(pQKV, pos, pQ, pK, S);
    conv_vt_kernel<<<dim3(S/32, HD/32, Bb*NKV), blkT>>>(pQKV, pVt, S);

    // 4. scores = QK^T/sqrt(D) (causal tiles only)
    hgemm<1,false><<<dim3(S/128, S/128, Bb*NH), 256, HG_SMEM>>>(
        pQ, pK, nullptr, pSC, nullptr,
        HD, S, (long)S*HD, (long)S*HD, (long)NH*S*S, (long)S*S, inv_sqrt_d);

    // 5. softmax -> P fp16
    softmax_h_kernel<<<(unsigned)(Bb*NH*S), 256>>>(pSC, pP, S);

    // 6. attnout = P @ V -> fp16 [b,s,h*d]
    hgemm<2,false><<<dim3(S/128, 1, Bb*NH), 256, HG_SMEM>>>(
        pP, pVt, nullptr, nullptr, pAO,
        S, HIDD, (long)S*S, (long)HD*S, (long)S*HIDD, HD, 1.f);

    // 7. h1 = x + attnout @ wo
    hgemm<0,true><<<dim3((int)(BS/128), HIDD/128, 1), 256, HG_SMEM>>>(
        pAO, pWOT, x, pH1, nullptr, HIDD, HIDD, 0, 0, 0, 0, 1.f);

    // 8. h2 = rmsnorm(h1)
    rmsnorm_h_kernel<<<(int)BS, 256>>>(pH1, ln2_w, pH);

    // 9. gu = h2 @ w_gate_up
    hgemm<0,false><<<dim3((int)(BS/128), 2*FFI/128, 1), 256, HG_SMEM>>>(
        pH, pGUT, nullptr, pGU, nullptr, HIDD, 2*FFI, 0, 0, 0, 0, 1.f);

    // 10. act = silu(gate)*up -> fp16
    long total = BS * FFI;
    silu_h_kernel<<<(unsigned)((total + 255)/256), 256>>>(pGU, pACT, total);

    // 11. out = h1 + act @ w_down
    hgemm<0,true><<<dim3((int)(BS/128), HIDD/128, 1), 256, HG_SMEM>>>(
        pACT, pDNT, pH1, out, nullptr, FFI, HIDD, 0, 0, 0, 0, 1.f);
}

// round 10
// speedup vs baseline: 6.7872x; 1.0472x over previous
#include <cuda_runtime.h>
#include <cuda_fp16.h>
#include <math.h>
#include <stdint.h>

#define NH   16
#define NKV  4
#define HD   128
#define HIDD 2048
#define FFI  8192
#define QKVW ((NH + 2*NKV) * HD)   /* 3072 */

// ================= scratch (B=4, S=1024) =================
static __device__ float g_qkv[4096L * QKVW];
static __device__ float g_scores[(long)4 * NH * 1024 * 1024];
static __device__ float g_h1[4096L * HIDD];

static __device__ __half g_h[4096L * HIDD];
static __device__ __half g_ao[4096L * HIDD];
static __device__ __half g_act[4096L * FFI];
static __device__ __half g_q[(long)4*NH*1024*HD];
static __device__ __half g_k[(long)4*NKV*1024*HD];
static __device__ __half g_vt[(long)4*NKV*HD*1024];
static __device__ __half g_p[(long)4*NH*1024*1024];
static __device__ __half g_wqkvT[(long)QKVW * HIDD];
static __device__ __half g_woT[(long)HIDD * HIDD];
static __device__ __half g_guT[(long)2*FFI * HIDD];   /* interleaved gate/up rows */
static __device__ __half g_dnT[(long)HIDD * FFI];

// ================= PTX helpers =================
__device__ __forceinline__ uint32_t smem_u32(const void* p) {
    uint32_t a;
    asm("{ .reg .u64 t; cvta.to.shared.u64 t, %1; cvt.u32.u64 %0, t; }" : "=r"(a) : "l"(p));
    return a;
}
__device__ __forceinline__ void cp16(uint32_t dst, const void* src) {
    asm volatile("cp.async.cg.shared.global [%0], [%1], 16;" :: "r"(dst), "l"(src));
}
__device__ __forceinline__ void cp_commit() { asm volatile("cp.async.commit_group;"); }
__device__ __forceinline__ void cp_wait1() { asm volatile("cp.async.wait_group 1;"); }
__device__ __forceinline__ void cp_wait0() { asm volatile("cp.async.wait_group 0;"); }

__device__ __forceinline__ void ldm_x4(uint32_t* r, uint32_t addr) {
    asm volatile("ldmatrix.sync.aligned.m8n8.x4.shared.b16 {%0,%1,%2,%3}, [%4];"
        : "=r"(r[0]), "=r"(r[1]), "=r"(r[2]), "=r"(r[3]) : "r"(addr));
}
__device__ __forceinline__ void mma16816h(float* d, const uint32_t* a, const uint32_t* b) {
    asm volatile("mma.sync.aligned.m16n8k16.row.col.f32.f16.f16.f32 "
        "{%0,%1,%2,%3}, {%4,%5,%6,%7}, {%8,%9}, {%0,%1,%2,%3};"
        : "+f"(d[0]), "+f"(d[1]), "+f"(d[2]), "+f"(d[3])
        : "r"(a[0]), "r"(a[1]), "r"(a[2]), "r"(a[3]), "r"(b[0]), "r"(b[1]));
}
__device__ __forceinline__ float silu_mul(float g, float u) {
    return (g / (1.f + __expf(-g))) * u;
}

// ================= fp16 TN GEMM =================
// MODE 0: weights (fp32 out, optional residual, block swizzle)
// MODE 1: QK^T    (fp32 out, causal tile skip, per-head batch via z)
// MODE 2: PV      (fp16 out, K truncated by causality, per-head batch)
// MODE 3: gate_up (interleaved B rows; epilogue silu(gate)*up -> fp16, block swizzle)
#define SAS 72
#define TILEB (128 * SAS * 2)     /* 18432 */
#define STAGE (2 * TILEB)         /* 36864 */
#define HG_SMEM (2 * STAGE)       /* 73728 */

template<int MODE, bool RES>
__global__ void __launch_bounds__(256, 2)
hgemm(const __half* __restrict__ A, const __half* __restrict__ B,
      const float* __restrict__ R, float* __restrict__ Cf, __half* __restrict__ Ch,
      int K, int ldc, long sA, long sB, long sCb, long sCh, float alpha)
{
    extern __shared__ char sm[];
    const uint32_t sbase = smem_u32(sm);
    const int tid = threadIdx.x;

    int m0, n0;
    if (MODE == 0 || MODE == 3) {
        int lin = blockIdx.y * gridDim.x + blockIdx.x;
        int grpSize = gridDim.x * 8;
        int grp = lin / grpSize, rem = lin % grpSize;
        m0 = (rem >> 3) * 128;
        n0 = (grp * 8 + (rem & 7)) * 128;
    } else {
        m0 = blockIdx.x * 128;
        n0 = blockIdx.y * 128;
    }
    if (MODE == 1 && n0 > m0) return;

    const int z = blockIdx.z;
    const long offA = (long)z * sA;
    const long offB = (long)(z >> 2) * sB;
    const long offC = (long)(z >> 4) * sCb + (long)(z & 15) * sCh;

    int NB = K >> 6;
    if (MODE == 2) { int nbe = (m0 >> 6) + 2; if (nbe < NB) NB = nbe; }

    const int wid = tid >> 5, lane = tid & 31;
    const int wm = (wid >> 2) * 64;
    const int wn = (wid & 3) * 32;

    const __half* srcs[2] = { A + offA + (long)m0 * K, B + offB + (long)n0 * K };

    const int alr = lane & 15, alc = (lane >> 4) * 8;
    const int blr = lane & 7;
    const int bhalf = (lane >> 3) & 1;
    const int bquad = (lane >> 4) * 8;

    float acc[4][4][4];
    #pragma unroll
    for (int i = 0; i < 4; i++)
        #pragma unroll
        for (int j = 0; j < 4; j++)
            #pragma unroll
            for (int q = 0; q < 4; q++) acc[i][j][q] = 0.f;

    auto load_stage = [&](int s, int blk) {
        const long kb = (long)blk << 6;
        #pragma unroll
        for (int t = 0; t < 2; t++) {
            const __half* S = srcs[t] + kb;
            const uint32_t dbase = sbase + s * STAGE + t * TILEB;
            #pragma unroll
            for (int i = 0; i < 4; i++) {
                int idx = tid + 256 * i;
                int r = idx >> 3, c = idx & 7;
                cp16(dbase + (r * SAS + c * 8) * 2, S + (long)r * K + c * 8);
            }
        }
        cp_commit();
    };

    load_stage(0, 0);

    for (int blk = 0; blk < NB; blk++) {
        const int s = blk & 1;
        if (blk + 1 < NB) { load_stage(s ^ 1, blk + 1); cp_wait1(); }
        else              { cp_wait0(); }
        __syncthreads();

        const uint32_t sA_ = sbase + s * STAGE;
        const uint32_t sB_ = sA_ + TILEB;

        #pragma unroll
        for (int kt = 0; kt < 4; kt++) {
            uint32_t aa[4][4], bb[4][2];
            #pragma unroll
            for (int ma = 0; ma < 4; ma++) {
                uint32_t ao = ((wm + ma * 16 + alr) * SAS + kt * 16 + alc) * 2;
                ldm_x4(aa[ma], sA_ + ao);
            }
            #pragma unroll
            for (int np = 0; np < 2; np++) {
                uint32_t bo = ((wn + np * 16 + bquad + blr) * SAS + kt * 16 + bhalf * 8) * 2;
                uint32_t t4[4];
                ldm_x4(t4, sB_ + bo);
                bb[np*2+0][0] = t4[0]; bb[np*2+0][1] = t4[1];
                bb[np*2+1][0] = t4[2]; bb[np*2+1][1] = t4[3];
            }
            #pragma unroll
            for (int ma = 0; ma < 4; ma++)
                #pragma unroll
                for (int na = 0; na < 4; na++)
                    mma16816h(acc[ma][na], aa[ma], bb[na]);
        }
        __syncthreads();
    }

    const int erow = lane >> 2, ecol = (lane & 3) * 2;
    #pragma unroll
    for (int ma = 0; ma < 4; ma++) {
        #pragma unroll
        for (int na = 0; na < 4; na++) {
            long r0 = m0 + wm + ma * 16 + erow;
            long cc = n0 + wn + na * 8 + ecol;
            float v00 = acc[ma][na][0] * alpha, v01 = acc[ma][na][1] * alpha;
            float v10 = acc[ma][na][2] * alpha, v11 = acc[ma][na][3] * alpha;
            if (MODE == 2) {
                long o0 = offC + r0 * ldc + cc;
                long o1 = offC + (r0 + 8) * ldc + cc;
                __half2 h0 = { __float2half_rn(v00), __float2half_rn(v01) };
                __half2 h1 = { __float2half_rn(v10), __float2half_rn(v11) };
                *(__half2*)&Ch[o0] = h0;
                *(__half2*)&Ch[o1] = h1;
            } else if (MODE == 3) {
                // cc even: (v00,v01) = (gate_j, up_j), j = cc>>1
                long j = cc >> 1;
                Ch[r0 * (long)FFI + j]       = __float2half_rn(silu_mul(v00, v01));
                Ch[(r0 + 8) * (long)FFI + j] = __float2half_rn(silu_mul(v10, v11));
            } else {
                if (RES) {
                    const float2 q0 = *(const float2*)&R[offC + r0 * ldc + cc];
                    const float2 q1 = *(const float2*)&R[offC + (r0 + 8) * ldc + cc];
                    v00 += q0.x; v01 += q0.y; v10 += q1.x; v11 += q1.y;
                }
                float2 w0 = {v00, v01}, w1 = {v10, v11};
                *(float2*)&Cf[offC + r0 * ldc + cc] = w0;
                *(float2*)&Cf[offC + (r0 + 8) * ldc + cc] = w1;
            }
        }
    }
}

// ================= block reductions =================
__device__ __forceinline__ float block_sum(float v) {
    #pragma unroll
    for (int o = 16; o > 0; o >>= 1) v += __shfl_xor_sync(0xffffffffu, v, o);
    __shared__ float sh[8]; __shared__ float total;
    int w = threadIdx.x >> 5, l = threadIdx.x & 31;
    if (l == 0) sh[w] = v;
    __syncthreads();
    if (threadIdx.x == 0) { float s = 0.f; for (int i = 0; i < 8; i++) s += sh[i]; total = s; }
    __syncthreads();
    return total;
}
__device__ __forceinline__ float block_max(float v) {
    #pragma unroll
    for (int o = 16; o > 0; o >>= 1) v = fmaxf(v, __shfl_xor_sync(0xffffffffu, v, o));
    __shared__ float shm[8]; __shared__ float totalm;
    int w = threadIdx.x >> 5, l = threadIdx.x & 31;
    if (l == 0) shm[w] = v;
    __syncthreads();
    if (threadIdx.x == 0) { float s = -3.4e38f; for (int i = 0; i < 8; i++) s = fmaxf(s, shm[i]); totalm = s; }
    __syncthreads();
    return totalm;
}

// ================= elementwise =================
__global__ void rmsnorm_h_kernel(const float* __restrict__ x, const float* __restrict__ w,
                                 __half* __restrict__ out) {
    long row = blockIdx.x;
    const float* xr = x + row * HIDD;
    float s = 0.f;
    for (int i = threadIdx.x; i < HIDD; i += 256) { float v = xr[i]; s += v * v; }
    s = block_sum(s);
    float inv = rsqrtf(s / (float)HIDD + 1e-6f);
    for (int i = threadIdx.x; i < HIDD; i += 256)
        out[row * HIDD + i] = __float2half_rn(xr[i] * inv * w[i]);
}

// transpose-convert: W [K,N] fp32 -> T [N*rowMul + rowAdd, K] fp16 (strided rows)
__global__ void convT_h_kernel(const float* __restrict__ W, __half* __restrict__ T,
                               int K, int N, int rowMul, int rowAdd) {
    __shared__ float t[32][33];
    int n0 = blockIdx.x * 32, k0 = blockIdx.y * 32;
    for (int i = threadIdx.y; i < 32; i += 8)
        t[i][threadIdx.x] = W[(long)(k0 + i) * N + n0 + threadIdx.x];
    __syncthreads();
    for (int i = threadIdx.y; i < 32; i += 8)
        T[(long)((n0 + i) * rowMul + rowAdd) * K + k0 + threadIdx.x] = __float2half_rn(t[threadIdx.x][i]);
}

// rope + split q,k
__global__ void conv_qk_kernel(const float* __restrict__ qkv, const int* __restrict__ pos,
                               __half* __restrict__ q, __half* __restrict__ k, int S) {
    long idx = (long)blockIdx.x * 256 + threadIdx.x;
    int d = (int)(idx & 63);
    long t = idx >> 6;
    int head = (int)(t % (NH + NKV)); t /= (NH + NKV);
    int s = (int)(t % S);
    int b = (int)(t / S);
    const float* base = qkv + ((long)(b * S + s)) * QKVW + head * HD;
    float t1 = base[d], t2 = base[d + 64];
    float invf = __powf(10000.f, -(float)d * (1.f/64.f));
    float ang = (float)pos[s] * invf;
    float sn, cs;
    __sincosf(ang, &sn, &cs);
    float r1 = t1 * cs - t2 * sn;
    float r2 = t2 * cs + t1 * sn;
    if (head < NH) {
        long o = ((long)(b * NH + head) * S + s) * HD;
        q[o + d] = __float2half_rn(r1);
        q[o + d + 64] = __float2half_rn(r2);
    } else {
        long o = ((long)(b * NKV + head - NH) * S + s) * HD;
        k[o + d] = __float2half_rn(r1);
        k[o + d + 64] = __float2half_rn(r2);
    }
}

// v transpose: qkv v slice -> vt [b,hk,d,s] fp16
__global__ void conv_vt_kernel(const float* __restrict__ qkv, __half* __restrict__ vt, int S) {
    __shared__ float t[32][33];
    int s0 = blockIdx.x * 32, d0 = blockIdx.y * 32;
    int z = blockIdx.z;
    int b = z >> 2, h = z & 3;
    for (int i = threadIdx.y; i < 32; i += 8)
        t[i][threadIdx.x] = qkv[((long)(b * S + s0 + i)) * QKVW + (NH + NKV + h) * HD + d0 + threadIdx.x];
    __syncthreads();
    for (int i = threadIdx.y; i < 32; i += 8)
        vt[((long)z * HD + d0 + i) * S + s0 + threadIdx.x] = __float2half_rn(t[threadIdx.x][i]);
}

// causal softmax: fp32 scores -> P fp16; single exp evaluation
__global__ void softmax_h_kernel(const float* __restrict__ sc, __half* __restrict__ p, int S) {
    long row = blockIdx.x;
    int r = (int)(row & (S - 1));
    int len = r + 1;
    const float* pr = sc + row * (long)S;
    long o = row * (long)S;
    float mx = -3.4e38f;
    for (int i = threadIdx.x; i < len; i += 256) mx = fmaxf(mx, pr[i]);
    mx = block_max(mx);
    float sum = 0.f;
    for (int i = threadIdx.x; i < len; i += 256) {
        float e = __expf(pr[i] - mx);
        p[o + i] = __float2half_rn(e);
        sum += e;
    }
    sum = block_sum(sum);
    __half2 rinv2 = __float2half2_rn(1.f / sum);
    // scale stored exp values in place (fp16)
    int len2 = len >> 1;
    __half2* p2 = (__half2*)(p + o);
    for (int i = threadIdx.x; i < len2; i += 256) p2[i] = __hmul2(p2[i], rinv2);
    if ((len & 1) && threadIdx.x == 0) p[o + len - 1] = __hmul(p[o + len - 1], __low2half(rinv2));
    __half z = __float2half_rn(0.f);
    for (int i = len + threadIdx.x; i < S; i += 256) p[o + i] = z;
}

// ================= host launcher =================
extern "C" void kernel_launch(void* const* d_in, const int* in_sizes, int n_in,
                              void* d_out, int out_size) {
    const float* x         = (const float*)d_in[0];
    const float* ln1_w     = (const float*)d_in[1];
    const float* wqkv      = (const float*)d_in[2];
    const float* wo        = (const float*)d_in[3];
    const float* ln2_w     = (const float*)d_in[4];
    const float* w_gate_up = (const float*)d_in[5];
    const float* w_down    = (const float*)d_in[6];
    const int*   pos       = (const int*)d_in[7];
    float* out = (float*)d_out;

    const int S  = in_sizes[7];                 // 1024
    const long BS = (long)in_sizes[0] / HIDD;   // 4096
    const int Bb = (int)(BS / S);               // 4

    float *pQKV, *pSC, *pH1;
    cudaGetSymbolAddress((void**)&pQKV, g_qkv);
    cudaGetSymbolAddress((void**)&pSC,  g_scores);
    cudaGetSymbolAddress((void**)&pH1,  g_h1);
    __half *pH,*pAO,*pACT,*pQ,*pK,*pVt,*pP;
    __half *pQKVT,*pWOT,*pGUT,*pDNT;
    cudaGetSymbolAddress((void**)&pH, g_h);
    cudaGetSymbolAddress((void**)&pAO, g_ao);
    cudaGetSymbolAddress((void**)&pACT, g_act);
    cudaGetSymbolAddress((void**)&pQ, g_q);
    cudaGetSymbolAddress((void**)&pK, g_k);
    cudaGetSymbolAddress((void**)&pVt, g_vt);
    cudaGetSymbolAddress((void**)&pP, g_p);
    cudaGetSymbolAddress((void**)&pQKVT, g_wqkvT);
    cudaGetSymbolAddress((void**)&pWOT, g_woT);
    cudaGetSymbolAddress((void**)&pGUT, g_guT);
    cudaGetSymbolAddress((void**)&pDNT, g_dnT);

    cudaFuncSetAttribute(hgemm<0,false>, cudaFuncAttributeMaxDynamicSharedMemorySize, HG_SMEM);
    cudaFuncSetAttribute(hgemm<0,true>,  cudaFuncAttributeMaxDynamicSharedMemorySize, HG_SMEM);
    cudaFuncSetAttribute(hgemm<1,false>, cudaFuncAttributeMaxDynamicSharedMemorySize, HG_SMEM);
    cudaFuncSetAttribute(hgemm<2,false>, cudaFuncAttributeMaxDynamicSharedMemorySize, HG_SMEM);
    cudaFuncSetAttribute(hgemm<3,false>, cudaFuncAttributeMaxDynamicSharedMemorySize, HG_SMEM);

    dim3 blkT(32, 8);
    const float inv_sqrt_d = 0.08838834764831843f;

    // weight transpose+convert (fp16, [N,K]); gate/up interleaved rows
    convT_h_kernel<<<dim3(QKVW/32,  HIDD/32), blkT>>>(wqkv,      pQKVT, HIDD, QKVW, 1, 0);
    convT_h_kernel<<<dim3(HIDD/32,  HIDD/32), blkT>>>(wo,        pWOT,  HIDD, HIDD, 1, 0);
    convT_h_kernel<<<dim3(FFI/32,   HIDD/32), blkT>>>(w_gate_up,       pGUT, HIDD, 2*FFI, 2, 0);
    convT_h_kernel<<<dim3(FFI/32,   HIDD/32), blkT>>>(w_gate_up + FFI, pGUT, HIDD, 2*FFI, 2, 1);
    convT_h_kernel<<<dim3(HIDD/32,  FFI/32),  blkT>>>(w_down,    pDNT,  FFI,  HIDD, 1, 0);

    // 1. h = rmsnorm(x) -> fp16
    rmsnorm_h_kernel<<<(int)BS, 256>>>(x, ln1_w, pH);

    // 2. qkv = h @ wqkv
    hgemm<0,false><<<dim3((int)(BS/128), QKVW/128, 1), 256, HG_SMEM>>>(
        pH, pQKVT, nullptr, pQKV, nullptr, HIDD, QKVW, 0, 0, 0, 0, 1.f);

    // 3. rope + split q,k ; transpose v
    conv_qk_kernel<<<(unsigned)((BS * (NH+NKV) * 64) / 256), 256>>>(pQKV, pos, pQ, pK, S);
    conv_vt_kernel<<<dim3(S/32, HD/32, Bb*NKV), blkT>>>(pQKV, pVt, S);

    // 4. scores = QK^T/sqrt(D) (causal tiles only)
    hgemm<1,false><<<dim3(S/128, S/128, Bb*NH), 256, HG_SMEM>>>(
        pQ, pK, nullptr, pSC, nullptr,
        HD, S, (long)S*HD, (long)S*HD, (long)NH*S*S, (long)S*S, inv_sqrt_d);

    // 5. softmax -> P fp16
    softmax_h_kernel<<<(unsigned)(Bb*NH*S), 256>>>(pSC, pP, S);

    // 6. attnout = P @ V -> fp16 [b,s,h*d]
    hgemm<2,false><<<dim3(S/128, 1, Bb*NH), 256, HG_SMEM>>>(
        pP, pVt, nullptr, nullptr, pAO,
        S, HIDD, (long)S*S, (long)HD*S, (long)S*HIDD, HD, 1.f);

    // 7. h1 = x + attnout @ wo
    hgemm<0,true><<<dim3((int)(BS/128), HIDD/128, 1), 256, HG_SMEM>>>(
        pAO, pWOT, x, pH1, nullptr, HIDD, HIDD, 0, 0, 0, 0, 1.f);

    // 8. h2 = rmsnorm(h1)
    rmsnorm_h_kernel<<<(int)BS, 256>>>(pH1, ln2_w, pH);

    // 9+10. act = silu(gate)*up fused into gate_up GEMM -> fp16
    hgemm<3,false><<<dim3((int)(BS/128), 2*FFI/128, 1), 256, HG_SMEM>>>(
        pH, pGUT, nullptr, nullptr, pACT, HIDD, 2*FFI, 0, 0, 0, 0, 1.f);

    // 11. out = h1 + act @ w_down
    hgemm<0,true><<<dim3((int)(BS/128), HIDD/128, 1), 256, HG_SMEM>>>(
        pACT, pDNT, pH1, out, nullptr, FFI, HIDD, 0, 0, 0, 0, 1.f);
}

// round 11
// speedup vs baseline: 7.1957x; 1.0602x over previous
#include <cuda_runtime.h>
#include <cuda_fp16.h>
#include <math.h>
#include <stdint.h>

#define NH   16
#define NKV  4
#define HD   128
#define HIDD 2048
#define FFI  8192
#define QKVW ((NH + 2*NKV) * HD)   /* 3072 */

// ================= scratch (B=4, S=1024) =================
static __device__ float g_qkv[4096L * QKVW];
static __device__ float g_scores[(long)4 * NH * 1024 * 1024];
static __device__ float g_h1[4096L * HIDD];

static __device__ __half g_h[4096L * HIDD];
static __device__ __half g_ao[4096L * HIDD];
static __device__ __half g_act[4096L * FFI];
static __device__ __half g_q[(long)4*NH*1024*HD];
static __device__ __half g_k[(long)4*NKV*1024*HD];
static __device__ __half g_vt[(long)4*NKV*HD*1024];
static __device__ __half g_p[(long)4*NH*1024*1024];
static __device__ __half g_wqkvT[(long)QKVW * HIDD];
static __device__ __half g_woT[(long)HIDD * HIDD];
static __device__ __half g_guT[(long)2*FFI * HIDD];   /* interleaved gate/up rows */
static __device__ __half g_dnT[(long)HIDD * FFI];

// ================= PTX helpers =================
__device__ __forceinline__ uint32_t smem_u32(const void* p) {
    uint32_t a;
    asm("{ .reg .u64 t; cvta.to.shared.u64 t, %1; cvt.u32.u64 %0, t; }" : "=r"(a) : "l"(p));
    return a;
}
__device__ __forceinline__ void cp16(uint32_t dst, const void* src) {
    asm volatile("cp.async.cg.shared.global [%0], [%1], 16;" :: "r"(dst), "l"(src));
}
__device__ __forceinline__ void cp_commit() { asm volatile("cp.async.commit_group;"); }
__device__ __forceinline__ void cp_wait1() { asm volatile("cp.async.wait_group 1;"); }
__device__ __forceinline__ void cp_wait0() { asm volatile("cp.async.wait_group 0;"); }

__device__ __forceinline__ void ldm_x4(uint32_t* r, uint32_t addr) {
    asm volatile("ldmatrix.sync.aligned.m8n8.x4.shared.b16 {%0,%1,%2,%3}, [%4];"
        : "=r"(r[0]), "=r"(r[1]), "=r"(r[2]), "=r"(r[3]) : "r"(addr));
}
__device__ __forceinline__ void mma16816h(float* d, const uint32_t* a, const uint32_t* b) {
    asm volatile("mma.sync.aligned.m16n8k16.row.col.f32.f16.f16.f32 "
        "{%0,%1,%2,%3}, {%4,%5,%6,%7}, {%8,%9}, {%0,%1,%2,%3};"
        : "+f"(d[0]), "+f"(d[1]), "+f"(d[2]), "+f"(d[3])
        : "r"(a[0]), "r"(a[1]), "r"(a[2]), "r"(a[3]), "r"(b[0]), "r"(b[1]));
}
__device__ __forceinline__ float silu_mul(float g, float u) {
    return (g / (1.f + __expf(-g))) * u;
}

// ================= fp16 TN GEMM =================
// MODE 0: weights (fp32 out, optional residual, block swizzle)
// MODE 1: QK^T    (fp32 out, causal tile skip, per-head batch via z)
// MODE 2: PV      (fp16 out, K truncated by causality, per-head batch)
// MODE 3: gate_up (interleaved B rows; epilogue silu(gate)*up -> fp16, block swizzle)
#define SAS 72
#define TILEB (128 * SAS * 2)     /* 18432 */
#define STAGE (2 * TILEB)         /* 36864 */
#define HG_SMEM (2 * STAGE)       /* 73728 */

template<int MODE, bool RES>
__global__ void __launch_bounds__(256, 2)
hgemm(const __half* __restrict__ A, const __half* __restrict__ B,
      const float* __restrict__ R, float* __restrict__ Cf, __half* __restrict__ Ch,
      int K, int ldc, long sA, long sB, long sCb, long sCh, float alpha)
{
    extern __shared__ char sm[];
    const uint32_t sbase = smem_u32(sm);
    const int tid = threadIdx.x;

    int m0, n0;
    if (MODE == 0 || MODE == 3) {
        int lin = blockIdx.y * gridDim.x + blockIdx.x;
        int grpSize = gridDim.x * 8;
        int grp = lin / grpSize, rem = lin % grpSize;
        m0 = (rem >> 3) * 128;
        n0 = (grp * 8 + (rem & 7)) * 128;
    } else {
        m0 = blockIdx.x * 128;
        n0 = blockIdx.y * 128;
    }
    if (MODE == 1 && n0 > m0) return;

    const int z = blockIdx.z;
    const long offA = (long)z * sA;
    const long offB = (long)(z >> 2) * sB;
    const long offC = (long)(z >> 4) * sCb + (long)(z & 15) * sCh;

    int NB = K >> 6;
    if (MODE == 2) { int nbe = (m0 >> 6) + 2; if (nbe < NB) NB = nbe; }

    const int wid = tid >> 5, lane = tid & 31;
    const int wm = (wid >> 2) * 64;
    const int wn = (wid & 3) * 32;

    const __half* srcs[2] = { A + offA + (long)m0 * K, B + offB + (long)n0 * K };

    const int alr = lane & 15, alc = (lane >> 4) * 8;
    const int blr = lane & 7;
    const int bhalf = (lane >> 3) & 1;
    const int bquad = (lane >> 4) * 8;

    float acc[4][4][4];
    #pragma unroll
    for (int i = 0; i < 4; i++)
        #pragma unroll
        for (int j = 0; j < 4; j++)
            #pragma unroll
            for (int q = 0; q < 4; q++) acc[i][j][q] = 0.f;

    auto load_stage = [&](int s, int blk) {
        const long kb = (long)blk << 6;
        #pragma unroll
        for (int t = 0; t < 2; t++) {
            const __half* S = srcs[t] + kb;
            const uint32_t dbase = sbase + s * STAGE + t * TILEB;
            #pragma unroll
            for (int i = 0; i < 4; i++) {
                int idx = tid + 256 * i;
                int r = idx >> 3, c = idx & 7;
                cp16(dbase + (r * SAS + c * 8) * 2, S + (long)r * K + c * 8);
            }
        }
        cp_commit();
    };

    load_stage(0, 0);

    for (int blk = 0; blk < NB; blk++) {
        const int s = blk & 1;
        if (blk + 1 < NB) { load_stage(s ^ 1, blk + 1); cp_wait1(); }
        else              { cp_wait0(); }
        __syncthreads();

        const uint32_t sA_ = sbase + s * STAGE;
        const uint32_t sB_ = sA_ + TILEB;

        #pragma unroll
        for (int kt = 0; kt < 4; kt++) {
            uint32_t aa[4][4], bb[4][2];
            #pragma unroll
            for (int ma = 0; ma < 4; ma++) {
                uint32_t ao = ((wm + ma * 16 + alr) * SAS + kt * 16 + alc) * 2;
                ldm_x4(aa[ma], sA_ + ao);
            }
            #pragma unroll
            for (int np = 0; np < 2; np++) {
                uint32_t bo = ((wn + np * 16 + bquad + blr) * SAS + kt * 16 + bhalf * 8) * 2;
                uint32_t t4[4];
                ldm_x4(t4, sB_ + bo);
                bb[np*2+0][0] = t4[0]; bb[np*2+0][1] = t4[1];
                bb[np*2+1][0] = t4[2]; bb[np*2+1][1] = t4[3];
            }
            #pragma unroll
            for (int ma = 0; ma < 4; ma++)
                #pragma unroll
                for (int na = 0; na < 4; na++)
                    mma16816h(acc[ma][na], aa[ma], bb[na]);
        }
        __syncthreads();
    }

    const int erow = lane >> 2, ecol = (lane & 3) * 2;
    #pragma unroll
    for (int ma = 0; ma < 4; ma++) {
        #pragma unroll
        for (int na = 0; na < 4; na++) {
            long r0 = m0 + wm + ma * 16 + erow;
            long cc = n0 + wn + na * 8 + ecol;
            float v00 = acc[ma][na][0] * alpha, v01 = acc[ma][na][1] * alpha;
            float v10 = acc[ma][na][2] * alpha, v11 = acc[ma][na][3] * alpha;
            if (MODE == 2) {
                long o0 = offC + r0 * ldc + cc;
                long o1 = offC + (r0 + 8) * ldc + cc;
                __half2 h0 = { __float2half_rn(v00), __float2half_rn(v01) };
                __half2 h1 = { __float2half_rn(v10), __float2half_rn(v11) };
                *(__half2*)&Ch[o0] = h0;
                *(__half2*)&Ch[o1] = h1;
            } else if (MODE == 3) {
                long j = cc >> 1;
                Ch[r0 * (long)FFI + j]       = __float2half_rn(silu_mul(v00, v01));
                Ch[(r0 + 8) * (long)FFI + j] = __float2half_rn(silu_mul(v10, v11));
            } else {
                if (RES) {
                    const float2 q0 = *(const float2*)&R[offC + r0 * ldc + cc];
                    const float2 q1 = *(const float2*)&R[offC + (r0 + 8) * ldc + cc];
                    v00 += q0.x; v01 += q0.y; v10 += q1.x; v11 += q1.y;
                }
                float2 w0 = {v00, v01}, w1 = {v10, v11};
                *(float2*)&Cf[offC + r0 * ldc + cc] = w0;
                *(float2*)&Cf[offC + (r0 + 8) * ldc + cc] = w1;
            }
        }
    }
}

// ================= block reductions =================
__device__ __forceinline__ float block_sum(float v) {
    #pragma unroll
    for (int o = 16; o > 0; o >>= 1) v += __shfl_xor_sync(0xffffffffu, v, o);
    __shared__ float sh[8]; __shared__ float total;
    int w = threadIdx.x >> 5, l = threadIdx.x & 31;
    if (l == 0) sh[w] = v;
    __syncthreads();
    if (threadIdx.x == 0) { float s = 0.f; for (int i = 0; i < 8; i++) s += sh[i]; total = s; }
    __syncthreads();
    return total;
}
__device__ __forceinline__ float block_max(float v) {
    #pragma unroll
    for (int o = 16; o > 0; o >>= 1) v = fmaxf(v, __shfl_xor_sync(0xffffffffu, v, o));
    __shared__ float shm[8]; __shared__ float totalm;
    int w = threadIdx.x >> 5, l = threadIdx.x & 31;
    if (l == 0) shm[w] = v;
    __syncthreads();
    if (threadIdx.x == 0) { float s = -3.4e38f; for (int i = 0; i < 8; i++) s = fmaxf(s, shm[i]); totalm = s; }
    __syncthreads();
    return totalm;
}

// ================= elementwise =================
__global__ void rmsnorm_h_kernel(const float* __restrict__ x, const float* __restrict__ w,
                                 __half* __restrict__ out) {
    long row = blockIdx.x;
    const float4* xr4 = (const float4*)(x + row * HIDD);
    const float4* w4  = (const float4*)w;
    float s = 0.f;
    #pragma unroll 2
    for (int i = threadIdx.x; i < HIDD / 4; i += 256) {
        float4 v = xr4[i];
        s += v.x * v.x + v.y * v.y + v.z * v.z + v.w * v.w;
    }
    s = block_sum(s);
    float inv = rsqrtf(s / (float)HIDD + 1e-6f);
    __half2* o2 = (__half2*)(out + row * HIDD);
    #pragma unroll 2
    for (int i = threadIdx.x; i < HIDD / 4; i += 256) {
        float4 v = xr4[i];
        float4 ww = w4[i];
        o2[2*i]   = __floats2half2_rn(v.x * inv * ww.x, v.y * inv * ww.y);
        o2[2*i+1] = __floats2half2_rn(v.z * inv * ww.z, v.w * inv * ww.w);
    }
}

// transpose-convert: W [K,N] fp32 -> T [N*rowMul + rowAdd, K] fp16 (64x64 tiles, half2 stores)
__global__ void convT_h_kernel(const float* __restrict__ W, __half* __restrict__ T,
                               int K, int N, int rowMul, int rowAdd) {
    __shared__ float sm[64][65];
    int n0 = blockIdx.x * 64, k0 = blockIdx.y * 64;
    int tid = threadIdx.x;
    int rcol = tid & 63, rrow = tid >> 6;      // 4 rows per pass
    #pragma unroll
    for (int p = 0; p < 16; p++) {
        int row = p * 4 + rrow;
        sm[row][rcol] = W[(long)(k0 + row) * N + n0 + rcol];
    }
    __syncthreads();
    int j = tid & 31, r8 = tid >> 5;           // 8 rows per pass
    #pragma unroll
    for (int p = 0; p < 8; p++) {
        int row = p * 8 + r8;
        __half2 h = __floats2half2_rn(sm[2*j][row], sm[2*j+1][row]);
        *(__half2*)&T[(long)((n0 + row) * rowMul + rowAdd) * K + k0 + 2*j] = h;
    }
}

// rope + split q,k
__global__ void conv_qk_kernel(const float* __restrict__ qkv, const int* __restrict__ pos,
                               __half* __restrict__ q, __half* __restrict__ k, int S) {
    long idx = (long)blockIdx.x * 256 + threadIdx.x;
    int d = (int)(idx & 63);
    long t = idx >> 6;
    int head = (int)(t % (NH + NKV)); t /= (NH + NKV);
    int s = (int)(t % S);
    int b = (int)(t / S);
    const float* base = qkv + ((long)(b * S + s)) * QKVW + head * HD;
    float t1 = base[d], t2 = base[d + 64];
    float invf = __powf(10000.f, -(float)d * (1.f/64.f));
    float ang = (float)pos[s] * invf;
    float sn, cs;
    __sincosf(ang, &sn, &cs);
    float r1 = t1 * cs - t2 * sn;
    float r2 = t2 * cs + t1 * sn;
    if (head < NH) {
        long o = ((long)(b * NH + head) * S + s) * HD;
        q[o + d] = __float2half_rn(r1);
        q[o + d + 64] = __float2half_rn(r2);
    } else {
        long o = ((long)(b * NKV + head - NH) * S + s) * HD;
        k[o + d] = __float2half_rn(r1);
        k[o + d + 64] = __float2half_rn(r2);
    }
}

// v transpose: qkv v slice -> vt [b,hk,d,s] fp16
__global__ void conv_vt_kernel(const float* __restrict__ qkv, __half* __restrict__ vt, int S) {
    __shared__ float t[32][33];
    int s0 = blockIdx.x * 32, d0 = blockIdx.y * 32;
    int z = blockIdx.z;
    int b = z >> 2, h = z & 3;
    for (int i = threadIdx.y; i < 32; i += 8)
        t[i][threadIdx.x] = qkv[((long)(b * S + s0 + i)) * QKVW + (NH + NKV + h) * HD + d0 + threadIdx.x];
    __syncthreads();
    for (int i = threadIdx.y; i < 32; i += 8)
        vt[((long)z * HD + d0 + i) * S + s0 + threadIdx.x] = __float2half_rn(t[threadIdx.x][i]);
}

// causal softmax: fp32 scores -> P fp16; single exp; zero-fill only to end of own 128-tile
__global__ void softmax_h_kernel(const float* __restrict__ sc, __half* __restrict__ p, int S) {
    long row = blockIdx.x;
    int r = (int)(row & (S - 1));
    int len = r + 1;
    const float* pr = sc + row * (long)S;
    long o = row * (long)S;
    float mx = -3.4e38f;
    for (int i = threadIdx.x; i < len; i += 256) mx = fmaxf(mx, pr[i]);
    mx = block_max(mx);
    float sum = 0.f;
    for (int i = threadIdx.x; i < len; i += 256) {
        float e = __expf(pr[i] - mx);
        p[o + i] = __float2half_rn(e);
        sum += e;
    }
    sum = block_sum(sum);
    __half2 rinv2 = __float2half2_rn(1.f / sum);
    int len2 = len >> 1;
    __half2* p2 = (__half2*)(p + o);
    for (int i = threadIdx.x; i < len2; i += 256) p2[i] = __hmul2(p2[i], rinv2);
    if ((len & 1) && threadIdx.x == 0) p[o + len - 1] = __hmul(p[o + len - 1], __low2half(rinv2));
    // PV for this row's m-tile only reads k < tile_end; zero-fill just that span
    int lim = ((r >> 7) + 1) << 7;
    __half z = __float2half_rn(0.f);
    for (int i = len + threadIdx.x; i < lim; i += 256) p[o + i] = z;
}

// ================= host launcher =================
extern "C" void kernel_launch(void* const* d_in, const int* in_sizes, int n_in,
                              void* d_out, int out_size) {
    const float* x         = (const float*)d_in[0];
    const float* ln1_w     = (const float*)d_in[1];
    const float* wqkv      = (const float*)d_in[2];
    const float* wo        = (const float*)d_in[3];
    const float* ln2_w     = (const float*)d_in[4];
    const float* w_gate_up = (const float*)d_in[5];
    const float* w_down    = (const float*)d_in[6];
    const int*   pos       = (const int*)d_in[7];
    float* out = (float*)d_out;

    const int S  = in_sizes[7];                 // 1024
    const long BS = (long)in_sizes[0] / HIDD;   // 4096
    const int Bb = (int)(BS / S);               // 4

    float *pQKV, *pSC, *pH1;
    cudaGetSymbolAddress((void**)&pQKV, g_qkv);
    cudaGetSymbolAddress((void**)&pSC,  g_scores);
    cudaGetSymbolAddress((void**)&pH1,  g_h1);
    __half *pH,*pAO,*pACT,*pQ,*pK,*pVt,*pP;
    __half *pQKVT,*pWOT,*pGUT,*pDNT;
    cudaGetSymbolAddress((void**)&pH, g_h);
    cudaGetSymbolAddress((void**)&pAO, g_ao);
    cudaGetSymbolAddress((void**)&pACT, g_act);
    cudaGetSymbolAddress((void**)&pQ, g_q);
    cudaGetSymbolAddress((void**)&pK, g_k);
    cudaGetSymbolAddress((void**)&pVt, g_vt);
    cudaGetSymbolAddress((void**)&pP, g_p);
    cudaGetSymbolAddress((void**)&pQKVT, g_wqkvT);
    cudaGetSymbolAddress((void**)&pWOT, g_woT);
    cudaGetSymbolAddress((void**)&pGUT, g_guT);
    cudaGetSymbolAddress((void**)&pDNT, g_dnT);

    cudaFuncSetAttribute(hgemm<0,false>, cudaFuncAttributeMaxDynamicSharedMemorySize, HG_SMEM);
    cudaFuncSetAttribute(hgemm<0,true>,  cudaFuncAttributeMaxDynamicSharedMemorySize, HG_SMEM);
    cudaFuncSetAttribute(hgemm<1,false>, cudaFuncAttributeMaxDynamicSharedMemorySize, HG_SMEM);
    cudaFuncSetAttribute(hgemm<2,false>, cudaFuncAttributeMaxDynamicSharedMemorySize, HG_SMEM);
    cudaFuncSetAttribute(hgemm<3,false>, cudaFuncAttributeMaxDynamicSharedMemorySize, HG_SMEM);

    dim3 blkT(32, 8);
    const float inv_sqrt_d = 0.08838834764831843f;

    // weight transpose+convert (fp16, [N,K]); gate/up interleaved rows
    convT_h_kernel<<<dim3(QKVW/64,  HIDD/64), 256>>>(wqkv,      pQKVT, HIDD, QKVW, 1, 0);
    convT_h_kernel<<<dim3(HIDD/64,  HIDD/64), 256>>>(wo,        pWOT,  HIDD, HIDD, 1, 0);
    convT_h_kernel<<<dim3(FFI/64,   HIDD/64), 256>>>(w_gate_up,       pGUT, HIDD, 2*FFI, 2, 0);
    convT_h_kernel<<<dim3(FFI/64,   HIDD/64), 256>>>(w_gate_up + FFI, pGUT, HIDD, 2*FFI, 2, 1);
    convT_h_kernel<<<dim3(HIDD/64,  FFI/64),  256>>>(w_down,    pDNT,  FFI,  HIDD, 1, 0);

    // 1. h = rmsnorm(x) -> fp16
    rmsnorm_h_kernel<<<(int)BS, 256>>>(x, ln1_w, pH);

    // 2. qkv = h @ wqkv
    hgemm<0,false><<<dim3((int)(BS/128), QKVW/128, 1), 256, HG_SMEM>>>(
        pH, pQKVT, nullptr, pQKV, nullptr, HIDD, QKVW, 0, 0, 0, 0, 1.f);

    // 3. rope + split q,k ; transpose v
    conv_qk_kernel<<<(unsigned)((BS * (NH+NKV) * 64) / 256), 256>>>(pQKV, pos, pQ, pK, S);
    conv_vt_kernel<<<dim3(S/32, HD/32, Bb*NKV), blkT>>>(pQKV, pVt, S);

    // 4. scores = QK^T/sqrt(D) (causal tiles only)
    hgemm<1,false><<<dim3(S/128, S/128, Bb*NH), 256, HG_SMEM>>>(
        pQ, pK, nullptr, pSC, nullptr,
        HD, S, (long)S*HD, (long)S*HD, (long)NH*S*S, (long)S*S, inv_sqrt_d);

    // 5. softmax -> P fp16
    softmax_h_kernel<<<(unsigned)(Bb*NH*S), 256>>>(pSC, pP, S);

    // 6. attnout = P @ V -> fp16 [b,s,h*d]
    hgemm<2,false><<<dim3(S/128, 1, Bb*NH), 256, HG_SMEM>>>(
        pP, pVt, nullptr, nullptr, pAO,
        S, HIDD, (long)S*S, (long)HD*S, (long)S*HIDD, HD, 1.f);

    // 7. h1 = x + attnout @ wo
    hgemm<0,true><<<dim3((int)(BS/128), HIDD/128, 1), 256, HG_SMEM>>>(
        pAO, pWOT, x, pH1, nullptr, HIDD, HIDD, 0, 0, 0, 0, 1.f);

    // 8. h2 = rmsnorm(h1)
    rmsnorm_h_kernel<<<(int)BS, 256>>>(pH1, ln2_w, pH);

    // 9+10. act = silu(gate)*up fused into gate_up GEMM -> fp16
    hgemm<3,false><<<dim3((int)(BS/128), 2*FFI/128, 1), 256, HG_SMEM>>>(
        pH, pGUT, nullptr, nullptr, pACT, HIDD, 2*FFI, 0, 0, 0, 0, 1.f);

    // 11. out = h1 + act @ w_down
    hgemm<0,true><<<dim3((int)(BS/128), HIDD/128, 1), 256, HG_SMEM>>>(
        pACT, pDNT, pH1, out, nullptr, FFI, HIDD, 0, 0, 0, 0, 1.f);
}

// round 12
// speedup vs baseline: 7.2559x; 1.0084x over previous
#include <cuda_runtime.h>
#include <cuda_fp16.h>
#include <math.h>
#include <stdint.h>

#define NH   16
#define NKV  4
#define HD   128
#define HIDD 2048
#define FFI  8192
#define QKVW ((NH + 2*NKV) * HD)   /* 3072 */

// ================= scratch (B=4, S=1024) =================
static __device__ float g_scores[(long)4 * NH * 1024 * 1024];
static __device__ float g_h1[4096L * HIDD];

static __device__ __half g_h[4096L * HIDD];
static __device__ __half g_ao[4096L * HIDD];
static __device__ __half g_act[4096L * FFI];
static __device__ __half g_q[(long)4*NH*1024*HD];
static __device__ __half g_k[(long)4*NKV*1024*HD];
static __device__ __half g_vt[(long)4*NKV*HD*1024];
static __device__ __half g_p[(long)4*NH*1024*1024];
static __device__ __half g_wqkvT[(long)QKVW * HIDD];
static __device__ __half g_woT[(long)HIDD * HIDD];
static __device__ __half g_guT[(long)2*FFI * HIDD];   /* interleaved gate/up rows */
static __device__ __half g_dnT[(long)HIDD * FFI];

// ================= PTX helpers =================
__device__ __forceinline__ uint32_t smem_u32(const void* p) {
    uint32_t a;
    asm("{ .reg .u64 t; cvta.to.shared.u64 t, %1; cvt.u32.u64 %0, t; }" : "=r"(a) : "l"(p));
    return a;
}
__device__ __forceinline__ void cp16(uint32_t dst, const void* src) {
    asm volatile("cp.async.cg.shared.global [%0], [%1], 16;" :: "r"(dst), "l"(src));
}
__device__ __forceinline__ void cp_commit() { asm volatile("cp.async.commit_group;"); }
__device__ __forceinline__ void cp_wait1() { asm volatile("cp.async.wait_group 1;"); }
__device__ __forceinline__ void cp_wait0() { asm volatile("cp.async.wait_group 0;"); }

__device__ __forceinline__ void ldm_x4(uint32_t* r, uint32_t addr) {
    asm volatile("ldmatrix.sync.aligned.m8n8.x4.shared.b16 {%0,%1,%2,%3}, [%4];"
        : "=r"(r[0]), "=r"(r[1]), "=r"(r[2]), "=r"(r[3]) : "r"(addr));
}
__device__ __forceinline__ void mma16816h(float* d, const uint32_t* a, const uint32_t* b) {
    asm volatile("mma.sync.aligned.m16n8k16.row.col.f32.f16.f16.f32 "
        "{%0,%1,%2,%3}, {%4,%5,%6,%7}, {%8,%9}, {%0,%1,%2,%3};"
        : "+f"(d[0]), "+f"(d[1]), "+f"(d[2]), "+f"(d[3])
        : "r"(a[0]), "r"(a[1]), "r"(a[2]), "r"(a[3]), "r"(b[0]), "r"(b[1]));
}
__device__ __forceinline__ float silu_mul(float g, float u) {
    return (g / (1.f + __expf(-g))) * u;
}

// ================= fp16 TN GEMM =================
// MODE 0: weights (fp32 out, optional residual, block swizzle)
// MODE 1: QK^T    (fp32 out, causal tile skip, per-head batch via z)
// MODE 2: PV      (fp16 out, K truncated by causality, per-head batch)
// MODE 3: gate_up (interleaved B rows; epilogue silu(gate)*up -> fp16, block swizzle)
// MODE 4: qkv     (epilogue stages tile to smem; RoPE+split q/k, transpose v)
#define SAS 72
#define TILEB (128 * SAS * 2)     /* 18432 */
#define STAGE (2 * TILEB)         /* 36864 */
#define HG_SMEM (2 * STAGE)       /* 73728 */
#define EPS_ST 133                /* fp32 staging stride: 128*133*4 = 68096 <= 73728 */

template<int MODE, bool RES>
__global__ void __launch_bounds__(256, 2)
hgemm(const __half* __restrict__ A, const __half* __restrict__ B,
      const float* __restrict__ R, float* __restrict__ Cf, __half* __restrict__ Ch,
      __half* __restrict__ Ck, __half* __restrict__ Cvt, const int* __restrict__ pos,
      int K, int ldc, long sA, long sB, long sCb, long sCh, float alpha, int S)
{
    extern __shared__ char sm[];
    const uint32_t sbase = smem_u32(sm);
    const int tid = threadIdx.x;

    int m0, n0;
    if (MODE == 0 || MODE == 3) {
        int lin = blockIdx.y * gridDim.x + blockIdx.x;
        int grpSize = gridDim.x * 8;
        int grp = lin / grpSize, rem = lin % grpSize;
        m0 = (rem >> 3) * 128;
        n0 = (grp * 8 + (rem & 7)) * 128;
    } else {
        m0 = blockIdx.x * 128;
        n0 = blockIdx.y * 128;
    }
    if (MODE == 1 && n0 > m0) return;

    const int z = blockIdx.z;
    const long offA = (long)z * sA;
    const long offB = (long)(z >> 2) * sB;
    const long offC = (long)(z >> 4) * sCb + (long)(z & 15) * sCh;

    int NB = K >> 6;
    if (MODE == 2) { int nbe = (m0 >> 6) + 2; if (nbe < NB) NB = nbe; }

    const int wid = tid >> 5, lane = tid & 31;
    const int wm = (wid >> 2) * 64;
    const int wn = (wid & 3) * 32;

    const __half* srcs[2] = { A + offA + (long)m0 * K, B + offB + (long)n0 * K };

    const int alr = lane & 15, alc = (lane >> 4) * 8;
    const int blr = lane & 7;
    const int bhalf = (lane >> 3) & 1;
    const int bquad = (lane >> 4) * 8;

    float acc[4][4][4];
    #pragma unroll
    for (int i = 0; i < 4; i++)
        #pragma unroll
        for (int j = 0; j < 4; j++)
            #pragma unroll
            for (int q = 0; q < 4; q++) acc[i][j][q] = 0.f;

    auto load_stage = [&](int s, int blk) {
        const long kb = (long)blk << 6;
        #pragma unroll
        for (int t = 0; t < 2; t++) {
            const __half* S_ = srcs[t] + kb;
            const uint32_t dbase = sbase + s * STAGE + t * TILEB;
            #pragma unroll
            for (int i = 0; i < 4; i++) {
                int idx = tid + 256 * i;
                int r = idx >> 3, c = idx & 7;
                cp16(dbase + (r * SAS + c * 8) * 2, S_ + (long)r * K + c * 8);
            }
        }
        cp_commit();
    };

    load_stage(0, 0);

    for (int blk = 0; blk < NB; blk++) {
        const int s = blk & 1;
        if (blk + 1 < NB) { load_stage(s ^ 1, blk + 1); cp_wait1(); }
        else              { cp_wait0(); }
        __syncthreads();

        const uint32_t sA_ = sbase + s * STAGE;
        const uint32_t sB_ = sA_ + TILEB;

        #pragma unroll
        for (int kt = 0; kt < 4; kt++) {
            uint32_t aa[4][4], bb[4][2];
            #pragma unroll
            for (int ma = 0; ma < 4; ma++) {
                uint32_t ao = ((wm + ma * 16 + alr) * SAS + kt * 16 + alc) * 2;
                ldm_x4(aa[ma], sA_ + ao);
            }
            #pragma unroll
            for (int np = 0; np < 2; np++) {
                uint32_t bo = ((wn + np * 16 + bquad + blr) * SAS + kt * 16 + bhalf * 8) * 2;
                uint32_t t4[4];
                ldm_x4(t4, sB_ + bo);
                bb[np*2+0][0] = t4[0]; bb[np*2+0][1] = t4[1];
                bb[np*2+1][0] = t4[2]; bb[np*2+1][1] = t4[3];
            }
            #pragma unroll
            for (int ma = 0; ma < 4; ma++)
                #pragma unroll
                for (int na = 0; na < 4; na++)
                    mma16816h(acc[ma][na], aa[ma], bb[na]);
        }
        __syncthreads();
    }

    const int erow = lane >> 2, ecol = (lane & 3) * 2;

    if (MODE == 4) {
        // stage accumulators to smem fp32 (stride 133, conflict-free both ways)
        float* st = (float*)sm;
        #pragma unroll
        for (int ma = 0; ma < 4; ma++) {
            #pragma unroll
            for (int na = 0; na < 4; na++) {
                int rr = wm + ma * 16 + erow;
                int cc = wn + na * 8 + ecol;
                st[rr * EPS_ST + cc]           = acc[ma][na][0];
                st[rr * EPS_ST + cc + 1]       = acc[ma][na][1];
                st[(rr + 8) * EPS_ST + cc]     = acc[ma][na][2];
                st[(rr + 8) * EPS_ST + cc + 1] = acc[ma][na][3];
            }
        }
        __syncthreads();
        const int nt = n0 >> 7;          // head tile: 0..15 q, 16..19 k, 20..23 v
        if (nt < NH + NKV) {
            // RoPE + split to q or k, layout [b, h, s, HD]
            for (int i = tid; i < 128 * 64; i += 256) {
                int rr = i >> 6;         // local row 0..127
                int d  = i & 63;
                float t1 = st[rr * EPS_ST + d];
                float t2 = st[rr * EPS_ST + d + 64];
                int grow = m0 + rr;
                int b = grow / S, s = grow - b * S;
                float invf = __powf(10000.f, -(float)d * (1.f/64.f));
                float ang = (float)pos[s] * invf;
                float sn, cs;
                __sincosf(ang, &sn, &cs);
                float r1 = t1 * cs - t2 * sn;
                float r2 = t2 * cs + t1 * sn;
                if (nt < NH) {
                    long o = ((long)(b * NH + nt) * S + s) * HD;
                    Ch[o + d]      = __float2half_rn(r1);
                    Ch[o + d + 64] = __float2half_rn(r2);
                } else {
                    long o = ((long)(b * NKV + nt - NH) * S + s) * HD;
                    Ck[o + d]      = __float2half_rn(r1);
                    Ck[o + d + 64] = __float2half_rn(r2);
                }
            }
        } else {
            // V transpose: vt[b, h, d, s]
            const int h = nt - NH - NKV;
            for (int i = tid; i < 128 * 128; i += 256) {
                int d  = i >> 7;         // 0..127
                int sc = i & 127;        // local row (token)
                float v = st[sc * EPS_ST + d];
                int grow = m0 + sc;
                int b = grow / S, s = grow - b * S;
                Cvt[((long)(b * NKV + h) * HD + d) * S + s] = __float2half_rn(v);
            }
        }
        return;
    }

    #pragma unroll
    for (int ma = 0; ma < 4; ma++) {
        #pragma unroll
        for (int na = 0; na < 4; na++) {
            long r0 = m0 + wm + ma * 16 + erow;
            long cc = n0 + wn + na * 8 + ecol;
            float v00 = acc[ma][na][0] * alpha, v01 = acc[ma][na][1] * alpha;
            float v10 = acc[ma][na][2] * alpha, v11 = acc[ma][na][3] * alpha;
            if (MODE == 2) {
                long o0 = offC + r0 * ldc + cc;
                long o1 = offC + (r0 + 8) * ldc + cc;
                __half2 h0 = { __float2half_rn(v00), __float2half_rn(v01) };
                __half2 h1 = { __float2half_rn(v10), __float2half_rn(v11) };
                *(__half2*)&Ch[o0] = h0;
                *(__half2*)&Ch[o1] = h1;
            } else if (MODE == 3) {
                long j = cc >> 1;
                Ch[r0 * (long)FFI + j]       = __float2half_rn(silu_mul(v00, v01));
                Ch[(r0 + 8) * (long)FFI + j] = __float2half_rn(silu_mul(v10, v11));
            } else {
                if (RES) {
                    const float2 q0 = *(const float2*)&R[offC + r0 * ldc + cc];
                    const float2 q1 = *(const float2*)&R[offC + (r0 + 8) * ldc + cc];
                    v00 += q0.x; v01 += q0.y; v10 += q1.x; v11 += q1.y;
                }
                float2 w0 = {v00, v01}, w1 = {v10, v11};
                *(float2*)&Cf[offC + r0 * ldc + cc] = w0;
                *(float2*)&Cf[offC + (r0 + 8) * ldc + cc] = w1;
            }
        }
    }
}

// ================= block reductions =================
__device__ __forceinline__ float block_sum(float v) {
    #pragma unroll
    for (int o = 16; o > 0; o >>= 1) v += __shfl_xor_sync(0xffffffffu, v, o);
    __shared__ float sh[8]; __shared__ float total;
    int w = threadIdx.x >> 5, l = threadIdx.x & 31;
    if (l == 0) sh[w] = v;
    __syncthreads();
    if (threadIdx.x == 0) { float s = 0.f; for (int i = 0; i < 8; i++) s += sh[i]; total = s; }
    __syncthreads();
    return total;
}
__device__ __forceinline__ float block_max(float v) {
    #pragma unroll
    for (int o = 16; o > 0; o >>= 1) v = fmaxf(v, __shfl_xor_sync(0xffffffffu, v, o));
    __shared__ float shm[8]; __shared__ float totalm;
    int w = threadIdx.x >> 5, l = threadIdx.x & 31;
    if (l == 0) shm[w] = v;
    __syncthreads();
    if (threadIdx.x == 0) { float s = -3.4e38f; for (int i = 0; i < 8; i++) s = fmaxf(s, shm[i]); totalm = s; }
    __syncthreads();
    return totalm;
}

// ================= elementwise =================
__global__ void rmsnorm_h_kernel(const float* __restrict__ x, const float* __restrict__ w,
                                 __half* __restrict__ out) {
    long row = blockIdx.x;
    const float4* xr4 = (const float4*)(x + row * HIDD);
    const float4* w4  = (const float4*)w;
    float s = 0.f;
    #pragma unroll 2
    for (int i = threadIdx.x; i < HIDD / 4; i += 256) {
        float4 v = xr4[i];
        s += v.x * v.x + v.y * v.y + v.z * v.z + v.w * v.w;
    }
    s = block_sum(s);
    float inv = rsqrtf(s / (float)HIDD + 1e-6f);
    __half2* o2 = (__half2*)(out + row * HIDD);
    #pragma unroll 2
    for (int i = threadIdx.x; i < HIDD / 4; i += 256) {
        float4 v = xr4[i];
        float4 ww = w4[i];
        o2[2*i]   = __floats2half2_rn(v.x * inv * ww.x, v.y * inv * ww.y);
        o2[2*i+1] = __floats2half2_rn(v.z * inv * ww.z, v.w * inv * ww.w);
    }
}

// transpose-convert: W [K,N] fp32 -> T [N*rowMul + rowAdd, K] fp16 (64x64 tiles, half2 stores)
__global__ void convT_h_kernel(const float* __restrict__ W, __half* __restrict__ T,
                               int K, int N, int rowMul, int rowAdd) {
    __shared__ float smT[64][65];
    int n0 = blockIdx.x * 64, k0 = blockIdx.y * 64;
    int tid = threadIdx.x;
    int rcol = tid & 63, rrow = tid >> 6;
    #pragma unroll
    for (int p = 0; p < 16; p++) {
        int row = p * 4 + rrow;
        smT[row][rcol] = W[(long)(k0 + row) * N + n0 + rcol];
    }
    __syncthreads();
    int j = tid & 31, r8 = tid >> 5;
    #pragma unroll
    for (int p = 0; p < 8; p++) {
        int row = p * 8 + r8;
        __half2 h = __floats2half2_rn(smT[2*j][row], smT[2*j+1][row]);
        *(__half2*)&T[(long)((n0 + row) * rowMul + rowAdd) * K + k0 + 2*j] = h;
    }
}

// causal softmax: fp32 scores -> P fp16; values cached in registers between passes
__global__ void softmax_h_kernel(const float* __restrict__ sc, __half* __restrict__ p, int S) {
    long row = blockIdx.x;
    int r = (int)(row & (S - 1));
    int len = r + 1;
    const float* pr = sc + row * (long)S;
    long o = row * (long)S;
    float vals[4];
    int cnt = 0;
    float mx = -3.4e38f;
    for (int i = threadIdx.x; i < len; i += 256) {
        float v = pr[i];
        vals[cnt++] = v;
        mx = fmaxf(mx, v);
    }
    mx = block_max(mx);
    float sum = 0.f;
    cnt = 0;
    for (int i = threadIdx.x; i < len; i += 256) {
        float e = __expf(vals[cnt++] - mx);
        p[o + i] = __float2half_rn(e);
        sum += e;
    }
    sum = block_sum(sum);
    __half2 rinv2 = __float2half2_rn(1.f / sum);
    int len2 = len >> 1;
    __half2* p2 = (__half2*)(p + o);
    for (int i = threadIdx.x; i < len2; i += 256) p2[i] = __hmul2(p2[i], rinv2);
    if ((len & 1) && threadIdx.x == 0) p[o + len - 1] = __hmul(p[o + len - 1], __low2half(rinv2));
    int lim = ((r >> 7) + 1) << 7;
    __half z = __float2half_rn(0.f);
    for (int i = len + threadIdx.x; i < lim; i += 256) p[o + i] = z;
}

// ================= host launcher =================
extern "C" void kernel_launch(void* const* d_in, const int* in_sizes, int n_in,
                              void* d_out, int out_size) {
    const float* x         = (const float*)d_in[0];
    const float* ln1_w     = (const float*)d_in[1];
    const float* wqkv      = (const float*)d_in[2];
    const float* wo        = (const float*)d_in[3];
    const float* ln2_w     = (const float*)d_in[4];
    const float* w_gate_up = (const float*)d_in[5];
    const float* w_down    = (const float*)d_in[6];
    const int*   pos       = (const int*)d_in[7];
    float* out = (float*)d_out;

    const int S  = in_sizes[7];                 // 1024
    const long BS = (long)in_sizes[0] / HIDD;   // 4096
    const int Bb = (int)(BS / S);               // 4

    float *pSC, *pH1;
    cudaGetSymbolAddress((void**)&pSC,  g_scores);
    cudaGetSymbolAddress((void**)&pH1,  g_h1);
    __half *pH,*pAO,*pACT,*pQ,*pK,*pVt,*pP;
    __half *pQKVT,*pWOT,*pGUT,*pDNT;
    cudaGetSymbolAddress((void**)&pH, g_h);
    cudaGetSymbolAddress((void**)&pAO, g_ao);
    cudaGetSymbolAddress((void**)&pACT, g_act);
    cudaGetSymbolAddress((void**)&pQ, g_q);
    cudaGetSymbolAddress((void**)&pK, g_k);
    cudaGetSymbolAddress((void**)&pVt, g_vt);
    cudaGetSymbolAddress((void**)&pP, g_p);
    cudaGetSymbolAddress((void**)&pQKVT, g_wqkvT);
    cudaGetSymbolAddress((void**)&pWOT, g_woT);
    cudaGetSymbolAddress((void**)&pGUT, g_guT);
    cudaGetSymbolAddress((void**)&pDNT, g_dnT);

    cudaFuncSetAttribute(hgemm<0,false>, cudaFuncAttributeMaxDynamicSharedMemorySize, HG_SMEM);
    cudaFuncSetAttribute(hgemm<0,true>,  cudaFuncAttributeMaxDynamicSharedMemorySize, HG_SMEM);
    cudaFuncSetAttribute(hgemm<1,false>, cudaFuncAttributeMaxDynamicSharedMemorySize, HG_SMEM);
    cudaFuncSetAttribute(hgemm<2,false>, cudaFuncAttributeMaxDynamicSharedMemorySize, HG_SMEM);
    cudaFuncSetAttribute(hgemm<3,false>, cudaFuncAttributeMaxDynamicSharedMemorySize, HG_SMEM);
    cudaFuncSetAttribute(hgemm<4,false>, cudaFuncAttributeMaxDynamicSharedMemorySize, HG_SMEM);

    const float inv_sqrt_d = 0.08838834764831843f;

    // weight transpose+convert (fp16, [N,K]); gate/up interleaved rows
    convT_h_kernel<<<dim3(QKVW/64,  HIDD/64), 256>>>(wqkv,      pQKVT, HIDD, QKVW, 1, 0);
    convT_h_kernel<<<dim3(HIDD/64,  HIDD/64), 256>>>(wo,        pWOT,  HIDD, HIDD, 1, 0);
    convT_h_kernel<<<dim3(FFI/64,   HIDD/64), 256>>>(w_gate_up,       pGUT, HIDD, 2*FFI, 2, 0);
    convT_h_kernel<<<dim3(FFI/64,   HIDD/64), 256>>>(w_gate_up + FFI, pGUT, HIDD, 2*FFI, 2, 1);
    convT_h_kernel<<<dim3(HIDD/64,  FFI/64),  256>>>(w_down,    pDNT,  FFI,  HIDD, 1, 0);

    // 1. h = rmsnorm(x) -> fp16
    rmsnorm_h_kernel<<<(int)BS, 256>>>(x, ln1_w, pH);

    // 2+3. qkv GEMM with fused RoPE/split/v-transpose epilogue
    hgemm<4,false><<<dim3((int)(BS/128), QKVW/128, 1), 256, HG_SMEM>>>(
        pH, pQKVT, nullptr, nullptr, pQ, pK, pVt, pos,
        HIDD, 0, 0, 0, 0, 0, 1.f, S);

    // 4. scores = QK^T/sqrt(D) (causal tiles only)
    hgemm<1,false><<<dim3(S/128, S/128, Bb*NH), 256, HG_SMEM>>>(
        pQ, pK, nullptr, pSC, nullptr, nullptr, nullptr, nullptr,
        HD, S, (long)S*HD, (long)S*HD, (long)NH*S*S, (long)S*S, inv_sqrt_d, S);

    // 5. softmax -> P fp16
    softmax_h_kernel<<<(unsigned)(Bb*NH*S), 256>>>(pSC, pP, S);

    // 6. attnout = P @ V -> fp16 [b,s,h*d]
    hgemm<2,false><<<dim3(S/128, 1, Bb*NH), 256, HG_SMEM>>>(
        pP, pVt, nullptr, nullptr, pAO, nullptr, nullptr, nullptr,
        S, HIDD, (long)S*S, (long)HD*S, (long)S*HIDD, HD, 1.f, S);

    // 7. h1 = x + attnout @ wo
    hgemm<0,true><<<dim3((int)(BS/128), HIDD/128, 1), 256, HG_SMEM>>>(
        pAO, pWOT, x, pH1, nullptr, nullptr, nullptr, nullptr,
        HIDD, HIDD, 0, 0, 0, 0, 1.f, S);

    // 8. h2 = rmsnorm(h1)
    rmsnorm_h_kernel<<<(int)BS, 256>>>(pH1, ln2_w, pH);

    // 9+10. act = silu(gate)*up fused into gate_up GEMM -> fp16
    hgemm<3,false><<<dim3((int)(BS/128), 2*FFI/128, 1), 256, HG_SMEM>>>(
        pH, pGUT, nullptr, nullptr, pACT, nullptr, nullptr, nullptr,
        HIDD, 2*FFI, 0, 0, 0, 0, 1.f, S);

    // 11. out = h1 + act @ w_down
    hgemm<0,true><<<dim3((int)(BS/128), HIDD/128, 1), 256, HG_SMEM>>>(
        pACT, pDNT, pH1, out, nullptr, nullptr, nullptr, nullptr,
        FFI, HIDD, 0, 0, 0, 0, 1.f, S);
}

// round 13
// speedup vs baseline: 7.9810x; 1.0999x over previous
#include <cuda_runtime.h>
#include <cuda_fp16.h>
#include <math.h>
#include <stdint.h>

#define NH   16
#define NKV  4
#define HD   128
#define HIDD 2048
#define FFI  8192
#define QKVW ((NH + 2*NKV) * HD)   /* 3072 */

// ================= scratch (B=4, S=1024) =================
static __device__ float g_h1[4096L * HIDD];

static __device__ __half g_h[4096L * HIDD];
static __device__ __half g_ao[4096L * HIDD];
static __device__ __half g_act[4096L * FFI];
static __device__ __half g_q[(long)4*NH*1024*HD];
static __device__ __half g_k[(long)4*NKV*1024*HD];
static __device__ __half g_vt[(long)4*NKV*HD*1024];
static __device__ __half g_wqkvT[(long)QKVW * HIDD];
static __device__ __half g_woT[(long)HIDD * HIDD];
static __device__ __half g_guT[(long)2*FFI * HIDD];   /* interleaved gate/up rows */
static __device__ __half g_dnT[(long)HIDD * FFI];

// ================= PTX helpers =================
__device__ __forceinline__ uint32_t smem_u32(const void* p) {
    uint32_t a;
    asm("{ .reg .u64 t; cvta.to.shared.u64 t, %1; cvt.u32.u64 %0, t; }" : "=r"(a) : "l"(p));
    return a;
}
__device__ __forceinline__ void cp16(uint32_t dst, const void* src) {
    asm volatile("cp.async.cg.shared.global [%0], [%1], 16;" :: "r"(dst), "l"(src));
}
__device__ __forceinline__ void cp_commit() { asm volatile("cp.async.commit_group;"); }
__device__ __forceinline__ void cp_wait1() { asm volatile("cp.async.wait_group 1;"); }
__device__ __forceinline__ void cp_wait0() { asm volatile("cp.async.wait_group 0;"); }

__device__ __forceinline__ void ldm_x4(uint32_t* r, uint32_t addr) {
    asm volatile("ldmatrix.sync.aligned.m8n8.x4.shared.b16 {%0,%1,%2,%3}, [%4];"
        : "=r"(r[0]), "=r"(r[1]), "=r"(r[2]), "=r"(r[3]) : "r"(addr));
}
__device__ __forceinline__ void mma16816h(float* d, const uint32_t* a, const uint32_t* b) {
    asm volatile("mma.sync.aligned.m16n8k16.row.col.f32.f16.f16.f32 "
        "{%0,%1,%2,%3}, {%4,%5,%6,%7}, {%8,%9}, {%0,%1,%2,%3};"
        : "+f"(d[0]), "+f"(d[1]), "+f"(d[2]), "+f"(d[3])
        : "r"(a[0]), "r"(a[1]), "r"(a[2]), "r"(a[3]), "r"(b[0]), "r"(b[1]));
}
__device__ __forceinline__ float silu_mul(float g, float u) {
    return (g / (1.f + __expf(-g))) * u;
}
__device__ __forceinline__ uint32_t pack_h2(float a, float b) {
    __half2 h = __floats2half2_rn(a, b);
    return *(uint32_t*)&h;
}

// ================= fp16 TN GEMM =================
// MODE 0: weights (fp32 out, optional residual, block swizzle)
// MODE 3: gate_up (interleaved B rows; epilogue silu(gate)*up -> fp16, block swizzle)
// MODE 4: qkv     (epilogue stages tile to smem; RoPE+split q/k (+1/sqrt(D) on q), transpose v)
#define SAS 72
#define TILEB (128 * SAS * 2)     /* 18432 */
#define STAGE (2 * TILEB)         /* 36864 */
#define HG_SMEM (2 * STAGE)       /* 73728 */
#define EPS_ST 133                /* fp32 staging stride */

template<int MODE, bool RES>
__global__ void __launch_bounds__(256, 2)
hgemm(const __half* __restrict__ A, const __half* __restrict__ B,
      const float* __restrict__ R, float* __restrict__ Cf, __half* __restrict__ Ch,
      __half* __restrict__ Ck, __half* __restrict__ Cvt, const int* __restrict__ pos,
      int K, int ldc, float qscale, int S)
{
    extern __shared__ char sm[];
    const uint32_t sbase = smem_u32(sm);
    const int tid = threadIdx.x;

    int m0, n0;
    {
        int lin = blockIdx.y * gridDim.x + blockIdx.x;
        int grpSize = gridDim.x * 8;
        int grp = lin / grpSize, rem = lin % grpSize;
        m0 = (rem >> 3) * 128;
        n0 = (grp * 8 + (rem & 7)) * 128;
    }

    const int NB = K >> 6;
    const int wid = tid >> 5, lane = tid & 31;
    const int wm = (wid >> 2) * 64;
    const int wn = (wid & 3) * 32;

    const __half* srcs[2] = { A + (long)m0 * K, B + (long)n0 * K };

    const int alr = lane & 15, alc = (lane >> 4) * 8;
    const int blr = lane & 7;
    const int bhalf = (lane >> 3) & 1;
    const int bquad = (lane >> 4) * 8;

    float acc[4][4][4];
    #pragma unroll
    for (int i = 0; i < 4; i++)
        #pragma unroll
        for (int j = 0; j < 4; j++)
            #pragma unroll
            for (int q = 0; q < 4; q++) acc[i][j][q] = 0.f;

    auto load_stage = [&](int s, int blk) {
        const long kb = (long)blk << 6;
        #pragma unroll
        for (int t = 0; t < 2; t++) {
            const __half* S_ = srcs[t] + kb;
            const uint32_t dbase = sbase + s * STAGE + t * TILEB;
            #pragma unroll
            for (int i = 0; i < 4; i++) {
                int idx = tid + 256 * i;
                int r = idx >> 3, c = idx & 7;
                cp16(dbase + (r * SAS + c * 8) * 2, S_ + (long)r * K + c * 8);
            }
        }
        cp_commit();
    };

    load_stage(0, 0);

    for (int blk = 0; blk < NB; blk++) {
        const int s = blk & 1;
        if (blk + 1 < NB) { load_stage(s ^ 1, blk + 1); cp_wait1(); }
        else              { cp_wait0(); }
        __syncthreads();

        const uint32_t sA_ = sbase + s * STAGE;
        const uint32_t sB_ = sA_ + TILEB;

        #pragma unroll
        for (int kt = 0; kt < 4; kt++) {
            uint32_t aa[4][4], bb[4][2];
            #pragma unroll
            for (int ma = 0; ma < 4; ma++) {
                uint32_t ao = ((wm + ma * 16 + alr) * SAS + kt * 16 + alc) * 2;
                ldm_x4(aa[ma], sA_ + ao);
            }
            #pragma unroll
            for (int np = 0; np < 2; np++) {
                uint32_t bo = ((wn + np * 16 + bquad + blr) * SAS + kt * 16 + bhalf * 8) * 2;
                uint32_t t4[4];
                ldm_x4(t4, sB_ + bo);
                bb[np*2+0][0] = t4[0]; bb[np*2+0][1] = t4[1];
                bb[np*2+1][0] = t4[2]; bb[np*2+1][1] = t4[3];
            }
            #pragma unroll
            for (int ma = 0; ma < 4; ma++)
                #pragma unroll
                for (int na = 0; na < 4; na++)
                    mma16816h(acc[ma][na], aa[ma], bb[na]);
        }
        __syncthreads();
    }

    const int erow = lane >> 2, ecol = (lane & 3) * 2;

    if (MODE == 4) {
        float* st = (float*)sm;
        #pragma unroll
        for (int ma = 0; ma < 4; ma++) {
            #pragma unroll
            for (int na = 0; na < 4; na++) {
                int rr = wm + ma * 16 + erow;
                int cc = wn + na * 8 + ecol;
                st[rr * EPS_ST + cc]           = acc[ma][na][0];
                st[rr * EPS_ST + cc + 1]       = acc[ma][na][1];
                st[(rr + 8) * EPS_ST + cc]     = acc[ma][na][2];
                st[(rr + 8) * EPS_ST + cc + 1] = acc[ma][na][3];
            }
        }
        __syncthreads();
        const int nt = n0 >> 7;          // 0..15 q, 16..19 k, 20..23 v
        if (nt < NH + NKV) {
            const float sc_ = (nt < NH) ? qscale : 1.f;
            for (int i = tid; i < 128 * 64; i += 256) {
                int rr = i >> 6;
                int d  = i & 63;
                float t1 = st[rr * EPS_ST + d];
                float t2 = st[rr * EPS_ST + d + 64];
                int grow = m0 + rr;
                int b = grow / S, s = grow - b * S;
                float invf = __powf(10000.f, -(float)d * (1.f/64.f));
                float ang = (float)pos[s] * invf;
                float sn, cs;
                __sincosf(ang, &sn, &cs);
                float r1 = (t1 * cs - t2 * sn) * sc_;
                float r2 = (t2 * cs + t1 * sn) * sc_;
                if (nt < NH) {
                    long o = ((long)(b * NH + nt) * S + s) * HD;
                    Ch[o + d]      = __float2half_rn(r1);
                    Ch[o + d + 64] = __float2half_rn(r2);
                } else {
                    long o = ((long)(b * NKV + nt - NH) * S + s) * HD;
                    Ck[o + d]      = __float2half_rn(r1);
                    Ck[o + d + 64] = __float2half_rn(r2);
                }
            }
        } else {
            const int h = nt - NH - NKV;
            for (int i = tid; i < 128 * 128; i += 256) {
                int d  = i >> 7;
                int sc2 = i & 127;
                float v = st[sc2 * EPS_ST + d];
                int grow = m0 + sc2;
                int b = grow / S, s = grow - b * S;
                Cvt[((long)(b * NKV + h) * HD + d) * S + s] = __float2half_rn(v);
            }
        }
        return;
    }

    #pragma unroll
    for (int ma = 0; ma < 4; ma++) {
        #pragma unroll
        for (int na = 0; na < 4; na++) {
            long r0 = m0 + wm + ma * 16 + erow;
            long cc = n0 + wn + na * 8 + ecol;
            float v00 = acc[ma][na][0], v01 = acc[ma][na][1];
            float v10 = acc[ma][na][2], v11 = acc[ma][na][3];
            if (MODE == 3) {
                long j = cc >> 1;
                Ch[r0 * (long)FFI + j]       = __float2half_rn(silu_mul(v00, v01));
                Ch[(r0 + 8) * (long)FFI + j] = __float2half_rn(silu_mul(v10, v11));
            } else {
                if (RES) {
                    const float2 q0 = *(const float2*)&R[r0 * ldc + cc];
                    const float2 q1 = *(const float2*)&R[(r0 + 8) * ldc + cc];
                    v00 += q0.x; v01 += q0.y; v10 += q1.x; v11 += q1.y;
                }
                float2 w0 = {v00, v01}, w1 = {v10, v11};
                *(float2*)&Cf[r0 * ldc + cc] = w0;
                *(float2*)&Cf[(r0 + 8) * ldc + cc] = w1;
            }
        }
    }
}

// ================= fused flash attention =================
// grid (S/128, 1, B*NH). 8 warps along m (16 rows each, full 128-col tiles).
// Q pre-scaled by 1/sqrt(D). ao[b,s,h*HD+d] fp16.
#define FT_STRIDE 136
#define FT_TILEB (128 * FT_STRIDE * 2)   /* 34816 */
#define FT_SMEM  (5 * FT_TILEB)          /* 174080 */

__global__ void __launch_bounds__(256, 1)
fattn(const __half* __restrict__ Qg, const __half* __restrict__ Kg,
      const __half* __restrict__ Vg, __half* __restrict__ AO, int S)
{
    extern __shared__ char sm[];
    const uint32_t sb = smem_u32(sm);
    const int tid = threadIdx.x, wid = tid >> 5, lane = tid & 31;
    const int m0 = blockIdx.x * 128;
    const int z = blockIdx.z;
    const int b = z >> 4, h = z & 15;
    const __half* Qp = Qg + ((long)z * S + m0) * HD;
    const __half* Kp = Kg + (long)(b * NKV + (h >> 2)) * S * HD;
    const __half* Vp = Vg + (long)(b * NKV + (h >> 2)) * HD * S;

    const uint32_t sQ = sb;

    // load Q tile
    #pragma unroll
    for (int i = 0; i < 8; i++) {
        int idx = tid + 256 * i;
        int r = idx >> 4, c = idx & 15;
        cp16(sQ + (r * FT_STRIDE + c * 8) * 2, Qp + (long)r * HD + c * 8);
    }
    cp_commit();

    auto load_kv = [&](int st, int j) {
        const uint32_t sK = sb + FT_TILEB + st * 2 * FT_TILEB;
        const uint32_t sV = sK + FT_TILEB;
        const __half* ks = Kp + (long)(j * 128) * HD;
        const __half* vs = Vp + j * 128;
        #pragma unroll
        for (int i = 0; i < 8; i++) {
            int idx = tid + 256 * i;
            int r = idx >> 4, c = idx & 15;
            cp16(sK + (r * FT_STRIDE + c * 8) * 2, ks + (long)r * HD + c * 8);
        }
        #pragma unroll
        for (int i = 0; i < 8; i++) {
            int idx = tid + 256 * i;
            int r = idx >> 4, c = idx & 15;
            cp16(sV + (r * FT_STRIDE + c * 8) * 2, vs + (long)r * S + c * 8);
        }
        cp_commit();
    };

    const int J = blockIdx.x + 1;
    load_kv(0, 0);

    const int wm = wid * 16;
    const int alr = lane & 15, alc = (lane >> 4) * 8;
    const int blr = lane & 7, bhalf = (lane >> 3) & 1, bquad = (lane >> 4) * 8;
    const int r0 = lane >> 2, c0 = (lane & 3) * 2;

    float acc_o[16][4];
    #pragma unroll
    for (int i = 0; i < 16; i++)
        #pragma unroll
        for (int q = 0; q < 4; q++) acc_o[i][q] = 0.f;
    float rm0 = -1e30f, rm1 = -1e30f, rs0 = 0.f, rs1 = 0.f;

    for (int j = 0; j < J; j++) {
        const int st = j & 1;
        if (j + 1 < J) { load_kv(st ^ 1, j + 1); cp_wait1(); }
        else           { cp_wait0(); }
        __syncthreads();
        const uint32_t sK = sb + FT_TILEB + st * 2 * FT_TILEB;
        const uint32_t sV = sK + FT_TILEB;

        // S = Q K^T
        float accs[16][4];
        #pragma unroll
        for (int i = 0; i < 16; i++)
            #pragma unroll
            for (int q = 0; q < 4; q++) accs[i][q] = 0.f;
        #pragma unroll
        for (int kt = 0; kt < 8; kt++) {
            uint32_t aa[4];
            ldm_x4(aa, sQ + ((wm + alr) * FT_STRIDE + kt * 16 + alc) * 2);
            #pragma unroll
            for (int np = 0; np < 8; np++) {
                uint32_t t4[4];
                ldm_x4(t4, sK + ((np * 16 + bquad + blr) * FT_STRIDE + kt * 16 + bhalf * 8) * 2);
                uint32_t b0[2] = { t4[0], t4[1] }, b1[2] = { t4[2], t4[3] };
                mma16816h(accs[2*np],   aa, b0);
                mma16816h(accs[2*np+1], aa, b1);
            }
        }
        // causal mask (diagonal tile only; j*128 == m0 there, compare local idx)
        if (j == blockIdx.x) {
            const int row0 = wm + r0, row1 = row0 + 8;
            #pragma unroll
            for (int na = 0; na < 16; na++) {
                int col = na * 8 + c0;
                if (col     > row0) accs[na][0] = -1e30f;
                if (col + 1 > row0) accs[na][1] = -1e30f;
                if (col     > row1) accs[na][2] = -1e30f;
                if (col + 1 > row1) accs[na][3] = -1e30f;
            }
        }
        // online softmax (rows r0, r0+8 per thread-quad)
        float mt0 = -1e30f, mt1 = -1e30f;
        #pragma unroll
        for (int na = 0; na < 16; na++) {
            mt0 = fmaxf(mt0, fmaxf(accs[na][0], accs[na][1]));
            mt1 = fmaxf(mt1, fmaxf(accs[na][2], accs[na][3]));
        }
        mt0 = fmaxf(mt0, __shfl_xor_sync(0xffffffffu, mt0, 1));
        mt0 = fmaxf(mt0, __shfl_xor_sync(0xffffffffu, mt0, 2));
        mt1 = fmaxf(mt1, __shfl_xor_sync(0xffffffffu, mt1, 1));
        mt1 = fmaxf(mt1, __shfl_xor_sync(0xffffffffu, mt1, 2));
        float nm0 = fmaxf(rm0, mt0), nm1 = fmaxf(rm1, mt1);
        float corr0 = __expf(rm0 - nm0), corr1 = __expf(rm1 - nm1);
        rm0 = nm0; rm1 = nm1;
        float st0 = 0.f, st1 = 0.f;
        uint32_t pa[8][4];
        #pragma unroll
        for (int kf = 0; kf < 8; kf++) {
            float p00 = __expf(accs[2*kf][0]   - nm0), p01 = __expf(accs[2*kf][1]   - nm0);
            float p10 = __expf(accs[2*kf][2]   - nm1), p11 = __expf(accs[2*kf][3]   - nm1);
            float q00 = __expf(accs[2*kf+1][0] - nm0), q01 = __expf(accs[2*kf+1][1] - nm0);
            float q10 = __expf(accs[2*kf+1][2] - nm1), q11 = __expf(accs[2*kf+1][3] - nm1);
            st0 += p00 + p01 + q00 + q01;
            st1 += p10 + p11 + q10 + q11;
            pa[kf][0] = pack_h2(p00, p01);
            pa[kf][1] = pack_h2(p10, p11);
            pa[kf][2] = pack_h2(q00, q01);
            pa[kf][3] = pack_h2(q10, q11);
        }
        st0 += __shfl_xor_sync(0xffffffffu, st0, 1);
        st0 += __shfl_xor_sync(0xffffffffu, st0, 2);
        st1 += __shfl_xor_sync(0xffffffffu, st1, 1);
        st1 += __shfl_xor_sync(0xffffffffu, st1, 2);
        rs0 = rs0 * corr0 + st0;
        rs1 = rs1 * corr1 + st1;
        #pragma unroll
        for (int na = 0; na < 16; na++) {
            acc_o[na][0] *= corr0; acc_o[na][1] *= corr0;
            acc_o[na][2] *= corr1; acc_o[na][3] *= corr1;
        }
        // O += P V   (B operand = V^T tile: rows d, cols keys)
        #pragma unroll
        for (int kf = 0; kf < 8; kf++) {
            #pragma unroll
            for (int np = 0; np < 8; np++) {
                uint32_t t4[4];
                ldm_x4(t4, sV + ((np * 16 + bquad + blr) * FT_STRIDE + kf * 16 + bhalf * 8) * 2);
                uint32_t b0[2] = { t4[0], t4[1] }, b1[2] = { t4[2], t4[3] };
                mma16816h(acc_o[2*np],   pa[kf], b0);
                mma16816h(acc_o[2*np+1], pa[kf], b1);
            }
        }
        __syncthreads();
    }

    const float i0 = 1.f / rs0, i1 = 1.f / rs1;
    const int s0 = m0 + wm + r0;
    const long base0 = ((long)b * S + s0) * HIDD + h * HD;
    const long base1 = ((long)b * S + s0 + 8) * HIDD + h * HD;
    #pragma unroll
    for (int na = 0; na < 16; na++) {
        int d = na * 8 + c0;
        __half2 h0 = __floats2half2_rn(acc_o[na][0] * i0, acc_o[na][1] * i0);
        __half2 h1 = __floats2half2_rn(acc_o[na][2] * i1, acc_o[na][3] * i1);
        *(__half2*)&AO[base0 + d] = h0;
        *(__half2*)&AO[base1 + d] = h1;
    }
}

// ================= block reductions =================
__device__ __forceinline__ float block_sum(float v) {
    #pragma unroll
    for (int o = 16; o > 0; o >>= 1) v += __shfl_xor_sync(0xffffffffu, v, o);
    __shared__ float sh[8]; __shared__ float total;
    int w = threadIdx.x >> 5, l = threadIdx.x & 31;
    if (l == 0) sh[w] = v;
    __syncthreads();
    if (threadIdx.x == 0) { float s = 0.f; for (int i = 0; i < 8; i++) s += sh[i]; total = s; }
    __syncthreads();
    return total;
}

// ================= elementwise =================
__global__ void rmsnorm_h_kernel(const float* __restrict__ x, const float* __restrict__ w,
                                 __half* __restrict__ out) {
    long row = blockIdx.x;
    const float4* xr4 = (const float4*)(x + row * HIDD);
    const float4* w4  = (const float4*)w;
    float s = 0.f;
    #pragma unroll 2
    for (int i = threadIdx.x; i < HIDD / 4; i += 256) {
        float4 v = xr4[i];
        s += v.x * v.x + v.y * v.y + v.z * v.z + v.w * v.w;
    }
    s = block_sum(s);
    float inv = rsqrtf(s / (float)HIDD + 1e-6f);
    __half2* o2 = (__half2*)(out + row * HIDD);
    #pragma unroll 2
    for (int i = threadIdx.x; i < HIDD / 4; i += 256) {
        float4 v = xr4[i];
        float4 ww = w4[i];
        o2[2*i]   = __floats2half2_rn(v.x * inv * ww.x, v.y * inv * ww.y);
        o2[2*i+1] = __floats2half2_rn(v.z * inv * ww.z, v.w * inv * ww.w);
    }
}

// transpose-convert: W [K,N] fp32 -> T [N*rowMul + rowAdd, K] fp16 (64x64 tiles, half2 stores)
__global__ void convT_h_kernel(const float* __restrict__ W, __half* __restrict__ T,
                               int K, int N, int rowMul, int rowAdd) {
    __shared__ float smT[64][65];
    int n0 = blockIdx.x * 64, k0 = blockIdx.y * 64;
    int tid = threadIdx.x;
    int rcol = tid & 63, rrow = tid >> 6;
    #pragma unroll
    for (int p = 0; p < 16; p++) {
        int row = p * 4 + rrow;
        smT[row][rcol] = W[(long)(k0 + row) * N + n0 + rcol];
    }
    __syncthreads();
    int j = tid & 31, r8 = tid >> 5;
    #pragma unroll
    for (int p = 0; p < 8; p++) {
        int row = p * 8 + r8;
        __half2 h = __floats2half2_rn(smT[2*j][row], smT[2*j+1][row]);
        *(__half2*)&T[(long)((n0 + row) * rowMul + rowAdd) * K + k0 + 2*j] = h;
    }
}

// ================= host launcher =================
extern "C" void kernel_launch(void* const* d_in, const int* in_sizes, int n_in,
                              void* d_out, int out_size) {
    const float* x         = (const float*)d_in[0];
    const float* ln1_w     = (const float*)d_in[1];
    const float* wqkv      = (const float*)d_in[2];
    const float* wo        = (const float*)d_in[3];
    const float* ln2_w     = (const float*)d_in[4];
    const float* w_gate_up = (const float*)d_in[5];
    const float* w_down    = (const float*)d_in[6];
    const int*   pos       = (const int*)d_in[7];
    float* out = (float*)d_out;

    const int S  = in_sizes[7];                 // 1024
    const long BS = (long)in_sizes[0] / HIDD;   // 4096
    const int Bb = (int)(BS / S);               // 4

    float *pH1;
    cudaGetSymbolAddress((void**)&pH1,  g_h1);
    __half *pH,*pAO,*pACT,*pQ,*pK,*pVt;
    __half *pQKVT,*pWOT,*pGUT,*pDNT;
    cudaGetSymbolAddress((void**)&pH, g_h);
    cudaGetSymbolAddress((void**)&pAO, g_ao);
    cudaGetSymbolAddress((void**)&pACT, g_act);
    cudaGetSymbolAddress((void**)&pQ, g_q);
    cudaGetSymbolAddress((void**)&pK, g_k);
    cudaGetSymbolAddress((void**)&pVt, g_vt);
    cudaGetSymbolAddress((void**)&pQKVT, g_wqkvT);
    cudaGetSymbolAddress((void**)&pWOT, g_woT);
    cudaGetSymbolAddress((void**)&pGUT, g_guT);
    cudaGetSymbolAddress((void**)&pDNT, g_dnT);

    cudaFuncSetAttribute(hgemm<0,false>, cudaFuncAttributeMaxDynamicSharedMemorySize, HG_SMEM);
    cudaFuncSetAttribute(hgemm<0,true>,  cudaFuncAttributeMaxDynamicSharedMemorySize, HG_SMEM);
    cudaFuncSetAttribute(hgemm<3,false>, cudaFuncAttributeMaxDynamicSharedMemorySize, HG_SMEM);
    cudaFuncSetAttribute(hgemm<4,false>, cudaFuncAttributeMaxDynamicSharedMemorySize, HG_SMEM);
    cudaFuncSetAttribute(fattn, cudaFuncAttributeMaxDynamicSharedMemorySize, FT_SMEM);

    const float inv_sqrt_d = 0.08838834764831843f;

    // weight transpose+convert (fp16, [N,K]); gate/up interleaved rows
    convT_h_kernel<<<dim3(QKVW/64,  HIDD/64), 256>>>(wqkv,      pQKVT, HIDD, QKVW, 1, 0);
    convT_h_kernel<<<dim3(HIDD/64,  HIDD/64), 256>>>(wo,        pWOT,  HIDD, HIDD, 1, 0);
    convT_h_kernel<<<dim3(FFI/64,   HIDD/64), 256>>>(w_gate_up,       pGUT, HIDD, 2*FFI, 2, 0);
    convT_h_kernel<<<dim3(FFI/64,   HIDD/64), 256>>>(w_gate_up + FFI, pGUT, HIDD, 2*FFI, 2, 1);
    convT_h_kernel<<<dim3(HIDD/64,  FFI/64),  256>>>(w_down,    pDNT,  FFI,  HIDD, 1, 0);

    // 1. h = rmsnorm(x) -> fp16
    rmsnorm_h_kernel<<<(int)BS, 256>>>(x, ln1_w, pH);

    // 2+3. qkv GEMM with fused RoPE/split/v-transpose epilogue (q pre-scaled by 1/sqrt(D))
    hgemm<4,false><<<dim3((int)(BS/128), QKVW/128, 1), 256, HG_SMEM>>>(
        pH, pQKVT, nullptr, nullptr, pQ, pK, pVt, pos,
        HIDD, 0, inv_sqrt_d, S);

    // 4-6. fused flash attention -> ao fp16 [b,s,h*d]
    fattn<<<dim3(S/128, 1, Bb*NH), 256, FT_SMEM>>>(pQ, pK, pVt, pAO, S);

    // 7. h1 = x + attnout @ wo
    hgemm<0,true><<<dim3((int)(BS/128), HIDD/128, 1), 256, HG_SMEM>>>(
        pAO, pWOT, x, pH1, nullptr, nullptr, nullptr, nullptr,
        HIDD, HIDD, 0.f, S);

    // 8. h2 = rmsnorm(h1)
    rmsnorm_h_kernel<<<(int)BS, 256>>>(pH1, ln2_w, pH);

    // 9+10. act = silu(gate)*up fused into gate_up GEMM -> fp16
    hgemm<3,false><<<dim3((int)(BS/128), 2*FFI/128, 1), 256, HG_SMEM>>>(
        pH, pGUT, nullptr, nullptr, pACT, nullptr, nullptr, nullptr,
        HIDD, 2*FFI, 0.f, S);

    // 11. out = h1 + act @ w_down
    hgemm<0,true><<<dim3((int)(BS/128), HIDD/128, 1), 256, HG_SMEM>>>(
        pACT, pDNT, pH1, out, nullptr, nullptr, nullptr, nullptr,
        FFI, HIDD, 0.f, S);
}

// round 14
// speedup vs baseline: 8.0283x; 1.0059x over previous
#include <cuda_runtime.h>
#include <cuda_fp16.h>
#include <math.h>
#include <stdint.h>

#define NH   16
#define NKV  4
#define HD   128
#define HIDD 2048
#define FFI  8192
#define QKVW ((NH + 2*NKV) * HD)   /* 3072 */

// ================= scratch (B=4, S=1024) =================
static __device__ float g_h1[4096L * HIDD];

static __device__ __half g_h[4096L * HIDD];
static __device__ __half g_ao[4096L * HIDD];
static __device__ __half g_act[4096L * FFI];
static __device__ __half g_q[(long)4*NH*1024*HD];
static __device__ __half g_k[(long)4*NKV*1024*HD];
static __device__ __half g_vt[(long)4*NKV*HD*1024];
static __device__ __half g_wqkvT[(long)QKVW * HIDD];
static __device__ __half g_woT[(long)HIDD * HIDD];
static __device__ __half g_guT[(long)2*FFI * HIDD];   /* interleaved gate/up rows */
static __device__ __half g_dnT[(long)HIDD * FFI];

// ================= PTX helpers =================
__device__ __forceinline__ uint32_t smem_u32(const void* p) {
    uint32_t a;
    asm("{ .reg .u64 t; cvta.to.shared.u64 t, %1; cvt.u32.u64 %0, t; }" : "=r"(a) : "l"(p));
    return a;
}
__device__ __forceinline__ void cp16(uint32_t dst, const void* src) {
    asm volatile("cp.async.cg.shared.global [%0], [%1], 16;" :: "r"(dst), "l"(src));
}
__device__ __forceinline__ void cp_commit() { asm volatile("cp.async.commit_group;"); }
__device__ __forceinline__ void cp_wait1() { asm volatile("cp.async.wait_group 1;"); }
__device__ __forceinline__ void cp_wait0() { asm volatile("cp.async.wait_group 0;"); }

__device__ __forceinline__ void ldm_x4(uint32_t* r, uint32_t addr) {
    asm volatile("ldmatrix.sync.aligned.m8n8.x4.shared.b16 {%0,%1,%2,%3}, [%4];"
        : "=r"(r[0]), "=r"(r[1]), "=r"(r[2]), "=r"(r[3]) : "r"(addr));
}
__device__ __forceinline__ void mma16816h(float* d, const uint32_t* a, const uint32_t* b) {
    asm volatile("mma.sync.aligned.m16n8k16.row.col.f32.f16.f16.f32 "
        "{%0,%1,%2,%3}, {%4,%5,%6,%7}, {%8,%9}, {%0,%1,%2,%3};"
        : "+f"(d[0]), "+f"(d[1]), "+f"(d[2]), "+f"(d[3])
        : "r"(a[0]), "r"(a[1]), "r"(a[2]), "r"(a[3]), "r"(b[0]), "r"(b[1]));
}
__device__ __forceinline__ float silu_mul(float g, float u) {
    return (g / (1.f + __expf(-g))) * u;
}
__device__ __forceinline__ uint32_t pack_h2(float a, float b) {
    __half2 h = __floats2half2_rn(a, b);
    return *(uint32_t*)&h;
}

// ================= fp16 TN GEMM =================
// MODE 0: weights (fp32 out, optional residual, block swizzle)
// MODE 3: gate_up (interleaved B rows; epilogue silu(gate)*up -> fp16, block swizzle)
// MODE 4: qkv     (epilogue stages tile to smem; RoPE+split q/k (+1/sqrt(D) on q), transpose v)
#define SAS 72
#define TILEB (128 * SAS * 2)     /* 18432 */
#define STAGE (2 * TILEB)         /* 36864 */
#define HG_SMEM (2 * STAGE)       /* 73728 */
#define EPS_ST 133                /* fp32 staging stride */

template<int MODE, bool RES>
__global__ void __launch_bounds__(256, 2)
hgemm(const __half* __restrict__ A, const __half* __restrict__ B,
      const float* __restrict__ R, float* __restrict__ Cf, __half* __restrict__ Ch,
      __half* __restrict__ Ck, __half* __restrict__ Cvt, const int* __restrict__ pos,
      int K, int ldc, float qscale, int S)
{
    extern __shared__ char sm[];
    const uint32_t sbase = smem_u32(sm);
    const int tid = threadIdx.x;

    int m0, n0;
    {
        int lin = blockIdx.y * gridDim.x + blockIdx.x;
        int grpSize = gridDim.x * 8;
        int grp = lin / grpSize, rem = lin % grpSize;
        m0 = (rem >> 3) * 128;
        n0 = (grp * 8 + (rem & 7)) * 128;
    }

    const int NB = K >> 6;
    const int wid = tid >> 5, lane = tid & 31;
    const int wm = (wid >> 2) * 64;
    const int wn = (wid & 3) * 32;

    const __half* srcs[2] = { A + (long)m0 * K, B + (long)n0 * K };

    const int alr = lane & 15, alc = (lane >> 4) * 8;
    const int blr = lane & 7;
    const int bhalf = (lane >> 3) & 1;
    const int bquad = (lane >> 4) * 8;

    float acc[4][4][4];
    #pragma unroll
    for (int i = 0; i < 4; i++)
        #pragma unroll
        for (int j = 0; j < 4; j++)
            #pragma unroll
            for (int q = 0; q < 4; q++) acc[i][j][q] = 0.f;

    auto load_stage = [&](int s, int blk) {
        const long kb = (long)blk << 6;
        #pragma unroll
        for (int t = 0; t < 2; t++) {
            const __half* S_ = srcs[t] + kb;
            const uint32_t dbase = sbase + s * STAGE + t * TILEB;
            #pragma unroll
            for (int i = 0; i < 4; i++) {
                int idx = tid + 256 * i;
                int r = idx >> 3, c = idx & 7;
                cp16(dbase + (r * SAS + c * 8) * 2, S_ + (long)r * K + c * 8);
            }
        }
        cp_commit();
    };

    load_stage(0, 0);

    for (int blk = 0; blk < NB; blk++) {
        const int s = blk & 1;
        if (blk + 1 < NB) { load_stage(s ^ 1, blk + 1); cp_wait1(); }
        else              { cp_wait0(); }
        __syncthreads();

        const uint32_t sA_ = sbase + s * STAGE;
        const uint32_t sB_ = sA_ + TILEB;

        #pragma unroll
        for (int kt = 0; kt < 4; kt++) {
            uint32_t aa[4][4], bb[4][2];
            #pragma unroll
            for (int ma = 0; ma < 4; ma++) {
                uint32_t ao = ((wm + ma * 16 + alr) * SAS + kt * 16 + alc) * 2;
                ldm_x4(aa[ma], sA_ + ao);
            }
            #pragma unroll
            for (int np = 0; np < 2; np++) {
                uint32_t bo = ((wn + np * 16 + bquad + blr) * SAS + kt * 16 + bhalf * 8) * 2;
                uint32_t t4[4];
                ldm_x4(t4, sB_ + bo);
                bb[np*2+0][0] = t4[0]; bb[np*2+0][1] = t4[1];
                bb[np*2+1][0] = t4[2]; bb[np*2+1][1] = t4[3];
            }
            #pragma unroll
            for (int ma = 0; ma < 4; ma++)
                #pragma unroll
                for (int na = 0; na < 4; na++)
                    mma16816h(acc[ma][na], aa[ma], bb[na]);
        }
        __syncthreads();
    }

    const int erow = lane >> 2, ecol = (lane & 3) * 2;

    if (MODE == 4) {
        float* st = (float*)sm;
        #pragma unroll
        for (int ma = 0; ma < 4; ma++) {
            #pragma unroll
            for (int na = 0; na < 4; na++) {
                int rr = wm + ma * 16 + erow;
                int cc = wn + na * 8 + ecol;
                st[rr * EPS_ST + cc]           = acc[ma][na][0];
                st[rr * EPS_ST + cc + 1]       = acc[ma][na][1];
                st[(rr + 8) * EPS_ST + cc]     = acc[ma][na][2];
                st[(rr + 8) * EPS_ST + cc + 1] = acc[ma][na][3];
            }
        }
        __syncthreads();
        const int nt = n0 >> 7;          // 0..15 q, 16..19 k, 20..23 v
        if (nt < NH + NKV) {
            const float sc_ = (nt < NH) ? qscale : 1.f;
            for (int i = tid; i < 128 * 64; i += 256) {
                int rr = i >> 6;
                int d  = i & 63;
                float t1 = st[rr * EPS_ST + d];
                float t2 = st[rr * EPS_ST + d + 64];
                int grow = m0 + rr;
                int b = grow / S, s = grow - b * S;
                float invf = __powf(10000.f, -(float)d * (1.f/64.f));
                float ang = (float)pos[s] * invf;
                float sn, cs;
                __sincosf(ang, &sn, &cs);
                float r1 = (t1 * cs - t2 * sn) * sc_;
                float r2 = (t2 * cs + t1 * sn) * sc_;
                if (nt < NH) {
                    long o = ((long)(b * NH + nt) * S + s) * HD;
                    Ch[o + d]      = __float2half_rn(r1);
                    Ch[o + d + 64] = __float2half_rn(r2);
                } else {
                    long o = ((long)(b * NKV + nt - NH) * S + s) * HD;
                    Ck[o + d]      = __float2half_rn(r1);
                    Ck[o + d + 64] = __float2half_rn(r2);
                }
            }
        } else {
            const int h = nt - NH - NKV;
            for (int i = tid; i < 128 * 128; i += 256) {
                int d  = i >> 7;
                int sc2 = i & 127;
                float v = st[sc2 * EPS_ST + d];
                int grow = m0 + sc2;
                int b = grow / S, s = grow - b * S;
                Cvt[((long)(b * NKV + h) * HD + d) * S + s] = __float2half_rn(v);
            }
        }
        return;
    }

    #pragma unroll
    for (int ma = 0; ma < 4; ma++) {
        #pragma unroll
        for (int na = 0; na < 4; na++) {
            long r0 = m0 + wm + ma * 16 + erow;
            long cc = n0 + wn + na * 8 + ecol;
            float v00 = acc[ma][na][0], v01 = acc[ma][na][1];
            float v10 = acc[ma][na][2], v11 = acc[ma][na][3];
            if (MODE == 3) {
                long j = cc >> 1;
                Ch[r0 * (long)FFI + j]       = __float2half_rn(silu_mul(v00, v01));
                Ch[(r0 + 8) * (long)FFI + j] = __float2half_rn(silu_mul(v10, v11));
            } else {
                if (RES) {
                    const float2 q0 = *(const float2*)&R[r0 * ldc + cc];
                    const float2 q1 = *(const float2*)&R[(r0 + 8) * ldc + cc];
                    v00 += q0.x; v01 += q0.y; v10 += q1.x; v11 += q1.y;
                }
                float2 w0 = {v00, v01}, w1 = {v10, v11};
                *(float2*)&Cf[r0 * ldc + cc] = w0;
                *(float2*)&Cf[(r0 + 8) * ldc + cc] = w1;
            }
        }
    }
}

// ================= fused flash attention =================
// grid (S/128, 1, B*NH). Heavy-first: mt = gridDim.x-1-blockIdx.x.
// 8 warps along m (16 rows each). Q pre-scaled by 1/sqrt(D). ao[b,s,h*HD+d] fp16.
#define FT_STRIDE 136
#define FT_TILEB (128 * FT_STRIDE * 2)   /* 34816 */
#define FT_SMEM  (5 * FT_TILEB)          /* 174080 */

__global__ void __launch_bounds__(256, 1)
fattn(const __half* __restrict__ Qg, const __half* __restrict__ Kg,
      const __half* __restrict__ Vg, __half* __restrict__ AO, int S)
{
    extern __shared__ char sm[];
    const uint32_t sb = smem_u32(sm);
    const int tid = threadIdx.x, wid = tid >> 5, lane = tid & 31;
    const int mt = gridDim.x - 1 - blockIdx.x;   // heavy tiles scheduled first
    const int m0 = mt * 128;
    const int z = blockIdx.z;
    const int b = z >> 4, h = z & 15;
    const __half* Qp = Qg + ((long)z * S + m0) * HD;
    const __half* Kp = Kg + (long)(b * NKV + (h >> 2)) * S * HD;
    const __half* Vp = Vg + (long)(b * NKV + (h >> 2)) * HD * S;

    const uint32_t sQ = sb;

    // load Q tile
    #pragma unroll
    for (int i = 0; i < 8; i++) {
        int idx = tid + 256 * i;
        int r = idx >> 4, c = idx & 15;
        cp16(sQ + (r * FT_STRIDE + c * 8) * 2, Qp + (long)r * HD + c * 8);
    }
    cp_commit();

    auto load_kv = [&](int st, int j) {
        const uint32_t sK = sb + FT_TILEB + st * 2 * FT_TILEB;
        const uint32_t sV = sK + FT_TILEB;
        const __half* ks = Kp + (long)(j * 128) * HD;
        const __half* vs = Vp + j * 128;
        #pragma unroll
        for (int i = 0; i < 8; i++) {
            int idx = tid + 256 * i;
            int r = idx >> 4, c = idx & 15;
            cp16(sK + (r * FT_STRIDE + c * 8) * 2, ks + (long)r * HD + c * 8);
        }
        #pragma unroll
        for (int i = 0; i < 8; i++) {
            int idx = tid + 256 * i;
            int r = idx >> 4, c = idx & 15;
            cp16(sV + (r * FT_STRIDE + c * 8) * 2, vs + (long)r * S + c * 8);
        }
        cp_commit();
    };

    const int J = mt + 1;
    load_kv(0, 0);

    const int wm = wid * 16;
    const int alr = lane & 15, alc = (lane >> 4) * 8;
    const int blr = lane & 7, bhalf = (lane >> 3) & 1, bquad = (lane >> 4) * 8;
    const int r0 = lane >> 2, c0 = (lane & 3) * 2;

    float acc_o[16][4];
    #pragma unroll
    for (int i = 0; i < 16; i++)
        #pragma unroll
        for (int q = 0; q < 4; q++) acc_o[i][q] = 0.f;
    float rm0 = -1e30f, rm1 = -1e30f, rs0 = 0.f, rs1 = 0.f;

    for (int j = 0; j < J; j++) {
        const int st = j & 1;
        if (j + 1 < J) { load_kv(st ^ 1, j + 1); cp_wait1(); }
        else           { cp_wait0(); }
        __syncthreads();
        const uint32_t sK = sb + FT_TILEB + st * 2 * FT_TILEB;
        const uint32_t sV = sK + FT_TILEB;

        // S = Q K^T
        float accs[16][4];
        #pragma unroll
        for (int i = 0; i < 16; i++)
            #pragma unroll
            for (int q = 0; q < 4; q++) accs[i][q] = 0.f;
        #pragma unroll
        for (int kt = 0; kt < 8; kt++) {
            uint32_t aa[4];
            ldm_x4(aa, sQ + ((wm + alr) * FT_STRIDE + kt * 16 + alc) * 2);
            #pragma unroll
            for (int np = 0; np < 8; np++) {
                uint32_t t4[4];
                ldm_x4(t4, sK + ((np * 16 + bquad + blr) * FT_STRIDE + kt * 16 + bhalf * 8) * 2);
                uint32_t b0[2] = { t4[0], t4[1] }, b1[2] = { t4[2], t4[3] };
                mma16816h(accs[2*np],   aa, b0);
                mma16816h(accs[2*np+1], aa, b1);
            }
        }
        // causal mask (diagonal tile only)
        if (j == mt) {
            const int row0 = wm + r0, row1 = row0 + 8;
            #pragma unroll
            for (int na = 0; na < 16; na++) {
                int col = na * 8 + c0;
                if (col     > row0) accs[na][0] = -1e30f;
                if (col + 1 > row0) accs[na][1] = -1e30f;
                if (col     > row1) accs[na][2] = -1e30f;
                if (col + 1 > row1) accs[na][3] = -1e30f;
            }
        }
        // online softmax (rows r0, r0+8 per thread-quad)
        float mt0 = -1e30f, mt1 = -1e30f;
        #pragma unroll
        for (int na = 0; na < 16; na++) {
            mt0 = fmaxf(mt0, fmaxf(accs[na][0], accs[na][1]));
            mt1 = fmaxf(mt1, fmaxf(accs[na][2], accs[na][3]));
        }
        mt0 = fmaxf(mt0, __shfl_xor_sync(0xffffffffu, mt0, 1));
        mt0 = fmaxf(mt0, __shfl_xor_sync(0xffffffffu, mt0, 2));
        mt1 = fmaxf(mt1, __shfl_xor_sync(0xffffffffu, mt1, 1));
        mt1 = fmaxf(mt1, __shfl_xor_sync(0xffffffffu, mt1, 2));
        float nm0 = fmaxf(rm0, mt0), nm1 = fmaxf(rm1, mt1);
        float corr0 = __expf(rm0 - nm0), corr1 = __expf(rm1 - nm1);
        rm0 = nm0; rm1 = nm1;
        float st0 = 0.f, st1 = 0.f;
        uint32_t pa[8][4];
        #pragma unroll
        for (int kf = 0; kf < 8; kf++) {
            float p00 = __expf(accs[2*kf][0]   - nm0), p01 = __expf(accs[2*kf][1]   - nm0);
            float p10 = __expf(accs[2*kf][2]   - nm1), p11 = __expf(accs[2*kf][3]   - nm1);
            float q00 = __expf(accs[2*kf+1][0] - nm0), q01 = __expf(accs[2*kf+1][1] - nm0);
            float q10 = __expf(accs[2*kf+1][2] - nm1), q11 = __expf(accs[2*kf+1][3] - nm1);
            st0 += p00 + p01 + q00 + q01;
            st1 += p10 + p11 + q10 + q11;
            pa[kf][0] = pack_h2(p00, p01);
            pa[kf][1] = pack_h2(p10, p11);
            pa[kf][2] = pack_h2(q00, q01);
            pa[kf][3] = pack_h2(q10, q11);
        }
        st0 += __shfl_xor_sync(0xffffffffu, st0, 1);
        st0 += __shfl_xor_sync(0xffffffffu, st0, 2);
        st1 += __shfl_xor_sync(0xffffffffu, st1, 1);
        st1 += __shfl_xor_sync(0xffffffffu, st1, 2);
        rs0 = rs0 * corr0 + st0;
        rs1 = rs1 * corr1 + st1;
        #pragma unroll
        for (int na = 0; na < 16; na++) {
            acc_o[na][0] *= corr0; acc_o[na][1] *= corr0;
            acc_o[na][2] *= corr1; acc_o[na][3] *= corr1;
        }
        // O += P V   (B operand = V^T tile: rows d, cols keys)
        #pragma unroll
        for (int kf = 0; kf < 8; kf++) {
            #pragma unroll
            for (int np = 0; np < 8; np++) {
                uint32_t t4[4];
                ldm_x4(t4, sV + ((np * 16 + bquad + blr) * FT_STRIDE + kf * 16 + bhalf * 8) * 2);
                uint32_t b0[2] = { t4[0], t4[1] }, b1[2] = { t4[2], t4[3] };
                mma16816h(acc_o[2*np],   pa[kf], b0);
                mma16816h(acc_o[2*np+1], pa[kf], b1);
            }
        }
        __syncthreads();
    }

    const float i0 = 1.f / rs0, i1 = 1.f / rs1;
    const int s0 = m0 + wm + r0;
    const long base0 = ((long)b * S + s0) * HIDD + h * HD;
    const long base1 = ((long)b * S + s0 + 8) * HIDD + h * HD;
    #pragma unroll
    for (int na = 0; na < 16; na++) {
        int d = na * 8 + c0;
        __half2 h0 = __floats2half2_rn(acc_o[na][0] * i0, acc_o[na][1] * i0);
        __half2 h1 = __floats2half2_rn(acc_o[na][2] * i1, acc_o[na][3] * i1);
        *(__half2*)&AO[base0 + d] = h0;
        *(__half2*)&AO[base1 + d] = h1;
    }
}

// ================= block reductions =================
__device__ __forceinline__ float block_sum(float v) {
    #pragma unroll
    for (int o = 16; o > 0; o >>= 1) v += __shfl_xor_sync(0xffffffffu, v, o);
    __shared__ float sh[8]; __shared__ float total;
    int w = threadIdx.x >> 5, l = threadIdx.x & 31;
    if (l == 0) sh[w] = v;
    __syncthreads();
    if (threadIdx.x == 0) { float s = 0.f; for (int i = 0; i < 8; i++) s += sh[i]; total = s; }
    __syncthreads();
    return total;
}

// ================= elementwise =================
__global__ void rmsnorm_h_kernel(const float* __restrict__ x, const float* __restrict__ w,
                                 __half* __restrict__ out) {
    long row = blockIdx.x;
    const float4* xr4 = (const float4*)(x + row * HIDD);
    const float4* w4  = (const float4*)w;
    float s = 0.f;
    #pragma unroll 2
    for (int i = threadIdx.x; i < HIDD / 4; i += 256) {
        float4 v = xr4[i];
        s += v.x * v.x + v.y * v.y + v.z * v.z + v.w * v.w;
    }
    s = block_sum(s);
    float inv = rsqrtf(s / (float)HIDD + 1e-6f);
    __half2* o2 = (__half2*)(out + row * HIDD);
    #pragma unroll 2
    for (int i = threadIdx.x; i < HIDD / 4; i += 256) {
        float4 v = xr4[i];
        float4 ww = w4[i];
        o2[2*i]   = __floats2half2_rn(v.x * inv * ww.x, v.y * inv * ww.y);
        o2[2*i+1] = __floats2half2_rn(v.z * inv * ww.z, v.w * inv * ww.w);
    }
}

// transpose-convert: W [K,N] fp32 -> T [N*rowMul + rowAdd, K] fp16
// 64x64 tiles; float4 loads, uint4 (8-half) stores.
__global__ void convT_h_kernel(const float* __restrict__ W, __half* __restrict__ T,
                               int K, int N, int rowMul, int rowAdd) {
    __shared__ float smT[64][65];
    int n0 = blockIdx.x * 64, k0 = blockIdx.y * 64;
    int tid = threadIdx.x;
    // load 64x64 fp32 tile with float4
    #pragma unroll
    for (int p = 0; p < 4; p++) {
        int idx = tid + 256 * p;          // 1024 float4 chunks
        int r = idx >> 4, c = idx & 15;
        float4 v = *(const float4*)&W[(long)(k0 + r) * N + n0 + c * 4];
        smT[r][c*4+0] = v.x; smT[r][c*4+1] = v.y; smT[r][c*4+2] = v.z; smT[r][c*4+3] = v.w;
    }
    __syncthreads();
    // store: each thread packs 8 consecutive k into one 16B store
    #pragma unroll
    for (int p = 0; p < 2; p++) {
        int idx = tid + 256 * p;          // 512 chunks: 64 rows x 8 chunks
        int row = idx >> 3, cj = idx & 7;
        uint32_t h4[4];
        #pragma unroll
        for (int t = 0; t < 4; t++) {
            __half2 h = __floats2half2_rn(smT[cj*8 + 2*t][row], smT[cj*8 + 2*t + 1][row]);
            h4[t] = *(uint32_t*)&h;
        }
        *(uint4*)&T[(long)((n0 + row) * rowMul + rowAdd) * K + k0 + cj * 8] =
            make_uint4(h4[0], h4[1], h4[2], h4[3]);
    }
}

// ================= host launcher =================
extern "C" void kernel_launch(void* const* d_in, const int* in_sizes, int n_in,
                              void* d_out, int out_size) {
    const float* x         = (const float*)d_in[0];
    const float* ln1_w     = (const float*)d_in[1];
    const float* wqkv      = (const float*)d_in[2];
    const float* wo        = (const float*)d_in[3];
    const float* ln2_w     = (const float*)d_in[4];
    const float* w_gate_up = (const float*)d_in[5];
    const float* w_down    = (const float*)d_in[6];
    const int*   pos       = (const int*)d_in[7];
    float* out = (float*)d_out;

    const int S  = in_sizes[7];                 // 1024
    const long BS = (long)in_sizes[0] / HIDD;   // 4096
    const int Bb = (int)(BS / S);               // 4

    float *pH1;
    cudaGetSymbolAddress((void**)&pH1,  g_h1);
    __half *pH,*pAO,*pACT,*pQ,*pK,*pVt;
    __half *pQKVT,*pWOT,*pGUT,*pDNT;
    cudaGetSymbolAddress((void**)&pH, g_h);
    cudaGetSymbolAddress((void**)&pAO, g_ao);
    cudaGetSymbolAddress((void**)&pACT, g_act);
    cudaGetSymbolAddress((void**)&pQ, g_q);
    cudaGetSymbolAddress((void**)&pK, g_k);
    cudaGetSymbolAddress((void**)&pVt, g_vt);
    cudaGetSymbolAddress((void**)&pQKVT, g_wqkvT);
    cudaGetSymbolAddress((void**)&pWOT, g_woT);
    cudaGetSymbolAddress((void**)&pGUT, g_guT);
    cudaGetSymbolAddress((void**)&pDNT, g_dnT);

    cudaFuncSetAttribute(hgemm<0,false>, cudaFuncAttributeMaxDynamicSharedMemorySize, HG_SMEM);
    cudaFuncSetAttribute(hgemm<0,true>,  cudaFuncAttributeMaxDynamicSharedMemorySize, HG_SMEM);
    cudaFuncSetAttribute(hgemm<3,false>, cudaFuncAttributeMaxDynamicSharedMemorySize, HG_SMEM);
    cudaFuncSetAttribute(hgemm<4,false>, cudaFuncAttributeMaxDynamicSharedMemorySize, HG_SMEM);
    cudaFuncSetAttribute(fattn, cudaFuncAttributeMaxDynamicSharedMemorySize, FT_SMEM);

    const float inv_sqrt_d = 0.08838834764831843f;

    // weight transpose+convert (fp16, [N,K]); gate/up interleaved rows
    convT_h_kernel<<<dim3(QKVW/64,  HIDD/64), 256>>>(wqkv,      pQKVT, HIDD, QKVW, 1, 0);
    convT_h_kernel<<<dim3(HIDD/64,  HIDD/64), 256>>>(wo,        pWOT,  HIDD, HIDD, 1, 0);
    convT_h_kernel<<<dim3(FFI/64,   HIDD/64), 256>>>(w_gate_up,       pGUT, HIDD, 2*FFI, 2, 0);
    convT_h_kernel<<<dim3(FFI/64,   HIDD/64), 256>>>(w_gate_up + FFI, pGUT, HIDD, 2*FFI, 2, 1);
    convT_h_kernel<<<dim3(HIDD/64,  FFI/64),  256>>>(w_down,    pDNT,  FFI,  HIDD, 1, 0);

    // 1. h = rmsnorm(x) -> fp16
    rmsnorm_h_kernel<<<(int)BS, 256>>>(x, ln1_w, pH);

    // 2+3. qkv GEMM with fused RoPE/split/v-transpose epilogue (q pre-scaled by 1/sqrt(D))
    hgemm<4,false><<<dim3((int)(BS/128), QKVW/128, 1), 256, HG_SMEM>>>(
        pH, pQKVT, nullptr, nullptr, pQ, pK, pVt, pos,
        HIDD, 0, inv_sqrt_d, S);

    // 4-6. fused flash attention -> ao fp16 [b,s,h*d]
    fattn<<<dim3(S/128, 1, Bb*NH), 256, FT_SMEM>>>(pQ, pK, pVt, pAO, S);

    // 7. h1 = x + attnout @ wo
    hgemm<0,true><<<dim3((int)(BS/128), HIDD/128, 1), 256, HG_SMEM>>>(
        pAO, pWOT, x, pH1, nullptr, nullptr, nullptr, nullptr,
        HIDD, HIDD, 0.f, S);

    // 8. h2 = rmsnorm(h1)
    rmsnorm_h_kernel<<<(int)BS, 256>>>(pH1, ln2_w, pH);

    // 9+10. act = silu(gate)*up fused into gate_up GEMM -> fp16
    hgemm<3,false><<<dim3((int)(BS/128), 2*FFI/128, 1), 256, HG_SMEM>>>(
        pH, pGUT, nullptr, nullptr, pACT, nullptr, nullptr, nullptr,
        HIDD, 2*FFI, 0.f, S);

    // 11. out = h1 + act @ w_down
    hgemm<0,true><<<dim3((int)(BS/128), HIDD/128, 1), 256, HG_SMEM>>>(
        pACT, pDNT, pH1, out, nullptr, nullptr, nullptr, nullptr,
        FFI, HIDD, 0.f, S);
}

// round 15
// speedup vs baseline: 8.2109x; 1.0227x over previous
#include <cuda_runtime.h>
#include <cuda_fp16.h>
#include <math.h>
#include <stdint.h>

#define NH   16
#define NKV  4
#define HD   128
#define HIDD 2048
#define FFI  8192
#define QKVW ((NH + 2*NKV) * HD)   /* 3072 */

// ================= scratch (B=4, S=1024) =================
static __device__ float g_h1[4096L * HIDD];

static __device__ __half g_h[4096L * HIDD];
static __device__ __half g_ao[4096L * HIDD];
static __device__ __half g_act[4096L * FFI];
static __device__ __half g_q[(long)4*NH*1024*HD];
static __device__ __half g_k[(long)4*NKV*1024*HD];
static __device__ __half g_vt[(long)4*NKV*HD*1024];
static __device__ __half g_wqkvH[(long)HIDD * QKVW];   /* [K,N] native */
static __device__ __half g_woH[(long)HIDD * HIDD];
static __device__ __half g_guH[(long)HIDD * 2*FFI];    /* [K,N], gate/up 8-block interleaved */
static __device__ __half g_dnH[(long)FFI * HIDD];

// ================= PTX helpers =================
__device__ __forceinline__ uint32_t smem_u32(const void* p) {
    uint32_t a;
    asm("{ .reg .u64 t; cvta.to.shared.u64 t, %1; cvt.u32.u64 %0, t; }" : "=r"(a) : "l"(p));
    return a;
}
__device__ __forceinline__ void cp16(uint32_t dst, const void* src) {
    asm volatile("cp.async.cg.shared.global [%0], [%1], 16;" :: "r"(dst), "l"(src));
}
__device__ __forceinline__ void cp_commit() { asm volatile("cp.async.commit_group;"); }
__device__ __forceinline__ void cp_wait1() { asm volatile("cp.async.wait_group 1;"); }
__device__ __forceinline__ void cp_wait0() { asm volatile("cp.async.wait_group 0;"); }

__device__ __forceinline__ void ldm_x4(uint32_t* r, uint32_t addr) {
    asm volatile("ldmatrix.sync.aligned.m8n8.x4.shared.b16 {%0,%1,%2,%3}, [%4];"
        : "=r"(r[0]), "=r"(r[1]), "=r"(r[2]), "=r"(r[3]) : "r"(addr));
}
__device__ __forceinline__ void ldm_x4t(uint32_t* r, uint32_t addr) {
    asm volatile("ldmatrix.sync.aligned.m8n8.x4.trans.shared.b16 {%0,%1,%2,%3}, [%4];"
        : "=r"(r[0]), "=r"(r[1]), "=r"(r[2]), "=r"(r[3]) : "r"(addr));
}
__device__ __forceinline__ void mma16816h(float* d, const uint32_t* a, const uint32_t* b) {
    asm volatile("mma.sync.aligned.m16n8k16.row.col.f32.f16.f16.f32 "
        "{%0,%1,%2,%3}, {%4,%5,%6,%7}, {%8,%9}, {%0,%1,%2,%3};"
        : "+f"(d[0]), "+f"(d[1]), "+f"(d[2]), "+f"(d[3])
        : "r"(a[0]), "r"(a[1]), "r"(a[2]), "r"(a[3]), "r"(b[0]), "r"(b[1]));
}
__device__ __forceinline__ float silu_mul(float g, float u) {
    return (g / (1.f + __expf(-g))) * u;
}
__device__ __forceinline__ uint32_t pack_h2(float a, float b) {
    __half2 h = __floats2half2_rn(a, b);
    return *(uint32_t*)&h;
}

// ================= fp16 GEMM (A: [M,K] row-major; B: [K,N] row-major via ldmatrix.trans) =================
// MODE 0: weights (fp32 out, optional residual, block swizzle)
// MODE 3: gate_up (8-block-interleaved B cols; epilogue silu(gate)*up -> fp16, block swizzle)
// MODE 4: qkv     (epilogue stages tile to smem; RoPE+split q/k (+1/sqrt(D) on q), transpose v)
#define SAS 72
#define ATILEB (128 * SAS * 2)    /* 18432 */
#define BSTR 136                  /* B smem row stride (halves) */
#define BTILEB (64 * BSTR * 2)    /* 17408 */
#define STAGE (ATILEB + BTILEB)   /* 35840 */
#define HG_SMEM (2 * STAGE)       /* 71680 */
#define EPS_ST 133                /* fp32 staging stride; 128*133*4=68096 <= 71680 */

template<int MODE, bool RES>
__global__ void __launch_bounds__(256, 2)
hgemm(const __half* __restrict__ A, const __half* __restrict__ B,
      const float* __restrict__ R, float* __restrict__ Cf, __half* __restrict__ Ch,
      __half* __restrict__ Ck, __half* __restrict__ Cvt, const int* __restrict__ pos,
      int K, int ldb, int ldc, float qscale, int S)
{
    extern __shared__ char sm[];
    const uint32_t sbase = smem_u32(sm);
    const int tid = threadIdx.x;

    int m0, n0;
    {
        int lin = blockIdx.y * gridDim.x + blockIdx.x;
        int grpSize = gridDim.x * 8;
        int grp = lin / grpSize, rem = lin % grpSize;
        m0 = (rem >> 3) * 128;
        n0 = (grp * 8 + (rem & 7)) * 128;
    }

    const int NB = K >> 6;
    const int wid = tid >> 5, lane = tid & 31;
    const int wm = (wid >> 2) * 64;
    const int wn = (wid & 3) * 32;

    const __half* Asrc = A + (long)m0 * K;
    const __half* Bsrc = B + n0;

    const int alr = lane & 15, alc = (lane >> 4) * 8;
    const int blr = lane & 7;
    const int bhalf = (lane >> 3) & 1;
    const int bquad = (lane >> 4) * 8;

    float acc[4][4][4];
    #pragma unroll
    for (int i = 0; i < 4; i++)
        #pragma unroll
        for (int j = 0; j < 4; j++)
            #pragma unroll
            for (int q = 0; q < 4; q++) acc[i][j][q] = 0.f;

    auto load_stage = [&](int s, int blk) {
        const long kb = (long)blk << 6;
        const uint32_t dA = sbase + s * STAGE;
        #pragma unroll
        for (int i = 0; i < 4; i++) {
            int idx = tid + 256 * i;
            int r = idx >> 3, c = idx & 7;
            cp16(dA + (r * SAS + c * 8) * 2, Asrc + kb + (long)r * K + c * 8);
        }
        const uint32_t dB = dA + ATILEB;
        #pragma unroll
        for (int i = 0; i < 4; i++) {
            int idx = tid + 256 * i;
            int r = idx >> 4, c = idx & 15;   // r: k-row 0..63, c: n-chunk
            cp16(dB + (r * BSTR + c * 8) * 2, Bsrc + (kb + r) * (long)ldb + c * 8);
        }
        cp_commit();
    };

    load_stage(0, 0);

    for (int blk = 0; blk < NB; blk++) {
        const int s = blk & 1;
        if (blk + 1 < NB) { load_stage(s ^ 1, blk + 1); cp_wait1(); }
        else              { cp_wait0(); }
        __syncthreads();

        const uint32_t sA_ = sbase + s * STAGE;
        const uint32_t sB_ = sA_ + ATILEB;

        #pragma unroll
        for (int kt = 0; kt < 4; kt++) {
            uint32_t aa[4][4], bb[4][2];
            #pragma unroll
            for (int ma = 0; ma < 4; ma++) {
                uint32_t ao = ((wm + ma * 16 + alr) * SAS + kt * 16 + alc) * 2;
                ldm_x4(aa[ma], sA_ + ao);
            }
            #pragma unroll
            for (int np = 0; np < 2; np++) {
                // B tile [k][n]: rows = k, .trans produces col-major fragments
                uint32_t bo = ((kt * 16 + bhalf * 8 + blr) * BSTR + wn + np * 16 + bquad) * 2;
                uint32_t t4[4];
                ldm_x4t(t4, sB_ + bo);
                bb[np*2+0][0] = t4[0]; bb[np*2+0][1] = t4[1];
                bb[np*2+1][0] = t4[2]; bb[np*2+1][1] = t4[3];
            }
            #pragma unroll
            for (int ma = 0; ma < 4; ma++)
                #pragma unroll
                for (int na = 0; na < 4; na++)
                    mma16816h(acc[ma][na], aa[ma], bb[na]);
        }
        __syncthreads();
    }

    const int erow = lane >> 2, ecol = (lane & 3) * 2;

    if (MODE == 4) {
        float* st = (float*)sm;
        #pragma unroll
        for (int ma = 0; ma < 4; ma++) {
            #pragma unroll
            for (int na = 0; na < 4; na++) {
                int rr = wm + ma * 16 + erow;
                int cc = wn + na * 8 + ecol;
                st[rr * EPS_ST + cc]           = acc[ma][na][0];
                st[rr * EPS_ST + cc + 1]       = acc[ma][na][1];
                st[(rr + 8) * EPS_ST + cc]     = acc[ma][na][2];
                st[(rr + 8) * EPS_ST + cc + 1] = acc[ma][na][3];
            }
        }
        __syncthreads();
        const int nt = n0 >> 7;          // 0..15 q, 16..19 k, 20..23 v
        if (nt < NH + NKV) {
            const float sc_ = (nt < NH) ? qscale : 1.f;
            for (int i = tid; i < 128 * 64; i += 256) {
                int rr = i >> 6;
                int d  = i & 63;
                float t1 = st[rr * EPS_ST + d];
                float t2 = st[rr * EPS_ST + d + 64];
                int grow = m0 + rr;
                int b = grow / S, s = grow - b * S;
                float invf = __powf(10000.f, -(float)d * (1.f/64.f));
                float ang = (float)pos[s] * invf;
                float sn, cs;
                __sincosf(ang, &sn, &cs);
                float r1 = (t1 * cs - t2 * sn) * sc_;
                float r2 = (t2 * cs + t1 * sn) * sc_;
                if (nt < NH) {
                    long o = ((long)(b * NH + nt) * S + s) * HD;
                    Ch[o + d]      = __float2half_rn(r1);
                    Ch[o + d + 64] = __float2half_rn(r2);
                } else {
                    long o = ((long)(b * NKV + nt - NH) * S + s) * HD;
                    Ck[o + d]      = __float2half_rn(r1);
                    Ck[o + d + 64] = __float2half_rn(r2);
                }
            }
        } else {
            const int h = nt - NH - NKV;
            for (int i = tid; i < 128 * 128; i += 256) {
                int d  = i >> 7;
                int sc2 = i & 127;
                float v = st[sc2 * EPS_ST + d];
                int grow = m0 + sc2;
                int b = grow / S, s = grow - b * S;
                Cvt[((long)(b * NKV + h) * HD + d) * S + s] = __float2half_rn(v);
            }
        }
        return;
    }

    if (MODE == 3) {
        // cols are 8-block interleaved: even na-frag = gate block, odd = up block
        #pragma unroll
        for (int ma = 0; ma < 4; ma++) {
            #pragma unroll
            for (int na = 0; na < 4; na += 2) {
                long r0 = m0 + wm + ma * 16 + erow;
                int cc = n0 + wn + na * 8 + ecol;          // gate col in interleaved space
                long j = ((long)(cc >> 4) << 3) + (cc & 7); // output col
                __half2 h0 = __floats2half2_rn(silu_mul(acc[ma][na][0], acc[ma][na+1][0]),
                                               silu_mul(acc[ma][na][1], acc[ma][na+1][1]));
                __half2 h1 = __floats2half2_rn(silu_mul(acc[ma][na][2], acc[ma][na+1][2]),
                                               silu_mul(acc[ma][na][3], acc[ma][na+1][3]));
                *(__half2*)&Ch[r0 * (long)FFI + j] = h0;
                *(__half2*)&Ch[(r0 + 8) * (long)FFI + j] = h1;
            }
        }
        return;
    }

    #pragma unroll
    for (int ma = 0; ma < 4; ma++) {
        #pragma unroll
        for (int na = 0; na < 4; na++) {
            long r0 = m0 + wm + ma * 16 + erow;
            long cc = n0 + wn + na * 8 + ecol;
            float v00 = acc[ma][na][0], v01 = acc[ma][na][1];
            float v10 = acc[ma][na][2], v11 = acc[ma][na][3];
            if (RES) {
                const float2 q0 = *(const float2*)&R[r0 * ldc + cc];
                const float2 q1 = *(const float2*)&R[(r0 + 8) * ldc + cc];
                v00 += q0.x; v01 += q0.y; v10 += q1.x; v11 += q1.y;
            }
            float2 w0 = {v00, v01}, w1 = {v10, v11};
            *(float2*)&Cf[r0 * ldc + cc] = w0;
            *(float2*)&Cf[(r0 + 8) * ldc + cc] = w1;
        }
    }
}

// ================= fused flash attention (unchanged from R14) =================
#define FT_STRIDE 136
#define FT_TILEB (128 * FT_STRIDE * 2)   /* 34816 */
#define FT_SMEM  (5 * FT_TILEB)          /* 174080 */

__global__ void __launch_bounds__(256, 1)
fattn(const __half* __restrict__ Qg, const __half* __restrict__ Kg,
      const __half* __restrict__ Vg, __half* __restrict__ AO, int S)
{
    extern __shared__ char sm[];
    const uint32_t sb = smem_u32(sm);
    const int tid = threadIdx.x, wid = tid >> 5, lane = tid & 31;
    const int mt = gridDim.x - 1 - blockIdx.x;
    const int m0 = mt * 128;
    const int z = blockIdx.z;
    const int b = z >> 4, h = z & 15;
    const __half* Qp = Qg + ((long)z * S + m0) * HD;
    const __half* Kp = Kg + (long)(b * NKV + (h >> 2)) * S * HD;
    const __half* Vp = Vg + (long)(b * NKV + (h >> 2)) * HD * S;

    const uint32_t sQ = sb;

    #pragma unroll
    for (int i = 0; i < 8; i++) {
        int idx = tid + 256 * i;
        int r = idx >> 4, c = idx & 15;
        cp16(sQ + (r * FT_STRIDE + c * 8) * 2, Qp + (long)r * HD + c * 8);
    }
    cp_commit();

    auto load_kv = [&](int st, int j) {
        const uint32_t sK = sb + FT_TILEB + st * 2 * FT_TILEB;
        const uint32_t sV = sK + FT_TILEB;
        const __half* ks = Kp + (long)(j * 128) * HD;
        const __half* vs = Vp + j * 128;
        #pragma unroll
        for (int i = 0; i < 8; i++) {
            int idx = tid + 256 * i;
            int r = idx >> 4, c = idx & 15;
            cp16(sK + (r * FT_STRIDE + c * 8) * 2, ks + (long)r * HD + c * 8);
        }
        #pragma unroll
        for (int i = 0; i < 8; i++) {
            int idx = tid + 256 * i;
            int r = idx >> 4, c = idx & 15;
            cp16(sV + (r * FT_STRIDE + c * 8) * 2, vs + (long)r * S + c * 8);
        }
        cp_commit();
    };

    const int J = mt + 1;
    load_kv(0, 0);

    const int wm = wid * 16;
    const int alr = lane & 15, alc = (lane >> 4) * 8;
    const int blr = lane & 7, bhalf = (lane >> 3) & 1, bquad = (lane >> 4) * 8;
    const int r0 = lane >> 2, c0 = (lane & 3) * 2;

    float acc_o[16][4];
    #pragma unroll
    for (int i = 0; i < 16; i++)
        #pragma unroll
        for (int q = 0; q < 4; q++) acc_o[i][q] = 0.f;
    float rm0 = -1e30f, rm1 = -1e30f, rs0 = 0.f, rs1 = 0.f;

    for (int j = 0; j < J; j++) {
        const int st = j & 1;
        if (j + 1 < J) { load_kv(st ^ 1, j + 1); cp_wait1(); }
        else           { cp_wait0(); }
        __syncthreads();
        const uint32_t sK = sb + FT_TILEB + st * 2 * FT_TILEB;
        const uint32_t sV = sK + FT_TILEB;

        float accs[16][4];
        #pragma unroll
        for (int i = 0; i < 16; i++)
            #pragma unroll
            for (int q = 0; q < 4; q++) accs[i][q] = 0.f;
        #pragma unroll
        for (int kt = 0; kt < 8; kt++) {
            uint32_t aa[4];
            ldm_x4(aa, sQ + ((wm + alr) * FT_STRIDE + kt * 16 + alc) * 2);
            #pragma unroll
            for (int np = 0; np < 8; np++) {
                uint32_t t4[4];
                ldm_x4(t4, sK + ((np * 16 + bquad + blr) * FT_STRIDE + kt * 16 + bhalf * 8) * 2);
                uint32_t b0[2] = { t4[0], t4[1] }, b1[2] = { t4[2], t4[3] };
                mma16816h(accs[2*np],   aa, b0);
                mma16816h(accs[2*np+1], aa, b1);
            }
        }
        if (j == mt) {
            const int row0 = wm + r0, row1 = row0 + 8;
            #pragma unroll
            for (int na = 0; na < 16; na++) {
                int col = na * 8 + c0;
                if (col     > row0) accs[na][0] = -1e30f;
                if (col + 1 > row0) accs[na][1] = -1e30f;
                if (col     > row1) accs[na][2] = -1e30f;
                if (col + 1 > row1) accs[na][3] = -1e30f;
            }
        }
        float mt0 = -1e30f, mt1 = -1e30f;
        #pragma unroll
        for (int na = 0; na < 16; na++) {
            mt0 = fmaxf(mt0, fmaxf(accs[na][0], accs[na][1]));
            mt1 = fmaxf(mt1, fmaxf(accs[na][2], accs[na][3]));
        }
        mt0 = fmaxf(mt0, __shfl_xor_sync(0xffffffffu, mt0, 1));
        mt0 = fmaxf(mt0, __shfl_xor_sync(0xffffffffu, mt0, 2));
        mt1 = fmaxf(mt1, __shfl_xor_sync(0xffffffffu, mt1, 1));
        mt1 = fmaxf(mt1, __shfl_xor_sync(0xffffffffu, mt1, 2));
        float nm0 = fmaxf(rm0, mt0), nm1 = fmaxf(rm1, mt1);
        float corr0 = __expf(rm0 - nm0), corr1 = __expf(rm1 - nm1);
        rm0 = nm0; rm1 = nm1;
        float st0 = 0.f, st1 = 0.f;
        uint32_t pa[8][4];
        #pragma unroll
        for (int kf = 0; kf < 8; kf++) {
            float p00 = __expf(accs[2*kf][0]   - nm0), p01 = __expf(accs[2*kf][1]   - nm0);
            float p10 = __expf(accs[2*kf][2]   - nm1), p11 = __expf(accs[2*kf][3]   - nm1);
            float q00 = __expf(accs[2*kf+1][0] - nm0), q01 = __expf(accs[2*kf+1][1] - nm0);
            float q10 = __expf(accs[2*kf+1][2] - nm1), q11 = __expf(accs[2*kf+1][3] - nm1);
            st0 += p00 + p01 + q00 + q01;
            st1 += p10 + p11 + q10 + q11;
            pa[kf][0] = pack_h2(p00, p01);
            pa[kf][1] = pack_h2(p10, p11);
            pa[kf][2] = pack_h2(q00, q01);
            pa[kf][3] = pack_h2(q10, q11);
        }
        st0 += __shfl_xor_sync(0xffffffffu, st0, 1);
        st0 += __shfl_xor_sync(0xffffffffu, st0, 2);
        st1 += __shfl_xor_sync(0xffffffffu, st1, 1);
        st1 += __shfl_xor_sync(0xffffffffu, st1, 2);
        rs0 = rs0 * corr0 + st0;
        rs1 = rs1 * corr1 + st1;
        #pragma unroll
        for (int na = 0; na < 16; na++) {
            acc_o[na][0] *= corr0; acc_o[na][1] *= corr0;
            acc_o[na][2] *= corr1; acc_o[na][3] *= corr1;
        }
        #pragma unroll
        for (int kf = 0; kf < 8; kf++) {
            #pragma unroll
            for (int np = 0; np < 8; np++) {
                uint32_t t4[4];
                ldm_x4(t4, sV + ((np * 16 + bquad + blr) * FT_STRIDE + kf * 16 + bhalf * 8) * 2);
                uint32_t b0[2] = { t4[0], t4[1] }, b1[2] = { t4[2], t4[3] };
                mma16816h(acc_o[2*np],   pa[kf], b0);
                mma16816h(acc_o[2*np+1], pa[kf], b1);
            }
        }
        __syncthreads();
    }

    const float i0 = 1.f / rs0, i1 = 1.f / rs1;
    const int s0 = m0 + wm + r0;
    const long base0 = ((long)b * S + s0) * HIDD + h * HD;
    const long base1 = ((long)b * S + s0 + 8) * HIDD + h * HD;
    #pragma unroll
    for (int na = 0; na < 16; na++) {
        int d = na * 8 + c0;
        __half2 h0 = __floats2half2_rn(acc_o[na][0] * i0, acc_o[na][1] * i0);
        __half2 h1 = __floats2half2_rn(acc_o[na][2] * i1, acc_o[na][3] * i1);
        *(__half2*)&AO[base0 + d] = h0;
        *(__half2*)&AO[base1 + d] = h1;
    }
}

// ================= block reductions =================
__device__ __forceinline__ float block_sum(float v) {
    #pragma unroll
    for (int o = 16; o > 0; o >>= 1) v += __shfl_xor_sync(0xffffffffu, v, o);
    __shared__ float sh[8]; __shared__ float total;
    int w = threadIdx.x >> 5, l = threadIdx.x & 31;
    if (l == 0) sh[w] = v;
    __syncthreads();
    if (threadIdx.x == 0) { float s = 0.f; for (int i = 0; i < 8; i++) s += sh[i]; total = s; }
    __syncthreads();
    return total;
}

// ================= elementwise =================
__global__ void rmsnorm_h_kernel(const float* __restrict__ x, const float* __restrict__ w,
                                 __half* __restrict__ out) {
    long row = blockIdx.x;
    const float4* xr4 = (const float4*)(x + row * HIDD);
    const float4* w4  = (const float4*)w;
    float s = 0.f;
    #pragma unroll 2
    for (int i = threadIdx.x; i < HIDD / 4; i += 256) {
        float4 v = xr4[i];
        s += v.x * v.x + v.y * v.y + v.z * v.z + v.w * v.w;
    }
    s = block_sum(s);
    float inv = rsqrtf(s / (float)HIDD + 1e-6f);
    __half2* o2 = (__half2*)(out + row * HIDD);
    #pragma unroll 2
    for (int i = threadIdx.x; i < HIDD / 4; i += 256) {
        float4 v = xr4[i];
        float4 ww = w4[i];
        o2[2*i]   = __floats2half2_rn(v.x * inv * ww.x, v.y * inv * ww.y);
        o2[2*i+1] = __floats2half2_rn(v.z * inv * ww.z, v.w * inv * ww.w);
    }
}

__device__ __forceinline__ uint4 cvt8(const float* p) {
    float4 a = *(const float4*)p, b = *(const float4*)(p + 4);
    uint4 o;
    o.x = pack_h2(a.x, a.y); o.y = pack_h2(a.z, a.w);
    o.z = pack_h2(b.x, b.y); o.w = pack_h2(b.z, b.w);
    return o;
}

// streaming fp32 -> fp16 convert (no transpose)
__global__ void convS_kernel(const float* __restrict__ W, __half* __restrict__ T, long n8) {
    long i = (long)blockIdx.x * 256 + threadIdx.x;
    if (i >= n8) return;
    *(uint4*)&T[i * 8] = cvt8(W + i * 8);
}

// gate_up convert with 8-col block interleave:
// out cols [16j..16j+7] = gate[8j..8j+7], [16j+8..16j+15] = up[8j..8j+7]
__global__ void convGU_kernel(const float* __restrict__ W, __half* __restrict__ T) {
    long idx = (long)blockIdx.x * 256 + threadIdx.x;   // HIDD * FFI/8 entries
    long row = idx / (FFI / 8);
    int  j   = (int)(idx % (FFI / 8));
    const float* base = W + row * (2L * FFI);
    __half* dst = T + row * (2L * FFI) + j * 16;
    *(uint4*)dst       = cvt8(base + j * 8);          // gate block
    *(uint4*)(dst + 8) = cvt8(base + FFI + j * 8);    // up block
}

// ================= host launcher =================
extern "C" void kernel_launch(void* const* d_in, const int* in_sizes, int n_in,
                              void* d_out, int out_size) {
    const float* x         = (const float*)d_in[0];
    const float* ln1_w     = (const float*)d_in[1];
    const float* wqkv      = (const float*)d_in[2];
    const float* wo        = (const float*)d_in[3];
    const float* ln2_w     = (const float*)d_in[4];
    const float* w_gate_up = (const float*)d_in[5];
    const float* w_down    = (const float*)d_in[6];
    const int*   pos       = (const int*)d_in[7];
    float* out = (float*)d_out;

    const int S  = in_sizes[7];                 // 1024
    const long BS = (long)in_sizes[0] / HIDD;   // 4096
    const int Bb = (int)(BS / S);               // 4

    float *pH1;
    cudaGetSymbolAddress((void**)&pH1,  g_h1);
    __half *pH,*pAO,*pACT,*pQ,*pK,*pVt;
    __half *pQKVH,*pWOH,*pGUH,*pDNH;
    cudaGetSymbolAddress((void**)&pH, g_h);
    cudaGetSymbolAddress((void**)&pAO, g_ao);
    cudaGetSymbolAddress((void**)&pACT, g_act);
    cudaGetSymbolAddress((void**)&pQ, g_q);
    cudaGetSymbolAddress((void**)&pK, g_k);
    cudaGetSymbolAddress((void**)&pVt, g_vt);
    cudaGetSymbolAddress((void**)&pQKVH, g_wqkvH);
    cudaGetSymbolAddress((void**)&pWOH, g_woH);
    cudaGetSymbolAddress((void**)&pGUH, g_guH);
    cudaGetSymbolAddress((void**)&pDNH, g_dnH);

    cudaFuncSetAttribute(hgemm<0,false>, cudaFuncAttributeMaxDynamicSharedMemorySize, HG_SMEM);
    cudaFuncSetAttribute(hgemm<0,true>,  cudaFuncAttributeMaxDynamicSharedMemorySize, HG_SMEM);
    cudaFuncSetAttribute(hgemm<3,false>, cudaFuncAttributeMaxDynamicSharedMemorySize, HG_SMEM);
    cudaFuncSetAttribute(hgemm<4,false>, cudaFuncAttributeMaxDynamicSharedMemorySize, HG_SMEM);
    cudaFuncSetAttribute(fattn, cudaFuncAttributeMaxDynamicSharedMemorySize, FT_SMEM);

    const float inv_sqrt_d = 0.08838834764831843f;

    // weight converts (streaming, native [K,N] layout)
    convS_kernel<<<(unsigned)(((long)HIDD*QKVW/8 + 255)/256), 256>>>(wqkv,   pQKVH, (long)HIDD*QKVW/8);
    convS_kernel<<<(unsigned)(((long)HIDD*HIDD/8 + 255)/256), 256>>>(wo,     pWOH,  (long)HIDD*HIDD/8);
    convGU_kernel<<<(unsigned)(((long)HIDD*FFI/8 + 255)/256), 256>>>(w_gate_up, pGUH);
    convS_kernel<<<(unsigned)(((long)FFI*HIDD/8 + 255)/256), 256>>>(w_down, pDNH,  (long)FFI*HIDD/8);

    // 1. h = rmsnorm(x) -> fp16
    rmsnorm_h_kernel<<<(int)BS, 256>>>(x, ln1_w, pH);

    // 2+3. qkv GEMM with fused RoPE/split/v-transpose epilogue (q pre-scaled by 1/sqrt(D))
    hgemm<4,false><<<dim3((int)(BS/128), QKVW/128, 1), 256, HG_SMEM>>>(
        pH, pQKVH, nullptr, nullptr, pQ, pK, pVt, pos,
        HIDD, QKVW, 0, inv_sqrt_d, S);

    // 4-6. fused flash attention -> ao fp16 [b,s,h*d]
    fattn<<<dim3(S/128, 1, Bb*NH), 256, FT_SMEM>>>(pQ, pK, pVt, pAO, S);

    // 7. h1 = x + attnout @ wo
    hgemm<0,true><<<dim3((int)(BS/128), HIDD/128, 1), 256, HG_SMEM>>>(
        pAO, pWOH, x, pH1, nullptr, nullptr, nullptr, nullptr,
        HIDD, HIDD, HIDD, 0.f, S);

    // 8. h2 = rmsnorm(h1)
    rmsnorm_h_kernel<<<(int)BS, 256>>>(pH1, ln2_w, pH);

    // 9+10. act = silu(gate)*up fused into gate_up GEMM -> fp16
    hgemm<3,false><<<dim3((int)(BS/128), 2*FFI/128, 1), 256, HG_SMEM>>>(
        pH, pGUH, nullptr, nullptr, pACT, nullptr, nullptr, nullptr,
        HIDD, 2*FFI, 0, 0.f, S);

    // 11. out = h1 + act @ w_down
    hgemm<0,true><<<dim3((int)(BS/128), HIDD/128, 1), 256, HG_SMEM>>>(
        pACT, pDNH, pH1, out, nullptr, nullptr, nullptr, nullptr,
        FFI, HIDD, HIDD, 0.f, S);
}